// round 1
// baseline (speedup 1.0000x reference)
#include <cuda_runtime.h>
#include <cuda_bf16.h>
#include <math.h>

// Problem constants
#define SEQ      4096
#define EMB      2048
#define NHEADS   16
#define NKV      4
#define HDIM     128
#define GROUP    (NHEADS / NKV)

// ---------------- scratch (device globals; no allocation allowed) ----------
__device__ float g_qproj[SEQ * NHEADS * HDIM];   // 4096 x 2048
__device__ float g_kproj[SEQ * NKV * HDIM];      // 4096 x 512
__device__ float g_vproj[SEQ * NKV * HDIM];      // 4096 x 512
__device__ float g_q    [NHEADS * SEQ * HDIM];   // head-major Q after norm+rope
__device__ float g_ctx  [SEQ * NHEADS * HDIM];   // 4096 x 2048 attention output

// ---------------- SGEMM: C[M,N] = A[M,K] @ B[K,N], row-major, fp32 ---------
// BM=BN=128, BK=8, 256 threads, 8x8 microtile. M%128==0, N%128==0, K%8==0.
__global__ void __launch_bounds__(256) sgemm128(const float* __restrict__ A,
                                                const float* __restrict__ B,
                                                float* __restrict__ C,
                                                int M, int N, int K) {
    __shared__ float As[8][128];
    __shared__ float Bs[8][128];

    const int tid = threadIdx.x;
    const int tx  = tid & 15;       // N direction
    const int ty  = tid >> 4;       // M direction
    const int row0 = blockIdx.y * 128;
    const int col0 = blockIdx.x * 128;

    float acc[8][8];
#pragma unroll
    for (int i = 0; i < 8; i++)
#pragma unroll
        for (int j = 0; j < 8; j++) acc[i][j] = 0.f;

    const int arow = tid >> 1;            // 0..127
    const int acol = (tid & 1) * 4;       // 0 or 4
    const int brow = tid >> 5;            // 0..7
    const int bcol = (tid & 31) * 4;      // 0..124

    const float* Aptr = A + (size_t)(row0 + arow) * K + acol;
    const float* Bptr = B + (size_t)brow * N + col0 + bcol;

    for (int k0 = 0; k0 < K; k0 += 8) {
        float4 a = *(const float4*)Aptr;  Aptr += 8;
        float4 b = *(const float4*)Bptr;  Bptr += (size_t)8 * N;
        As[acol + 0][arow] = a.x;
        As[acol + 1][arow] = a.y;
        As[acol + 2][arow] = a.z;
        As[acol + 3][arow] = a.w;
        *(float4*)&Bs[brow][bcol] = b;
        __syncthreads();

#pragma unroll
        for (int kk = 0; kk < 8; kk++) {
            float4 m0 = *(float4*)&As[kk][ty * 8];
            float4 m1 = *(float4*)&As[kk][ty * 8 + 4];
            float4 n0 = *(float4*)&Bs[kk][tx * 8];
            float4 n1 = *(float4*)&Bs[kk][tx * 8 + 4];
            float rm[8] = {m0.x, m0.y, m0.z, m0.w, m1.x, m1.y, m1.z, m1.w};
            float rn[8] = {n0.x, n0.y, n0.z, n0.w, n1.x, n1.y, n1.z, n1.w};
#pragma unroll
            for (int i = 0; i < 8; i++)
#pragma unroll
                for (int j = 0; j < 8; j++) acc[i][j] += rm[i] * rn[j];
        }
        __syncthreads();
    }

#pragma unroll
    for (int i = 0; i < 8; i++) {
        float* Crow = C + (size_t)(row0 + ty * 8 + i) * N + col0 + tx * 8;
        float4 c0 = make_float4(acc[i][0], acc[i][1], acc[i][2], acc[i][3]);
        float4 c1 = make_float4(acc[i][4], acc[i][5], acc[i][6], acc[i][7]);
        *(float4*)(Crow)     = c0;
        *(float4*)(Crow + 4) = c1;
    }
}

// ---------------- RMSNorm + RoPE (+ V pass-through) ------------------------
// grid: (SEQ, 24). unit<16: Q head; 16..19: K head; 20..23: V copy. 128 thr.
__global__ void __launch_bounds__(128) norm_rope_kernel(
    const float* __restrict__ qproj, const float* __restrict__ kproj,
    const float* __restrict__ vproj, const int* __restrict__ pos_ids,
    const float* __restrict__ qw, const float* __restrict__ kw,
    float* __restrict__ qout,  // [NHEADS][SEQ][HDIM]
    float* __restrict__ kout,  // [NKV][SEQ][HDIM]  (in d_out)
    float* __restrict__ vout)  // [NKV][SEQ][HDIM]  (in d_out)
{
    const int s    = blockIdx.x;
    const int unit = blockIdx.y;
    const int d    = threadIdx.x;

    if (unit >= 20) {                       // V: pure layout transpose
        const int kv = unit - 20;
        vout[((size_t)kv * SEQ + s) * HDIM + d] =
            vproj[(size_t)s * (NKV * HDIM) + kv * HDIM + d];
        return;
    }

    float v; const float* w;
    if (unit < 16) {
        v = qproj[(size_t)s * (NHEADS * HDIM) + unit * HDIM + d];
        w = qw;
    } else {
        v = kproj[(size_t)s * (NKV * HDIM) + (unit - 16) * HDIM + d];
        w = kw;
    }

    // RMSNorm over 128
    float sq = v * v;
#pragma unroll
    for (int off = 16; off > 0; off >>= 1)
        sq += __shfl_xor_sync(0xffffffffu, sq, off);
    __shared__ float wsum[4];
    if ((d & 31) == 0) wsum[d >> 5] = sq;
    __syncthreads();
    const float tot = wsum[0] + wsum[1] + wsum[2] + wsum[3];
    const float inv = rsqrtf(tot * (1.0f / HDIM) + 1e-6f);

    __shared__ float xn[HDIM];
    xn[d] = w[d] * v * inv;
    __syncthreads();

    // RoPE
    const float pos = (float)pos_ids[s];
    const int   i   = d & 63;
    const float freq  = powf(10000.0f, -(float)i / 64.0f);
    const float ang_f = pos * freq;                 // fp32 like reference
    const double ang  = (double)ang_f;
    const float c  = (float)cos(ang);
    const float sn = (float)sin(ang);
    float out;
    if (d < 64) out = xn[d] * c - xn[d + 64] * sn;
    else        out = xn[d] * c + xn[d - 64] * sn;

    if (unit < 16)
        qout[((size_t)unit * SEQ + s) * HDIM + d] = out;
    else
        kout[((size_t)(unit - 16) * SEQ + s) * HDIM + d] = out;
}

// ---------------- Flash attention (fp32, causal) ---------------------------
// BM=BN=64, D=128, 256 threads (16x16), 4x4 score microtile, 4x8 O microtile.
#define KT_LD  68
#define STG_LD 132
#define PS_LD  68
#define FLASH_SMEM_FLOATS (64*128 + 128*KT_LD + 64*STG_LD + 64*PS_LD)

__global__ void __launch_bounds__(256, 1) flash_kernel(
    const float* __restrict__ Q,    // [NHEADS][SEQ][HDIM]
    const float* __restrict__ Kd,   // [NKV][SEQ][HDIM]
    const float* __restrict__ Vd,   // [NKV][SEQ][HDIM]
    float* __restrict__ ctx)        // [SEQ][NHEADS*HDIM]
{
    extern __shared__ float sm[];
    float* Qs  = sm;                       // [64][128]
    float* KT  = Qs  + 64 * 128;           // [128][KT_LD]   K transposed
    float* STG = KT  + 128 * KT_LD;        // [64][STG_LD]   K staging / V tile
    float* Ps  = STG + 64 * STG_LD;        // [64][PS_LD]    probabilities

    const int tid  = threadIdx.x;
    const int tx   = tid & 15;
    const int ty   = tid >> 4;
    const int qt   = blockIdx.x;           // query tile
    const int head = blockIdx.y;
    const int kv   = head / GROUP;
    const int q0   = qt * 64;

    // load Q tile (contiguous)
    {
        const float4* src = (const float4*)(Q + ((size_t)head * SEQ + q0) * HDIM);
        float4* dst = (float4*)Qs;
        for (int i = tid; i < 64 * 32; i += 256) dst[i] = src[i];
    }

    float o[4][8];
#pragma unroll
    for (int i = 0; i < 4; i++)
#pragma unroll
        for (int j = 0; j < 8; j++) o[i][j] = 0.f;
    float m_i[4] = {-INFINITY, -INFINITY, -INFINITY, -INFINITY};
    float l_i[4] = {0.f, 0.f, 0.f, 0.f};

    const float scale = 0.08838834764831845f;  // 1/sqrt(128)
    const int ntiles = qt + 1;                 // causal

    for (int jt = 0; jt < ntiles; jt++) {
        const int k0 = jt * 64;

        // load K tile -> STG (padded)
        {
            const float* Kbase = Kd + ((size_t)kv * SEQ + k0) * HDIM;
            for (int i = tid; i < 64 * 32; i += 256) {
                const int row = i >> 5, c = (i & 31) * 4;
                *(float4*)&STG[row * STG_LD + c] =
                    *(const float4*)(Kbase + row * HDIM + c);
            }
        }
        __syncthreads();

        // transpose STG -> KT  (reads: conflict-free; writes: coalesced rows)
        for (int i = tid; i < 64 * 32; i += 256) {
            const int key = i & 63, dv = i >> 6;       // dv 0..31
            float4 v = *(const float4*)&STG[key * STG_LD + 4 * dv];
            KT[(4 * dv + 0) * KT_LD + key] = v.x;
            KT[(4 * dv + 1) * KT_LD + key] = v.y;
            KT[(4 * dv + 2) * KT_LD + key] = v.z;
            KT[(4 * dv + 3) * KT_LD + key] = v.w;
        }
        __syncthreads();

        // load V tile -> STG (overwrites K staging; consumed after next sync)
        {
            const float* Vbase = Vd + ((size_t)kv * SEQ + k0) * HDIM;
            for (int i = tid; i < 64 * 32; i += 256) {
                const int row = i >> 5, c = (i & 31) * 4;
                *(float4*)&STG[row * STG_LD + c] =
                    *(const float4*)(Vbase + row * HDIM + c);
            }
        }

        // S = Q @ K^T  (64x64x128)
        float s_acc[4][4];
#pragma unroll
        for (int i = 0; i < 4; i++)
#pragma unroll
            for (int j = 0; j < 4; j++) s_acc[i][j] = 0.f;

#pragma unroll 8
        for (int d0 = 0; d0 < 128; d0 += 4) {
            float4 qv[4], kt[4];
#pragma unroll
            for (int i = 0; i < 4; i++)
                qv[i] = *(const float4*)&Qs[(4 * ty + i) * 128 + d0];
#pragma unroll
            for (int dd = 0; dd < 4; dd++)
                kt[dd] = *(const float4*)&KT[(d0 + dd) * KT_LD + 4 * tx];
#pragma unroll
            for (int i = 0; i < 4; i++) {
                const float qe[4] = {qv[i].x, qv[i].y, qv[i].z, qv[i].w};
#pragma unroll
                for (int dd = 0; dd < 4; dd++) {
                    s_acc[i][0] += qe[dd] * kt[dd].x;
                    s_acc[i][1] += qe[dd] * kt[dd].y;
                    s_acc[i][2] += qe[dd] * kt[dd].z;
                    s_acc[i][3] += qe[dd] * kt[dd].w;
                }
            }
        }

        // online softmax per row (16-lane groups share a row set)
        const bool diag = (jt == qt);
#pragma unroll
        for (int i = 0; i < 4; i++) {
            const int q_idx = q0 + 4 * ty + i;
            float sv[4];
#pragma unroll
            for (int j = 0; j < 4; j++) {
                float s = s_acc[i][j] * scale;
                if (diag && (k0 + 4 * tx + j > q_idx)) s = -1.0e9f;
                sv[j] = s;
            }
            float rm = fmaxf(fmaxf(sv[0], sv[1]), fmaxf(sv[2], sv[3]));
#pragma unroll
            for (int off = 8; off > 0; off >>= 1)
                rm = fmaxf(rm, __shfl_xor_sync(0xffffffffu, rm, off));
            const float m_new = fmaxf(m_i[i], rm);
            const float corr  = __expf(m_i[i] - m_new);
            float pj[4], rs = 0.f;
#pragma unroll
            for (int j = 0; j < 4; j++) { pj[j] = __expf(sv[j] - m_new); rs += pj[j]; }
#pragma unroll
            for (int off = 8; off > 0; off >>= 1)
                rs += __shfl_xor_sync(0xffffffffu, rs, off);
            l_i[i] = l_i[i] * corr + rs;
            m_i[i] = m_new;
#pragma unroll
            for (int j = 0; j < 8; j++) o[i][j] *= corr;
            *(float4*)&Ps[(4 * ty + i) * PS_LD + 4 * tx] =
                make_float4(pj[0], pj[1], pj[2], pj[3]);
        }
        __syncthreads();   // V tile + Ps visible

        // O += P @ V  (64x128x64)
#pragma unroll 4
        for (int k0i = 0; k0i < 64; k0i += 4) {
            float4 p[4];
#pragma unroll
            for (int i = 0; i < 4; i++)
                p[i] = *(const float4*)&Ps[(4 * ty + i) * PS_LD + k0i];
#pragma unroll
            for (int kk = 0; kk < 4; kk++) {
                float4 va = *(const float4*)&STG[(k0i + kk) * STG_LD + 8 * tx];
                float4 vb = *(const float4*)&STG[(k0i + kk) * STG_LD + 8 * tx + 4];
#pragma unroll
                for (int i = 0; i < 4; i++) {
                    const float pm = (kk == 0) ? p[i].x : (kk == 1) ? p[i].y
                                   : (kk == 2) ? p[i].z : p[i].w;
                    o[i][0] += pm * va.x;  o[i][1] += pm * va.y;
                    o[i][2] += pm * va.z;  o[i][3] += pm * va.w;
                    o[i][4] += pm * vb.x;  o[i][5] += pm * vb.y;
                    o[i][6] += pm * vb.z;  o[i][7] += pm * vb.w;
                }
            }
        }
        __syncthreads();   // protect STG/KT/Ps for next iteration
    }

    // epilogue: normalize and scatter to [s][h*128+d]
#pragma unroll
    for (int i = 0; i < 4; i++) {
        const float inv = 1.0f / l_i[i];
        float* dst = ctx + (size_t)(q0 + 4 * ty + i) * (NHEADS * HDIM)
                         + head * HDIM + 8 * tx;
        float4 c0 = make_float4(o[i][0] * inv, o[i][1] * inv,
                                o[i][2] * inv, o[i][3] * inv);
        float4 c1 = make_float4(o[i][4] * inv, o[i][5] * inv,
                                o[i][6] * inv, o[i][7] * inv);
        *(float4*)(dst)     = c0;
        *(float4*)(dst + 4) = c1;
    }
}

// ---------------- launch ----------------------------------------------------
extern "C" void kernel_launch(void* const* d_in, const int* in_sizes, int n_in,
                              void* d_out, int out_size) {
    const float* x   = (const float*)d_in[0];
    const int*   pos = (const int*)  d_in[1];
    // d_in[2] = attn_mask (pure causal triu(-1e9)) -- implemented analytically
    const float* Wq  = (const float*)d_in[3];
    const float* Wk  = (const float*)d_in[4];
    const float* Wv  = (const float*)d_in[5];
    const float* Wo  = (const float*)d_in[6];
    const float* qw  = (const float*)d_in[7];
    const float* kw  = (const float*)d_in[8];

    float* out  = (float*)d_out;                       // [4096, 2048]
    float* kout = out  + (size_t)SEQ * EMB;            // [4, 4096, 128]
    float* vout = kout + (size_t)NKV * SEQ * HDIM;     // [4, 4096, 128]

    float *qproj, *kproj, *vproj, *q, *ctx;
    cudaGetSymbolAddress((void**)&qproj, g_qproj);
    cudaGetSymbolAddress((void**)&kproj, g_kproj);
    cudaGetSymbolAddress((void**)&vproj, g_vproj);
    cudaGetSymbolAddress((void**)&q,     g_q);
    cudaGetSymbolAddress((void**)&ctx,   g_ctx);

    // 1) projections
    sgemm128<<<dim3(EMB / 128, SEQ / 128), 256>>>(x, Wq, qproj, SEQ, EMB, EMB);
    sgemm128<<<dim3((NKV * HDIM) / 128, SEQ / 128), 256>>>(x, Wk, kproj, SEQ, NKV * HDIM, EMB);
    sgemm128<<<dim3((NKV * HDIM) / 128, SEQ / 128), 256>>>(x, Wv, vproj, SEQ, NKV * HDIM, EMB);

    // 2) rmsnorm + rope (+ V transpose straight into d_out)
    norm_rope_kernel<<<dim3(SEQ, 24), 128>>>(qproj, kproj, vproj, pos,
                                             qw, kw, q, kout, vout);

    // 3) causal flash attention
    const int smem_bytes = FLASH_SMEM_FLOATS * (int)sizeof(float);
    cudaFuncSetAttribute(flash_kernel,
                         cudaFuncAttributeMaxDynamicSharedMemorySize, smem_bytes);
    flash_kernel<<<dim3(SEQ / 64, NHEADS), 256, smem_bytes>>>(q, kout, vout, ctx);

    // 4) output projection
    sgemm128<<<dim3(EMB / 128, SEQ / 128), 256>>>(ctx, Wo, out, SEQ, EMB, EMB);
}

// round 2
// speedup vs baseline: 1.1440x; 1.1440x over previous
#include <cuda_runtime.h>
#include <cuda_bf16.h>
#include <math.h>

// Problem constants
#define SEQ      4096
#define EMB      2048
#define NHEADS   16
#define NKV      4
#define HDIM     128
#define GROUP    (NHEADS / NKV)

typedef unsigned long long u64;

// ---------------- scratch (device globals; no allocation allowed) ----------
__device__ float g_qproj[SEQ * NHEADS * HDIM];   // 4096 x 2048
__device__ float g_kproj[SEQ * NKV * HDIM];      // 4096 x 512
__device__ float g_vproj[SEQ * NKV * HDIM];      // 4096 x 512
__device__ float g_q    [NHEADS * SEQ * HDIM];   // head-major Q after norm+rope
__device__ float g_ctx  [SEQ * NHEADS * HDIM];   // 4096 x 2048 attention output
__device__ float g_rcos [SEQ * 64];
__device__ float g_rsin [SEQ * 64];

// ---------------- f32x2 packed-math helpers --------------------------------
__device__ __forceinline__ void fma2(u64& acc, u64 a, u64 b) {
    asm("fma.rn.f32x2 %0, %1, %2, %0;" : "+l"(acc) : "l"(a), "l"(b));
}
__device__ __forceinline__ u64 mul2(u64 a, u64 b) {
    u64 r; asm("mul.rn.f32x2 %0, %1, %2;" : "=l"(r) : "l"(a), "l"(b)); return r;
}
__device__ __forceinline__ u64 bc2(float x) {
    u64 r; unsigned u = __float_as_uint(x);
    asm("mov.b64 %0, {%1, %1};" : "=l"(r) : "r"(u)); return r;
}
__device__ __forceinline__ float2 unpk(u64 v) {
    float2 r;
    r.x = __uint_as_float((unsigned)(v & 0xffffffffULL));
    r.y = __uint_as_float((unsigned)(v >> 32));
    return r;
}

// ---------------- SGEMM: C[M,N] = A[M,K] @ B[K,N], row-major, fp32 ---------
// BM=BN=128, BK=8, 256 threads, 8x8 microtile, packed f32x2 FMA.
__global__ void __launch_bounds__(256) sgemm128(const float* __restrict__ A,
                                                const float* __restrict__ B,
                                                float* __restrict__ C,
                                                int M, int N, int K) {
    __shared__ float As[8][128];
    __shared__ float Bs[8][128];

    const int tid = threadIdx.x;
    const int tx  = tid & 15;       // N direction
    const int ty  = tid >> 4;       // M direction
    const int row0 = blockIdx.y * 128;
    const int col0 = blockIdx.x * 128;

    u64 acc2[8][4];
#pragma unroll
    for (int i = 0; i < 8; i++)
#pragma unroll
        for (int j = 0; j < 4; j++) acc2[i][j] = 0ULL;

    const int arow = tid >> 1;            // 0..127
    const int acol = (tid & 1) * 4;       // 0 or 4
    const int brow = tid >> 5;            // 0..7
    const int bcol = (tid & 31) * 4;      // 0..124

    const float* Aptr = A + (size_t)(row0 + arow) * K + acol;
    const float* Bptr = B + (size_t)brow * N + col0 + bcol;

    for (int k0 = 0; k0 < K; k0 += 8) {
        float4 a = *(const float4*)Aptr;  Aptr += 8;
        float4 b = *(const float4*)Bptr;  Bptr += (size_t)8 * N;
        As[acol + 0][arow] = a.x;
        As[acol + 1][arow] = a.y;
        As[acol + 2][arow] = a.z;
        As[acol + 3][arow] = a.w;
        *(float4*)&Bs[brow][bcol] = b;
        __syncthreads();

#pragma unroll
        for (int kk = 0; kk < 8; kk++) {
            float4 m0 = *(float4*)&As[kk][ty * 8];
            float4 m1 = *(float4*)&As[kk][ty * 8 + 4];
            const ulonglong2* bp = (const ulonglong2*)&Bs[kk][tx * 8];
            ulonglong2 b01 = bp[0];
            ulonglong2 b23 = bp[1];
            u64 bb[4] = {b01.x, b01.y, b23.x, b23.y};
            float rm[8] = {m0.x, m0.y, m0.z, m0.w, m1.x, m1.y, m1.z, m1.w};
#pragma unroll
            for (int i = 0; i < 8; i++) {
                u64 am = bc2(rm[i]);
#pragma unroll
                for (int j = 0; j < 4; j++) fma2(acc2[i][j], am, bb[j]);
            }
        }
        __syncthreads();
    }

#pragma unroll
    for (int i = 0; i < 8; i++) {
        float* Crow = C + (size_t)(row0 + ty * 8 + i) * N + col0 + tx * 8;
        float2 c0 = unpk(acc2[i][0]);
        float2 c1 = unpk(acc2[i][1]);
        float2 c2 = unpk(acc2[i][2]);
        float2 c3 = unpk(acc2[i][3]);
        *(float4*)(Crow)     = make_float4(c0.x, c0.y, c1.x, c1.y);
        *(float4*)(Crow + 4) = make_float4(c2.x, c2.y, c3.x, c3.y);
    }
}

// ---------------- RoPE table precompute (once, tiny) ------------------------
__global__ void __launch_bounds__(64) rope_table_kernel(const int* __restrict__ pos_ids) {
    const int s = blockIdx.x;
    const int i = threadIdx.x;  // 0..63
    const float freq  = powf(10000.0f, -(float)i / 64.0f);
    const float ang_f = (float)pos_ids[s] * freq;   // fp32 like reference
    const double ang  = (double)ang_f;
    g_rcos[s * 64 + i] = (float)cos(ang);
    g_rsin[s * 64 + i] = (float)sin(ang);
}

// ---------------- RMSNorm + RoPE (+ V pass-through) ------------------------
// grid: (SEQ, 24). unit<16: Q head; 16..19: K head; 20..23: V copy. 128 thr.
__global__ void __launch_bounds__(128) norm_rope_kernel(
    const float* __restrict__ qproj, const float* __restrict__ kproj,
    const float* __restrict__ vproj,
    const float* __restrict__ qw, const float* __restrict__ kw,
    float* __restrict__ qout,  // [NHEADS][SEQ][HDIM]
    float* __restrict__ kout,  // [NKV][SEQ][HDIM]  (in d_out)
    float* __restrict__ vout)  // [NKV][SEQ][HDIM]  (in d_out)
{
    const int s    = blockIdx.x;
    const int unit = blockIdx.y;
    const int d    = threadIdx.x;

    if (unit >= 20) {                       // V: pure layout transpose
        const int kv = unit - 20;
        vout[((size_t)kv * SEQ + s) * HDIM + d] =
            vproj[(size_t)s * (NKV * HDIM) + kv * HDIM + d];
        return;
    }

    float v; const float* w;
    if (unit < 16) {
        v = qproj[(size_t)s * (NHEADS * HDIM) + unit * HDIM + d];
        w = qw;
    } else {
        v = kproj[(size_t)s * (NKV * HDIM) + (unit - 16) * HDIM + d];
        w = kw;
    }

    // RMSNorm over 128
    float sq = v * v;
#pragma unroll
    for (int off = 16; off > 0; off >>= 1)
        sq += __shfl_xor_sync(0xffffffffu, sq, off);
    __shared__ float wsum[4];
    if ((d & 31) == 0) wsum[d >> 5] = sq;
    __syncthreads();
    const float tot = wsum[0] + wsum[1] + wsum[2] + wsum[3];
    const float inv = rsqrtf(tot * (1.0f / HDIM) + 1e-6f);

    __shared__ float xn[HDIM];
    xn[d] = w[d] * v * inv;
    __syncthreads();

    // RoPE from precomputed table
    const int i   = d & 63;
    const float c  = g_rcos[s * 64 + i];
    const float sn = g_rsin[s * 64 + i];
    float out;
    if (d < 64) out = xn[d] * c - xn[d + 64] * sn;
    else        out = xn[d] * c + xn[d - 64] * sn;

    if (unit < 16)
        qout[((size_t)unit * SEQ + s) * HDIM + d] = out;
    else
        kout[((size_t)(unit - 16) * SEQ + s) * HDIM + d] = out;
}

// ---------------- Flash attention (fp32, causal, f32x2 math) ---------------
// BM=BN=64, D=128, 256 threads (16x16), 4x4 score microtile, 4x8 O microtile.
#define KT_LD  68
#define STG_LD 132
#define PS_LD  68
#define FLASH_SMEM_FLOATS (64*128 + 128*KT_LD + 64*STG_LD + 64*PS_LD)

__global__ void __launch_bounds__(256, 1) flash_kernel(
    const float* __restrict__ Q,    // [NHEADS][SEQ][HDIM]
    const float* __restrict__ Kd,   // [NKV][SEQ][HDIM]
    const float* __restrict__ Vd,   // [NKV][SEQ][HDIM]
    float* __restrict__ ctx)        // [SEQ][NHEADS*HDIM]
{
    extern __shared__ float sm[];
    float* Qs  = sm;                       // [64][128]
    float* KT  = Qs  + 64 * 128;           // [128][KT_LD]   K transposed
    float* STG = KT  + 128 * KT_LD;        // [64][STG_LD]   K staging / V tile
    float* Ps  = STG + 64 * STG_LD;        // [64][PS_LD]    probabilities

    const int tid  = threadIdx.x;
    const int tx   = tid & 15;
    const int ty   = tid >> 4;
    const int qt   = blockIdx.x;           // query tile
    const int head = blockIdx.y;
    const int kv   = head / GROUP;
    const int q0   = qt * 64;

    // load Q tile (contiguous)
    {
        const float4* src = (const float4*)(Q + ((size_t)head * SEQ + q0) * HDIM);
        float4* dst = (float4*)Qs;
        for (int i = tid; i < 64 * 32; i += 256) dst[i] = src[i];
    }

    u64 o2[4][4];
#pragma unroll
    for (int i = 0; i < 4; i++)
#pragma unroll
        for (int j = 0; j < 4; j++) o2[i][j] = 0ULL;
    float m_i[4] = {-INFINITY, -INFINITY, -INFINITY, -INFINITY};
    float l_i[4] = {0.f, 0.f, 0.f, 0.f};

    const float scale = 0.08838834764831845f;  // 1/sqrt(128)
    const int ntiles = qt + 1;                 // causal

    for (int jt = 0; jt < ntiles; jt++) {
        const int k0 = jt * 64;

        // load K tile -> STG (padded)
        {
            const float* Kbase = Kd + ((size_t)kv * SEQ + k0) * HDIM;
            for (int i = tid; i < 64 * 32; i += 256) {
                const int row = i >> 5, c = (i & 31) * 4;
                *(float4*)&STG[row * STG_LD + c] =
                    *(const float4*)(Kbase + row * HDIM + c);
            }
        }
        __syncthreads();

        // transpose STG -> KT
        for (int i = tid; i < 64 * 32; i += 256) {
            const int key = i & 63, dv = i >> 6;       // dv 0..31
            float4 v = *(const float4*)&STG[key * STG_LD + 4 * dv];
            KT[(4 * dv + 0) * KT_LD + key] = v.x;
            KT[(4 * dv + 1) * KT_LD + key] = v.y;
            KT[(4 * dv + 2) * KT_LD + key] = v.z;
            KT[(4 * dv + 3) * KT_LD + key] = v.w;
        }
        __syncthreads();

        // load V tile -> STG (overwrites K staging; consumed after next sync)
        {
            const float* Vbase = Vd + ((size_t)kv * SEQ + k0) * HDIM;
            for (int i = tid; i < 64 * 32; i += 256) {
                const int row = i >> 5, c = (i & 31) * 4;
                *(float4*)&STG[row * STG_LD + c] =
                    *(const float4*)(Vbase + row * HDIM + c);
            }
        }

        // S = Q @ K^T  (64x64x128), packed f32x2 along key dim
        u64 s2[4][2];
#pragma unroll
        for (int i = 0; i < 4; i++) { s2[i][0] = 0ULL; s2[i][1] = 0ULL; }

#pragma unroll 8
        for (int d0 = 0; d0 < 128; d0 += 4) {
            float4 qv[4];
            ulonglong2 ktp[4];
#pragma unroll
            for (int i = 0; i < 4; i++)
                qv[i] = *(const float4*)&Qs[(4 * ty + i) * 128 + d0];
#pragma unroll
            for (int dd = 0; dd < 4; dd++)
                ktp[dd] = *(const ulonglong2*)&KT[(d0 + dd) * KT_LD + 4 * tx];
#pragma unroll
            for (int i = 0; i < 4; i++) {
                const float qe[4] = {qv[i].x, qv[i].y, qv[i].z, qv[i].w};
#pragma unroll
                for (int dd = 0; dd < 4; dd++) {
                    u64 qq = bc2(qe[dd]);
                    fma2(s2[i][0], qq, ktp[dd].x);
                    fma2(s2[i][1], qq, ktp[dd].y);
                }
            }
        }

        // online softmax per row (16-lane groups share a row set)
        const bool diag = (jt == qt);
#pragma unroll
        for (int i = 0; i < 4; i++) {
            const int q_idx = q0 + 4 * ty + i;
            float2 sa = unpk(s2[i][0]);
            float2 sb = unpk(s2[i][1]);
            float sv[4] = {sa.x, sa.y, sb.x, sb.y};
#pragma unroll
            for (int j = 0; j < 4; j++) {
                float s = sv[j] * scale;
                if (diag && (k0 + 4 * tx + j > q_idx)) s = -1.0e9f;
                sv[j] = s;
            }
            float rm = fmaxf(fmaxf(sv[0], sv[1]), fmaxf(sv[2], sv[3]));
#pragma unroll
            for (int off = 8; off > 0; off >>= 1)
                rm = fmaxf(rm, __shfl_xor_sync(0xffffffffu, rm, off));
            const float m_new = fmaxf(m_i[i], rm);
            const float corr  = __expf(m_i[i] - m_new);
            float pj[4], rs = 0.f;
#pragma unroll
            for (int j = 0; j < 4; j++) { pj[j] = __expf(sv[j] - m_new); rs += pj[j]; }
#pragma unroll
            for (int off = 8; off > 0; off >>= 1)
                rs += __shfl_xor_sync(0xffffffffu, rs, off);
            l_i[i] = l_i[i] * corr + rs;
            m_i[i] = m_new;
            u64 cc = bc2(corr);
#pragma unroll
            for (int j = 0; j < 4; j++) o2[i][j] = mul2(o2[i][j], cc);
            *(float4*)&Ps[(4 * ty + i) * PS_LD + 4 * tx] =
                make_float4(pj[0], pj[1], pj[2], pj[3]);
        }
        __syncthreads();   // V tile + Ps visible

        // O += P @ V  (64x128x64), packed along output dim
#pragma unroll 4
        for (int k0i = 0; k0i < 64; k0i += 4) {
            float4 p[4];
#pragma unroll
            for (int i = 0; i < 4; i++)
                p[i] = *(const float4*)&Ps[(4 * ty + i) * PS_LD + k0i];
#pragma unroll
            for (int kk = 0; kk < 4; kk++) {
                const ulonglong2* vp =
                    (const ulonglong2*)&STG[(k0i + kk) * STG_LD + 8 * tx];
                ulonglong2 v01 = vp[0];
                ulonglong2 v23 = vp[1];
                u64 vv[4] = {v01.x, v01.y, v23.x, v23.y};
#pragma unroll
                for (int i = 0; i < 4; i++) {
                    const float pm = (kk == 0) ? p[i].x : (kk == 1) ? p[i].y
                                   : (kk == 2) ? p[i].z : p[i].w;
                    u64 pp = bc2(pm);
#pragma unroll
                    for (int j = 0; j < 4; j++) fma2(o2[i][j], pp, vv[j]);
                }
            }
        }
        __syncthreads();   // protect STG/KT/Ps for next iteration
    }

    // epilogue: normalize and scatter to [s][h*128+d]
#pragma unroll
    for (int i = 0; i < 4; i++) {
        const float inv = 1.0f / l_i[i];
        float* dst = ctx + (size_t)(q0 + 4 * ty + i) * (NHEADS * HDIM)
                         + head * HDIM + 8 * tx;
        float2 a = unpk(o2[i][0]);
        float2 b = unpk(o2[i][1]);
        float2 c = unpk(o2[i][2]);
        float2 d = unpk(o2[i][3]);
        *(float4*)(dst)     = make_float4(a.x * inv, a.y * inv, b.x * inv, b.y * inv);
        *(float4*)(dst + 4) = make_float4(c.x * inv, c.y * inv, d.x * inv, d.y * inv);
    }
}

// ---------------- launch ----------------------------------------------------
extern "C" void kernel_launch(void* const* d_in, const int* in_sizes, int n_in,
                              void* d_out, int out_size) {
    const float* x   = (const float*)d_in[0];
    const int*   pos = (const int*)  d_in[1];
    // d_in[2] = attn_mask (pure causal triu(-1e9)) -- implemented analytically
    const float* Wq  = (const float*)d_in[3];
    const float* Wk  = (const float*)d_in[4];
    const float* Wv  = (const float*)d_in[5];
    const float* Wo  = (const float*)d_in[6];
    const float* qw  = (const float*)d_in[7];
    const float* kw  = (const float*)d_in[8];

    float* out  = (float*)d_out;                       // [4096, 2048]
    float* kout = out  + (size_t)SEQ * EMB;            // [4, 4096, 128]
    float* vout = kout + (size_t)NKV * SEQ * HDIM;     // [4, 4096, 128]

    float *qproj, *kproj, *vproj, *q, *ctx;
    cudaGetSymbolAddress((void**)&qproj, g_qproj);
    cudaGetSymbolAddress((void**)&kproj, g_kproj);
    cudaGetSymbolAddress((void**)&vproj, g_vproj);
    cudaGetSymbolAddress((void**)&q,     g_q);
    cudaGetSymbolAddress((void**)&ctx,   g_ctx);

    // 0) rope table (cheap; overlaps nothing but costs ~16us)
    rope_table_kernel<<<SEQ, 64>>>(pos);

    // 1) projections
    sgemm128<<<dim3(EMB / 128, SEQ / 128), 256>>>(x, Wq, qproj, SEQ, EMB, EMB);
    sgemm128<<<dim3((NKV * HDIM) / 128, SEQ / 128), 256>>>(x, Wk, kproj, SEQ, NKV * HDIM, EMB);
    sgemm128<<<dim3((NKV * HDIM) / 128, SEQ / 128), 256>>>(x, Wv, vproj, SEQ, NKV * HDIM, EMB);

    // 2) rmsnorm + rope (+ V transpose straight into d_out)
    norm_rope_kernel<<<dim3(SEQ, 24), 128>>>(qproj, kproj, vproj,
                                             qw, kw, q, kout, vout);

    // 3) causal flash attention
    const int smem_bytes = FLASH_SMEM_FLOATS * (int)sizeof(float);
    cudaFuncSetAttribute(flash_kernel,
                         cudaFuncAttributeMaxDynamicSharedMemorySize, smem_bytes);
    flash_kernel<<<dim3(SEQ / 64, NHEADS), 256, smem_bytes>>>(q, kout, vout, ctx);

    // 4) output projection
    sgemm128<<<dim3(EMB / 128, SEQ / 128), 256>>>(ctx, Wo, out, SEQ, EMB, EMB);
}

// round 3
// speedup vs baseline: 1.6967x; 1.4831x over previous
#include <cuda_runtime.h>
#include <cuda_bf16.h>
#include <math.h>

// Problem constants
#define SEQ      4096
#define EMB      2048
#define NHEADS   16
#define NKV      4
#define HDIM     128
#define GROUP    (NHEADS / NKV)

typedef unsigned long long u64;
typedef unsigned int u32;

// ---------------- scratch (device globals; no allocation allowed) ----------
__device__ float g_qproj[SEQ * NHEADS * HDIM];   // 4096 x 2048
__device__ float g_kproj[SEQ * NKV * HDIM];      // 4096 x 512
__device__ float g_vproj[SEQ * NKV * HDIM];      // 4096 x 512
__device__ float g_q    [NHEADS * SEQ * HDIM];   // head-major Q after norm+rope
__device__ float g_ctx  [SEQ * NHEADS * HDIM];   // 4096 x 2048 attention output
__device__ float g_rcos [SEQ * 64];
__device__ float g_rsin [SEQ * 64];

// ---------------- f32x2 packed-math helpers (flash kernel) -----------------
__device__ __forceinline__ void fma2(u64& acc, u64 a, u64 b) {
    asm("fma.rn.f32x2 %0, %1, %2, %0;" : "+l"(acc) : "l"(a), "l"(b));
}
__device__ __forceinline__ u64 mul2(u64 a, u64 b) {
    u64 r; asm("mul.rn.f32x2 %0, %1, %2;" : "=l"(r) : "l"(a), "l"(b)); return r;
}
__device__ __forceinline__ u64 bc2(float x) {
    u64 r; unsigned u = __float_as_uint(x);
    asm("mov.b64 %0, {%1, %1};" : "=l"(r) : "r"(u)); return r;
}
__device__ __forceinline__ float2 unpk(u64 v) {
    float2 r;
    r.x = __uint_as_float((unsigned)(v & 0xffffffffULL));
    r.y = __uint_as_float((unsigned)(v >> 32));
    return r;
}

// ---------------- tf32 tensor-core helpers ----------------------------------
__device__ __forceinline__ u32 to_tf32(float f) {
    u32 u; asm("cvt.rna.tf32.f32 %0, %1;" : "=r"(u) : "f"(f)); return u;
}
__device__ __forceinline__ void mma_tf32(float c[4], uint4 a, u32 b0, u32 b1) {
    asm("mma.sync.aligned.m16n8k8.row.col.f32.tf32.tf32.f32 "
        "{%0,%1,%2,%3},{%4,%5,%6,%7},{%8,%9},{%0,%1,%2,%3};"
        : "+f"(c[0]), "+f"(c[1]), "+f"(c[2]), "+f"(c[3])
        : "r"(a.x), "r"(a.y), "r"(a.z), "r"(a.w), "r"(b0), "r"(b1));
}

// ---------------- tf32 MMA GEMM: C[M,N] = A[M,K] @ B[K,N], row-major -------
// BM=BN=128, BK=64, 256 threads (8 warps, 2x4), warp tile 64x32.
// A/B staged in SMEM in mma-fragment order with XOR bank swizzle:
//   A_s: idx = ((kt*8 + mt)*32 + (lane ^ kt))*4 + reg          (16KB*2)
//   B_s: idx = ((kt*16 + nt)*2 + reg)*32 + (lane ^ 4*(nt&7))
#define GEMM_SMEM_BYTES (16384 * 4)

__global__ void __launch_bounds__(256) mma_gemm(const float* __restrict__ A,
                                                const float* __restrict__ B,
                                                float* __restrict__ C,
                                                int M, int N, int K) {
    extern __shared__ u32 sm_u[];
    u32* As = sm_u;            // 8192 u32
    u32* Bs = sm_u + 8192;     // 8192 u32

    const int t    = threadIdx.x;
    const int lane = t & 31;
    const int wid  = t >> 5;
    const int wm   = wid >> 2;         // 0..1
    const int wn   = wid & 3;          // 0..3
    const int gr   = lane >> 2;
    const int ci   = lane & 3;
    const int row0 = blockIdx.y * 128;
    const int col0 = blockIdx.x * 128;

    // --- loader constants ---
    // A: pass p loads row m = p*16 + (t>>4), float4 at k4 = (t&15)*4
    const int a_r    = t >> 4;              // row-in-16 (= m & 15)
    const int a_k4   = (t & 15) * 4;
    const int a_kt   = (t & 15) >> 1;
    const int a_reg  = ((a_r >= 8) ? 1 : 0) + ((t & 1) ? 2 : 0);
    const int a_lb   = 4 * (a_r & 7);       // lane base; +j
    // B: pass p loads row k = p*8 + (t>>5), float4 at n4 = (t&31)*4
    const int b_kin  = t >> 5;              // k-in-8 (= ci of frag)
    const int b_n4   = (t & 31) * 4;
    const int b_nt   = (t & 31) >> 1;
    const int b_reg  = (b_kin >= 4) ? 1 : 0;
    const int b_lb   = 16 * (t & 1) + (b_kin & 3);  // lane = b_lb + 4*j
    const int b_swz  = 4 * (b_nt & 7);

    float c[4][4][4];
#pragma unroll
    for (int i = 0; i < 4; i++)
#pragma unroll
        for (int n = 0; n < 4; n++)
#pragma unroll
            for (int r = 0; r < 4; r++) c[i][n][r] = 0.f;

    for (int kb = 0; kb < K; kb += 64) {
        // ---- stage A tile (128x64) in fragment order ----
#pragma unroll
        for (int p = 0; p < 8; p++) {
            const int m = p * 16 + a_r;
            const float4 v = *(const float4*)&A[(size_t)(row0 + m) * K + kb + a_k4];
            const float va[4] = {v.x, v.y, v.z, v.w};
            const int base = ((a_kt * 8 + p) * 32);
#pragma unroll
            for (int j = 0; j < 4; j++) {
                As[(base + ((a_lb + j) ^ a_kt)) * 4 + a_reg] = to_tf32(va[j]);
            }
        }
        // ---- stage B tile (64x128) in fragment order ----
#pragma unroll
        for (int p = 0; p < 8; p++) {
            const int k = p * 8 + b_kin;
            const float4 v = *(const float4*)&B[(size_t)(kb + k) * N + col0 + b_n4];
            const float vb[4] = {v.x, v.y, v.z, v.w};
            const int base = ((p * 16 + b_nt) * 2 + b_reg) * 32;
#pragma unroll
            for (int j = 0; j < 4; j++) {
                Bs[base + ((b_lb + 4 * j) ^ b_swz)] = to_tf32(vb[j]);
            }
        }
        __syncthreads();

        // ---- mma over 8 k-steps ----
#pragma unroll
        for (int kt = 0; kt < 8; kt++) {
            uint4 af[4];
#pragma unroll
            for (int i = 0; i < 4; i++) {
                const int mt = wm * 4 + i;
                af[i] = *(const uint4*)&As[((kt * 8 + mt) * 32 + (lane ^ kt)) * 4];
            }
            u32 bf[4][2];
#pragma unroll
            for (int n = 0; n < 4; n++) {
                const int nt = wn * 4 + n;
                const int swz = 4 * (nt & 7);
                const int base = (kt * 16 + nt) * 2 * 32;
                bf[n][0] = Bs[base + (lane ^ swz)];
                bf[n][1] = Bs[base + 32 + (lane ^ swz)];
            }
#pragma unroll
            for (int i = 0; i < 4; i++)
#pragma unroll
                for (int n = 0; n < 4; n++)
                    mma_tf32(c[i][n], af[i], bf[n][0], bf[n][1]);
        }
        __syncthreads();
    }

    // ---- epilogue ----
#pragma unroll
    for (int i = 0; i < 4; i++) {
        const int row = row0 + wm * 64 + i * 16 + gr;
#pragma unroll
        for (int n = 0; n < 4; n++) {
            const int col = col0 + wn * 32 + n * 8 + 2 * ci;
            *(float2*)&C[(size_t)row * N + col] =
                make_float2(c[i][n][0], c[i][n][1]);
            *(float2*)&C[(size_t)(row + 8) * N + col] =
                make_float2(c[i][n][2], c[i][n][3]);
        }
    }
}

// ---------------- RoPE table precompute (once, tiny) ------------------------
__global__ void __launch_bounds__(64) rope_table_kernel(const int* __restrict__ pos_ids) {
    const int s = blockIdx.x;
    const int i = threadIdx.x;  // 0..63
    const float freq  = powf(10000.0f, -(float)i / 64.0f);
    const float ang_f = (float)pos_ids[s] * freq;   // fp32 like reference
    const double ang  = (double)ang_f;
    g_rcos[s * 64 + i] = (float)cos(ang);
    g_rsin[s * 64 + i] = (float)sin(ang);
}

// ---------------- RMSNorm + RoPE (+ V pass-through) ------------------------
__global__ void __launch_bounds__(128) norm_rope_kernel(
    const float* __restrict__ qproj, const float* __restrict__ kproj,
    const float* __restrict__ vproj,
    const float* __restrict__ qw, const float* __restrict__ kw,
    float* __restrict__ qout,  // [NHEADS][SEQ][HDIM]
    float* __restrict__ kout,  // [NKV][SEQ][HDIM]  (in d_out)
    float* __restrict__ vout)  // [NKV][SEQ][HDIM]  (in d_out)
{
    const int s    = blockIdx.x;
    const int unit = blockIdx.y;
    const int d    = threadIdx.x;

    if (unit >= 20) {                       // V: pure layout transpose
        const int kv = unit - 20;
        vout[((size_t)kv * SEQ + s) * HDIM + d] =
            vproj[(size_t)s * (NKV * HDIM) + kv * HDIM + d];
        return;
    }

    float v; const float* w;
    if (unit < 16) {
        v = qproj[(size_t)s * (NHEADS * HDIM) + unit * HDIM + d];
        w = qw;
    } else {
        v = kproj[(size_t)s * (NKV * HDIM) + (unit - 16) * HDIM + d];
        w = kw;
    }

    float sq = v * v;
#pragma unroll
    for (int off = 16; off > 0; off >>= 1)
        sq += __shfl_xor_sync(0xffffffffu, sq, off);
    __shared__ float wsum[4];
    if ((d & 31) == 0) wsum[d >> 5] = sq;
    __syncthreads();
    const float tot = wsum[0] + wsum[1] + wsum[2] + wsum[3];
    const float inv = rsqrtf(tot * (1.0f / HDIM) + 1e-6f);

    __shared__ float xn[HDIM];
    xn[d] = w[d] * v * inv;
    __syncthreads();

    const int i   = d & 63;
    const float c  = g_rcos[s * 64 + i];
    const float sn = g_rsin[s * 64 + i];
    float out;
    if (d < 64) out = xn[d] * c - xn[d + 64] * sn;
    else        out = xn[d] * c + xn[d - 64] * sn;

    if (unit < 16)
        qout[((size_t)unit * SEQ + s) * HDIM + d] = out;
    else
        kout[((size_t)(unit - 16) * SEQ + s) * HDIM + d] = out;
}

// ---------------- Flash attention (fp32, causal, f32x2 math) ---------------
#define KT_LD  68
#define STG_LD 132
#define PS_LD  68
#define FLASH_SMEM_FLOATS (64*128 + 128*KT_LD + 64*STG_LD + 64*PS_LD)

__global__ void __launch_bounds__(256, 1) flash_kernel(
    const float* __restrict__ Q,    // [NHEADS][SEQ][HDIM]
    const float* __restrict__ Kd,   // [NKV][SEQ][HDIM]
    const float* __restrict__ Vd,   // [NKV][SEQ][HDIM]
    float* __restrict__ ctx)        // [SEQ][NHEADS*HDIM]
{
    extern __shared__ float sm[];
    float* Qs  = sm;                       // [64][128]
    float* KT  = Qs  + 64 * 128;           // [128][KT_LD]
    float* STG = KT  + 128 * KT_LD;        // [64][STG_LD]
    float* Ps  = STG + 64 * STG_LD;        // [64][PS_LD]

    const int tid  = threadIdx.x;
    const int tx   = tid & 15;
    const int ty   = tid >> 4;
    const int qt   = blockIdx.x;
    const int head = blockIdx.y;
    const int kv   = head / GROUP;
    const int q0   = qt * 64;

    {
        const float4* src = (const float4*)(Q + ((size_t)head * SEQ + q0) * HDIM);
        float4* dst = (float4*)Qs;
        for (int i = tid; i < 64 * 32; i += 256) dst[i] = src[i];
    }

    u64 o2[4][4];
#pragma unroll
    for (int i = 0; i < 4; i++)
#pragma unroll
        for (int j = 0; j < 4; j++) o2[i][j] = 0ULL;
    float m_i[4] = {-INFINITY, -INFINITY, -INFINITY, -INFINITY};
    float l_i[4] = {0.f, 0.f, 0.f, 0.f};

    const float scale = 0.08838834764831845f;
    const int ntiles = qt + 1;

    for (int jt = 0; jt < ntiles; jt++) {
        const int k0 = jt * 64;

        {
            const float* Kbase = Kd + ((size_t)kv * SEQ + k0) * HDIM;
            for (int i = tid; i < 64 * 32; i += 256) {
                const int row = i >> 5, c = (i & 31) * 4;
                *(float4*)&STG[row * STG_LD + c] =
                    *(const float4*)(Kbase + row * HDIM + c);
            }
        }
        __syncthreads();

        for (int i = tid; i < 64 * 32; i += 256) {
            const int key = i & 63, dv = i >> 6;
            float4 v = *(const float4*)&STG[key * STG_LD + 4 * dv];
            KT[(4 * dv + 0) * KT_LD + key] = v.x;
            KT[(4 * dv + 1) * KT_LD + key] = v.y;
            KT[(4 * dv + 2) * KT_LD + key] = v.z;
            KT[(4 * dv + 3) * KT_LD + key] = v.w;
        }
        __syncthreads();

        {
            const float* Vbase = Vd + ((size_t)kv * SEQ + k0) * HDIM;
            for (int i = tid; i < 64 * 32; i += 256) {
                const int row = i >> 5, c = (i & 31) * 4;
                *(float4*)&STG[row * STG_LD + c] =
                    *(const float4*)(Vbase + row * HDIM + c);
            }
        }

        u64 s2[4][2];
#pragma unroll
        for (int i = 0; i < 4; i++) { s2[i][0] = 0ULL; s2[i][1] = 0ULL; }

#pragma unroll 8
        for (int d0 = 0; d0 < 128; d0 += 4) {
            float4 qv[4];
            ulonglong2 ktp[4];
#pragma unroll
            for (int i = 0; i < 4; i++)
                qv[i] = *(const float4*)&Qs[(4 * ty + i) * 128 + d0];
#pragma unroll
            for (int dd = 0; dd < 4; dd++)
                ktp[dd] = *(const ulonglong2*)&KT[(d0 + dd) * KT_LD + 4 * tx];
#pragma unroll
            for (int i = 0; i < 4; i++) {
                const float qe[4] = {qv[i].x, qv[i].y, qv[i].z, qv[i].w};
#pragma unroll
                for (int dd = 0; dd < 4; dd++) {
                    u64 qq = bc2(qe[dd]);
                    fma2(s2[i][0], qq, ktp[dd].x);
                    fma2(s2[i][1], qq, ktp[dd].y);
                }
            }
        }

        const bool diag = (jt == qt);
#pragma unroll
        for (int i = 0; i < 4; i++) {
            const int q_idx = q0 + 4 * ty + i;
            float2 sa = unpk(s2[i][0]);
            float2 sb = unpk(s2[i][1]);
            float sv[4] = {sa.x, sa.y, sb.x, sb.y};
#pragma unroll
            for (int j = 0; j < 4; j++) {
                float s = sv[j] * scale;
                if (diag && (k0 + 4 * tx + j > q_idx)) s = -1.0e9f;
                sv[j] = s;
            }
            float rm = fmaxf(fmaxf(sv[0], sv[1]), fmaxf(sv[2], sv[3]));
#pragma unroll
            for (int off = 8; off > 0; off >>= 1)
                rm = fmaxf(rm, __shfl_xor_sync(0xffffffffu, rm, off));
            const float m_new = fmaxf(m_i[i], rm);
            const float corr  = __expf(m_i[i] - m_new);
            float pj[4], rs = 0.f;
#pragma unroll
            for (int j = 0; j < 4; j++) { pj[j] = __expf(sv[j] - m_new); rs += pj[j]; }
#pragma unroll
            for (int off = 8; off > 0; off >>= 1)
                rs += __shfl_xor_sync(0xffffffffu, rs, off);
            l_i[i] = l_i[i] * corr + rs;
            m_i[i] = m_new;
            u64 cc = bc2(corr);
#pragma unroll
            for (int j = 0; j < 4; j++) o2[i][j] = mul2(o2[i][j], cc);
            *(float4*)&Ps[(4 * ty + i) * PS_LD + 4 * tx] =
                make_float4(pj[0], pj[1], pj[2], pj[3]);
        }
        __syncthreads();

#pragma unroll 4
        for (int k0i = 0; k0i < 64; k0i += 4) {
            float4 p[4];
#pragma unroll
            for (int i = 0; i < 4; i++)
                p[i] = *(const float4*)&Ps[(4 * ty + i) * PS_LD + k0i];
#pragma unroll
            for (int kk = 0; kk < 4; kk++) {
                const ulonglong2* vp =
                    (const ulonglong2*)&STG[(k0i + kk) * STG_LD + 8 * tx];
                ulonglong2 v01 = vp[0];
                ulonglong2 v23 = vp[1];
                u64 vv[4] = {v01.x, v01.y, v23.x, v23.y};
#pragma unroll
                for (int i = 0; i < 4; i++) {
                    const float pm = (kk == 0) ? p[i].x : (kk == 1) ? p[i].y
                                   : (kk == 2) ? p[i].z : p[i].w;
                    u64 pp = bc2(pm);
#pragma unroll
                    for (int j = 0; j < 4; j++) fma2(o2[i][j], pp, vv[j]);
                }
            }
        }
        __syncthreads();
    }

#pragma unroll
    for (int i = 0; i < 4; i++) {
        const float inv = 1.0f / l_i[i];
        float* dst = ctx + (size_t)(q0 + 4 * ty + i) * (NHEADS * HDIM)
                         + head * HDIM + 8 * tx;
        float2 a = unpk(o2[i][0]);
        float2 b = unpk(o2[i][1]);
        float2 c = unpk(o2[i][2]);
        float2 d = unpk(o2[i][3]);
        *(float4*)(dst)     = make_float4(a.x * inv, a.y * inv, b.x * inv, b.y * inv);
        *(float4*)(dst + 4) = make_float4(c.x * inv, c.y * inv, d.x * inv, d.y * inv);
    }
}

// ---------------- launch ----------------------------------------------------
extern "C" void kernel_launch(void* const* d_in, const int* in_sizes, int n_in,
                              void* d_out, int out_size) {
    const float* x   = (const float*)d_in[0];
    const int*   pos = (const int*)  d_in[1];
    // d_in[2] = attn_mask (pure causal triu(-1e9)) -- implemented analytically
    const float* Wq  = (const float*)d_in[3];
    const float* Wk  = (const float*)d_in[4];
    const float* Wv  = (const float*)d_in[5];
    const float* Wo  = (const float*)d_in[6];
    const float* qw  = (const float*)d_in[7];
    const float* kw  = (const float*)d_in[8];

    float* out  = (float*)d_out;                       // [4096, 2048]
    float* kout = out  + (size_t)SEQ * EMB;            // [4, 4096, 128]
    float* vout = kout + (size_t)NKV * SEQ * HDIM;     // [4, 4096, 128]

    float *qproj, *kproj, *vproj, *q, *ctx;
    cudaGetSymbolAddress((void**)&qproj, g_qproj);
    cudaGetSymbolAddress((void**)&kproj, g_kproj);
    cudaGetSymbolAddress((void**)&vproj, g_vproj);
    cudaGetSymbolAddress((void**)&q,     g_q);
    cudaGetSymbolAddress((void**)&ctx,   g_ctx);

    cudaFuncSetAttribute(mma_gemm,
                         cudaFuncAttributeMaxDynamicSharedMemorySize, GEMM_SMEM_BYTES);

    // 0) rope table
    rope_table_kernel<<<SEQ, 64>>>(pos);

    // 1) projections (tf32 tensor cores)
    mma_gemm<<<dim3(EMB / 128, SEQ / 128), 256, GEMM_SMEM_BYTES>>>(x, Wq, qproj, SEQ, EMB, EMB);
    mma_gemm<<<dim3((NKV * HDIM) / 128, SEQ / 128), 256, GEMM_SMEM_BYTES>>>(x, Wk, kproj, SEQ, NKV * HDIM, EMB);
    mma_gemm<<<dim3((NKV * HDIM) / 128, SEQ / 128), 256, GEMM_SMEM_BYTES>>>(x, Wv, vproj, SEQ, NKV * HDIM, EMB);

    // 2) rmsnorm + rope (+ V transpose straight into d_out)
    norm_rope_kernel<<<dim3(SEQ, 24), 128>>>(qproj, kproj, vproj,
                                             qw, kw, q, kout, vout);

    // 3) causal flash attention
    const int smem_bytes = FLASH_SMEM_FLOATS * (int)sizeof(float);
    cudaFuncSetAttribute(flash_kernel,
                         cudaFuncAttributeMaxDynamicSharedMemorySize, smem_bytes);
    flash_kernel<<<dim3(SEQ / 64, NHEADS), 256, smem_bytes>>>(q, kout, vout, ctx);

    // 4) output projection (tf32 tensor cores)
    mma_gemm<<<dim3(EMB / 128, SEQ / 128), 256, GEMM_SMEM_BYTES>>>(ctx, Wo, out, SEQ, EMB, EMB);
}

// round 4
// speedup vs baseline: 3.6367x; 2.1435x over previous
#include <cuda_runtime.h>
#include <cuda_bf16.h>
#include <math.h>

// Problem constants
#define SEQ      4096
#define EMB      2048
#define NHEADS   16
#define NKV      4
#define HDIM     128
#define GROUP    (NHEADS / NKV)

typedef unsigned long long u64;
typedef unsigned int u32;

// ---------------- scratch (device globals; no allocation allowed) ----------
__device__ float g_qproj[SEQ * NHEADS * HDIM];   // 4096 x 2048
__device__ float g_kproj[SEQ * NKV * HDIM];      // 4096 x 512
__device__ float g_vproj[SEQ * NKV * HDIM];      // 4096 x 512
__device__ float g_q    [NHEADS * SEQ * HDIM];   // head-major Q after norm+rope
__device__ float g_ctx  [SEQ * NHEADS * HDIM];   // 4096 x 2048 attention output
__device__ float g_rcos [SEQ * 64];
__device__ float g_rsin [SEQ * 64];

// ---------------- tf32 tensor-core helpers ----------------------------------
__device__ __forceinline__ u32 to_tf32(float f) {
    u32 u; asm("cvt.rna.tf32.f32 %0, %1;" : "=r"(u) : "f"(f)); return u;
}
__device__ __forceinline__ void mma_tf32(float c[4], uint4 a, u32 b0, u32 b1) {
    asm("mma.sync.aligned.m16n8k8.row.col.f32.tf32.tf32.f32 "
        "{%0,%1,%2,%3},{%4,%5,%6,%7},{%8,%9},{%0,%1,%2,%3};"
        : "+f"(c[0]), "+f"(c[1]), "+f"(c[2]), "+f"(c[3])
        : "r"(a.x), "r"(a.y), "r"(a.z), "r"(a.w), "r"(b0), "r"(b1));
}

// ---------------- tf32 MMA GEMM: C[M,N] = A[M,K] @ B[K,N], row-major -------
// BM=BN=128, BK=64, 256 threads (8 warps, 2x4), warp tile 64x32.
#define GEMM_SMEM_BYTES (16384 * 4)

__global__ void __launch_bounds__(256, 2) mma_gemm(const float* __restrict__ A,
                                                   const float* __restrict__ B,
                                                   float* __restrict__ C,
                                                   int M, int N, int K) {
    extern __shared__ u32 sm_u[];
    u32* As = sm_u;            // 8192 u32
    u32* Bs = sm_u + 8192;     // 8192 u32

    const int t    = threadIdx.x;
    const int lane = t & 31;
    const int wid  = t >> 5;
    const int wm   = wid >> 2;         // 0..1
    const int wn   = wid & 3;          // 0..3
    const int gr   = lane >> 2;
    const int ci   = lane & 3;
    const int row0 = blockIdx.y * 128;
    const int col0 = blockIdx.x * 128;

    const int a_r    = t >> 4;
    const int a_k4   = (t & 15) * 4;
    const int a_kt   = (t & 15) >> 1;
    const int a_reg  = ((a_r >= 8) ? 1 : 0) + ((t & 1) ? 2 : 0);
    const int a_lb   = 4 * (a_r & 7);
    const int b_kin  = t >> 5;
    const int b_n4   = (t & 31) * 4;
    const int b_nt   = (t & 31) >> 1;
    const int b_reg  = (b_kin >= 4) ? 1 : 0;
    const int b_lb   = 16 * (t & 1) + (b_kin & 3);
    const int b_swz  = 4 * (b_nt & 7);

    float c[4][4][4];
#pragma unroll
    for (int i = 0; i < 4; i++)
#pragma unroll
        for (int n = 0; n < 4; n++)
#pragma unroll
            for (int r = 0; r < 4; r++) c[i][n][r] = 0.f;

    for (int kb = 0; kb < K; kb += 64) {
#pragma unroll
        for (int p = 0; p < 8; p++) {
            const int m = p * 16 + a_r;
            const float4 v = *(const float4*)&A[(size_t)(row0 + m) * K + kb + a_k4];
            const float va[4] = {v.x, v.y, v.z, v.w};
            const int base = ((a_kt * 8 + p) * 32);
#pragma unroll
            for (int j = 0; j < 4; j++) {
                As[(base + ((a_lb + j) ^ a_kt)) * 4 + a_reg] = to_tf32(va[j]);
            }
        }
#pragma unroll
        for (int p = 0; p < 8; p++) {
            const int k = p * 8 + b_kin;
            const float4 v = *(const float4*)&B[(size_t)(kb + k) * N + col0 + b_n4];
            const float vb[4] = {v.x, v.y, v.z, v.w};
            const int base = ((p * 16 + b_nt) * 2 + b_reg) * 32;
#pragma unroll
            for (int j = 0; j < 4; j++) {
                Bs[base + ((b_lb + 4 * j) ^ b_swz)] = to_tf32(vb[j]);
            }
        }
        __syncthreads();

#pragma unroll
        for (int kt = 0; kt < 8; kt++) {
            uint4 af[4];
#pragma unroll
            for (int i = 0; i < 4; i++) {
                const int mt = wm * 4 + i;
                af[i] = *(const uint4*)&As[((kt * 8 + mt) * 32 + (lane ^ kt)) * 4];
            }
            u32 bf[4][2];
#pragma unroll
            for (int n = 0; n < 4; n++) {
                const int nt = wn * 4 + n;
                const int swz = 4 * (nt & 7);
                const int base = (kt * 16 + nt) * 2 * 32;
                bf[n][0] = Bs[base + (lane ^ swz)];
                bf[n][1] = Bs[base + 32 + (lane ^ swz)];
            }
#pragma unroll
            for (int i = 0; i < 4; i++)
#pragma unroll
                for (int n = 0; n < 4; n++)
                    mma_tf32(c[i][n], af[i], bf[n][0], bf[n][1]);
        }
        __syncthreads();
    }

#pragma unroll
    for (int i = 0; i < 4; i++) {
        const int row = row0 + wm * 64 + i * 16 + gr;
#pragma unroll
        for (int n = 0; n < 4; n++) {
            const int col = col0 + wn * 32 + n * 8 + 2 * ci;
            *(float2*)&C[(size_t)row * N + col] =
                make_float2(c[i][n][0], c[i][n][1]);
            *(float2*)&C[(size_t)(row + 8) * N + col] =
                make_float2(c[i][n][2], c[i][n][3]);
        }
    }
}

// ---------------- RoPE table precompute (once, tiny) ------------------------
__global__ void __launch_bounds__(64) rope_table_kernel(const int* __restrict__ pos_ids) {
    const int s = blockIdx.x;
    const int i = threadIdx.x;  // 0..63
    const float freq  = powf(10000.0f, -(float)i / 64.0f);
    const float ang_f = (float)pos_ids[s] * freq;   // fp32 like reference
    const double ang  = (double)ang_f;
    g_rcos[s * 64 + i] = (float)cos(ang);
    g_rsin[s * 64 + i] = (float)sin(ang);
}

// ---------------- RMSNorm + RoPE (+ V pass-through) ------------------------
__global__ void __launch_bounds__(128) norm_rope_kernel(
    const float* __restrict__ qproj, const float* __restrict__ kproj,
    const float* __restrict__ vproj,
    const float* __restrict__ qw, const float* __restrict__ kw,
    float* __restrict__ qout,  // [NHEADS][SEQ][HDIM]
    float* __restrict__ kout,  // [NKV][SEQ][HDIM]  (in d_out)
    float* __restrict__ vout)  // [NKV][SEQ][HDIM]  (in d_out)
{
    const int s    = blockIdx.x;
    const int unit = blockIdx.y;
    const int d    = threadIdx.x;

    if (unit >= 20) {                       // V: pure layout transpose
        const int kv = unit - 20;
        vout[((size_t)kv * SEQ + s) * HDIM + d] =
            vproj[(size_t)s * (NKV * HDIM) + kv * HDIM + d];
        return;
    }

    float v; const float* w;
    if (unit < 16) {
        v = qproj[(size_t)s * (NHEADS * HDIM) + unit * HDIM + d];
        w = qw;
    } else {
        v = kproj[(size_t)s * (NKV * HDIM) + (unit - 16) * HDIM + d];
        w = kw;
    }

    float sq = v * v;
#pragma unroll
    for (int off = 16; off > 0; off >>= 1)
        sq += __shfl_xor_sync(0xffffffffu, sq, off);
    __shared__ float wsum[4];
    if ((d & 31) == 0) wsum[d >> 5] = sq;
    __syncthreads();
    const float tot = wsum[0] + wsum[1] + wsum[2] + wsum[3];
    const float inv = rsqrtf(tot * (1.0f / HDIM) + 1e-6f);

    __shared__ float xn[HDIM];
    xn[d] = w[d] * v * inv;
    __syncthreads();

    const int i   = d & 63;
    const float c  = g_rcos[s * 64 + i];
    const float sn = g_rsin[s * 64 + i];
    float out;
    if (d < 64) out = xn[d] * c - xn[d + 64] * sn;
    else        out = xn[d] * c + xn[d - 64] * sn;

    if (unit < 16)
        qout[((size_t)unit * SEQ + s) * HDIM + d] = out;
    else
        kout[((size_t)(unit - 16) * SEQ + s) * HDIM + d] = out;
}

// ---------------- Flash attention (tf32 tensor cores, causal) --------------
// BM=128, BN=64, D=128. 256 threads, 8 warps; warp w owns query rows
// [w*16, w*16+16). m16n8k8 tf32 MMA for S=Q@K^T and O+=P@V.
// All SMEM leading dims ≡ 4 (mod 32) -> conflict-free fragment LDS.
#define FQ_LD 132
#define FK_LD 132
#define FV_LD 68
#define FP_LD 68
#define FLASH_SMEM_WORDS (128*FQ_LD + 64*FK_LD + 128*FV_LD + 128*FP_LD)
#define FLASH_SMEM_BYTES (FLASH_SMEM_WORDS * 4)

__global__ void __launch_bounds__(256, 1) flash_mma(
    const float* __restrict__ Q,    // [NHEADS][SEQ][HDIM]
    const float* __restrict__ Kd,   // [NKV][SEQ][HDIM]
    const float* __restrict__ Vd,   // [NKV][SEQ][HDIM]
    float* __restrict__ ctx)        // [SEQ][NHEADS*HDIM]
{
    extern __shared__ u32 smu[];
    u32* Qs = smu;                      // [128][FQ_LD] tf32
    u32* Ks = Qs + 128 * FQ_LD;         // [64][FK_LD]  tf32
    u32* Vt = Ks + 64 * FK_LD;          // [128 dims][FV_LD keys] tf32
    u32* Ps = Vt + 128 * FV_LD;         // [128][FP_LD] tf32 P; doubles as V staging [64][132]

    const int tid  = threadIdx.x;
    const int lane = tid & 31;
    const int w    = tid >> 5;
    const int g    = lane >> 2;
    const int t    = lane & 3;
    const int qt   = blockIdx.x;
    const int head = blockIdx.y;
    const int kv   = head / GROUP;
    const int q0   = qt * 128;
    const int rw   = w * 16;

    // ---- stage Q tile (tf32) ----
    {
        const float4* src = (const float4*)(Q + ((size_t)head * SEQ + q0) * HDIM);
        for (int i = tid; i < 128 * 32; i += 256) {
            const int row = i >> 5, c = (i & 31) * 4;
            float4 v = src[i];
            u32* d = &Qs[row * FQ_LD + c];
            d[0] = to_tf32(v.x); d[1] = to_tf32(v.y);
            d[2] = to_tf32(v.z); d[3] = to_tf32(v.w);
        }
    }
    __syncthreads();

    // ---- preload Q fragments (persistent across KV loop) ----
    uint4 af[16];
#pragma unroll
    for (int kt = 0; kt < 16; kt++) {
        af[kt].x = Qs[(rw + g)     * FQ_LD + kt * 8 + t];
        af[kt].y = Qs[(rw + g + 8) * FQ_LD + kt * 8 + t];
        af[kt].z = Qs[(rw + g)     * FQ_LD + kt * 8 + t + 4];
        af[kt].w = Qs[(rw + g + 8) * FQ_LD + kt * 8 + t + 4];
    }

    float o[16][4];
#pragma unroll
    for (int n = 0; n < 16; n++)
#pragma unroll
        for (int r = 0; r < 4; r++) o[n][r] = 0.f;
    float mA = -INFINITY, mB = -INFINITY, lA = 0.f, lB = 0.f;

    const float scale = 0.08838834764831845f;   // 1/sqrt(128)
    const int rowA = q0 + rw + g;
    const int rowB = rowA + 8;
    const int njt  = 2 * qt + 2;

    for (int jt = 0; jt < njt; jt++) {
        const int k0 = jt * 64;

        // ---- stage K (tf32) and V (tf32, raw layout into Ps staging) ----
        {
            const float4* ksrc = (const float4*)(Kd + ((size_t)kv * SEQ + k0) * HDIM);
            const float4* vsrc = (const float4*)(Vd + ((size_t)kv * SEQ + k0) * HDIM);
            for (int i = tid; i < 64 * 32; i += 256) {
                const int row = i >> 5, c = (i & 31) * 4;
                float4 a = ksrc[i];
                u32* dk = &Ks[row * FK_LD + c];
                dk[0] = to_tf32(a.x); dk[1] = to_tf32(a.y);
                dk[2] = to_tf32(a.z); dk[3] = to_tf32(a.w);
                float4 b = vsrc[i];
                u32* dv = &Ps[row * 132 + c];
                dv[0] = to_tf32(b.x); dv[1] = to_tf32(b.y);
                dv[2] = to_tf32(b.z); dv[3] = to_tf32(b.w);
            }
        }
        __syncthreads();

        // ---- transpose V staging -> Vt[dim][key] ----
        for (int i = tid; i < 64 * 32; i += 256) {
            const int key = i & 63, dv4 = i >> 6;   // dv4 0..31
            uint4 vv = *(const uint4*)&Ps[key * 132 + 4 * dv4];
            Vt[(4 * dv4 + 0) * FV_LD + key] = vv.x;
            Vt[(4 * dv4 + 1) * FV_LD + key] = vv.y;
            Vt[(4 * dv4 + 2) * FV_LD + key] = vv.z;
            Vt[(4 * dv4 + 3) * FV_LD + key] = vv.w;
        }
        __syncthreads();

        // ---- S = Q @ K^T : warp tile 16x64, 16 k-steps x 8 n-tiles ----
        float s[8][4];
#pragma unroll
        for (int n = 0; n < 8; n++)
#pragma unroll
            for (int r = 0; r < 4; r++) s[n][r] = 0.f;

#pragma unroll
        for (int kt = 0; kt < 16; kt++) {
#pragma unroll
            for (int nt = 0; nt < 8; nt++) {
                const u32 b0 = Ks[(nt * 8 + g) * FK_LD + kt * 8 + t];
                const u32 b1 = Ks[(nt * 8 + g) * FK_LD + kt * 8 + t + 4];
                mma_tf32(s[nt], af[kt], b0, b1);
            }
        }

        // ---- scale + causal mask ----
        const bool dodiag = (jt >= 2 * qt);
#pragma unroll
        for (int nt = 0; nt < 8; nt++) {
            const int c0 = k0 + nt * 8 + 2 * t;
            const int c1 = c0 + 1;
            s[nt][0] *= scale; s[nt][1] *= scale;
            s[nt][2] *= scale; s[nt][3] *= scale;
            if (dodiag) {
                if (c0 > rowA) s[nt][0] = -1e30f;
                if (c1 > rowA) s[nt][1] = -1e30f;
                if (c0 > rowB) s[nt][2] = -1e30f;
                if (c1 > rowB) s[nt][3] = -1e30f;
            }
        }

        // ---- online softmax (rows g, g+8 private to quad) ----
        float mxA = -1e30f, mxB = -1e30f;
#pragma unroll
        for (int nt = 0; nt < 8; nt++) {
            mxA = fmaxf(mxA, fmaxf(s[nt][0], s[nt][1]));
            mxB = fmaxf(mxB, fmaxf(s[nt][2], s[nt][3]));
        }
        mxA = fmaxf(mxA, __shfl_xor_sync(0xffffffffu, mxA, 1));
        mxA = fmaxf(mxA, __shfl_xor_sync(0xffffffffu, mxA, 2));
        mxB = fmaxf(mxB, __shfl_xor_sync(0xffffffffu, mxB, 1));
        mxB = fmaxf(mxB, __shfl_xor_sync(0xffffffffu, mxB, 2));

        const float mnA = fmaxf(mA, mxA);
        const float mnB = fmaxf(mB, mxB);
        const float cA  = __expf(mA - mnA);
        const float cB  = __expf(mB - mnB);

        float sA = 0.f, sB = 0.f;
#pragma unroll
        for (int nt = 0; nt < 8; nt++) {
            const float p0 = __expf(s[nt][0] - mnA);
            const float p1 = __expf(s[nt][1] - mnA);
            const float p2 = __expf(s[nt][2] - mnB);
            const float p3 = __expf(s[nt][3] - mnB);
            sA += p0 + p1;  sB += p2 + p3;
            const int cc = nt * 8 + 2 * t;
            Ps[(rw + g)     * FP_LD + cc]     = to_tf32(p0);
            Ps[(rw + g)     * FP_LD + cc + 1] = to_tf32(p1);
            Ps[(rw + g + 8) * FP_LD + cc]     = to_tf32(p2);
            Ps[(rw + g + 8) * FP_LD + cc + 1] = to_tf32(p3);
        }
        sA += __shfl_xor_sync(0xffffffffu, sA, 1);
        sA += __shfl_xor_sync(0xffffffffu, sA, 2);
        sB += __shfl_xor_sync(0xffffffffu, sB, 1);
        sB += __shfl_xor_sync(0xffffffffu, sB, 2);

        lA = lA * cA + sA;  lB = lB * cB + sB;
        mA = mnA;           mB = mnB;
#pragma unroll
        for (int nt = 0; nt < 16; nt++) {
            o[nt][0] *= cA;  o[nt][1] *= cA;
            o[nt][2] *= cB;  o[nt][3] *= cB;
        }
        __syncwarp();   // P rows are warp-private; order STS -> LDS

        // ---- O += P @ V : 8 k-steps x 16 n-tiles ----
#pragma unroll
        for (int kt = 0; kt < 8; kt++) {
            uint4 pf;
            pf.x = Ps[(rw + g)     * FP_LD + kt * 8 + t];
            pf.y = Ps[(rw + g + 8) * FP_LD + kt * 8 + t];
            pf.z = Ps[(rw + g)     * FP_LD + kt * 8 + t + 4];
            pf.w = Ps[(rw + g + 8) * FP_LD + kt * 8 + t + 4];
#pragma unroll
            for (int nt = 0; nt < 16; nt++) {
                const u32 b0 = Vt[(nt * 8 + g) * FV_LD + kt * 8 + t];
                const u32 b1 = Vt[(nt * 8 + g) * FV_LD + kt * 8 + t + 4];
                mma_tf32(o[nt], pf, b0, b1);
            }
        }
        __syncthreads();   // protect Ks/Ps/Vt for next iteration
    }

    // ---- epilogue: normalize, scatter to ctx[s][head*128 + d] ----
    const float iA = 1.0f / lA;
    const float iB = 1.0f / lB;
#pragma unroll
    for (int nt = 0; nt < 16; nt++) {
        const int col = head * HDIM + nt * 8 + 2 * t;
        *(float2*)&ctx[(size_t)rowA * EMB + col] =
            make_float2(o[nt][0] * iA, o[nt][1] * iA);
        *(float2*)&ctx[(size_t)rowB * EMB + col] =
            make_float2(o[nt][2] * iB, o[nt][3] * iB);
    }
}

// ---------------- launch ----------------------------------------------------
extern "C" void kernel_launch(void* const* d_in, const int* in_sizes, int n_in,
                              void* d_out, int out_size) {
    const float* x   = (const float*)d_in[0];
    const int*   pos = (const int*)  d_in[1];
    // d_in[2] = attn_mask (pure causal triu(-1e9)) -- implemented analytically
    const float* Wq  = (const float*)d_in[3];
    const float* Wk  = (const float*)d_in[4];
    const float* Wv  = (const float*)d_in[5];
    const float* Wo  = (const float*)d_in[6];
    const float* qw  = (const float*)d_in[7];
    const float* kw  = (const float*)d_in[8];

    float* out  = (float*)d_out;                       // [4096, 2048]
    float* kout = out  + (size_t)SEQ * EMB;            // [4, 4096, 128]
    float* vout = kout + (size_t)NKV * SEQ * HDIM;     // [4, 4096, 128]

    float *qproj, *kproj, *vproj, *q, *ctx;
    cudaGetSymbolAddress((void**)&qproj, g_qproj);
    cudaGetSymbolAddress((void**)&kproj, g_kproj);
    cudaGetSymbolAddress((void**)&vproj, g_vproj);
    cudaGetSymbolAddress((void**)&q,     g_q);
    cudaGetSymbolAddress((void**)&ctx,   g_ctx);

    cudaFuncSetAttribute(mma_gemm,
                         cudaFuncAttributeMaxDynamicSharedMemorySize, GEMM_SMEM_BYTES);
    cudaFuncSetAttribute(flash_mma,
                         cudaFuncAttributeMaxDynamicSharedMemorySize, FLASH_SMEM_BYTES);

    // 0) rope table
    rope_table_kernel<<<SEQ, 64>>>(pos);

    // 1) projections (tf32 tensor cores)
    mma_gemm<<<dim3(EMB / 128, SEQ / 128), 256, GEMM_SMEM_BYTES>>>(x, Wq, qproj, SEQ, EMB, EMB);
    mma_gemm<<<dim3((NKV * HDIM) / 128, SEQ / 128), 256, GEMM_SMEM_BYTES>>>(x, Wk, kproj, SEQ, NKV * HDIM, EMB);
    mma_gemm<<<dim3((NKV * HDIM) / 128, SEQ / 128), 256, GEMM_SMEM_BYTES>>>(x, Wv, vproj, SEQ, NKV * HDIM, EMB);

    // 2) rmsnorm + rope (+ V transpose straight into d_out)
    norm_rope_kernel<<<dim3(SEQ, 24), 128>>>(qproj, kproj, vproj,
                                             qw, kw, q, kout, vout);

    // 3) causal flash attention (tf32 tensor cores)
    flash_mma<<<dim3(SEQ / 128, NHEADS), 256, FLASH_SMEM_BYTES>>>(q, kout, vout, ctx);

    // 4) output projection (tf32 tensor cores)
    mma_gemm<<<dim3(EMB / 128, SEQ / 128), 256, GEMM_SMEM_BYTES>>>(ctx, Wo, out, SEQ, EMB, EMB);
}

// round 6
// speedup vs baseline: 6.8486x; 1.8832x over previous
#include <cuda_runtime.h>
#include <cuda_fp16.h>
#include <math.h>
#include <stdint.h>

// Problem constants
#define SEQ      4096
#define EMB      2048
#define NHEADS   16
#define NKV      4
#define HDIM     128
#define GROUP    (NHEADS / NKV)

typedef unsigned long long u64;
typedef unsigned int u32;

// ---------------- scratch (device globals; no allocation allowed) ----------
__device__ float  g_qproj[SEQ * NHEADS * HDIM];   // 4096 x 2048 fp32
__device__ float  g_kproj[SEQ * NKV * HDIM];
__device__ float  g_vproj[SEQ * NKV * HDIM];
__device__ __half g_xh  [SEQ * EMB];              // x in half
__device__ __half g_qh  [NHEADS * SEQ * HDIM];    // Q after norm+rope, half
__device__ __half g_ctxh[SEQ * NHEADS * HDIM];    // attention output, half
__device__ float  g_rcos[SEQ * 64];
__device__ float  g_rsin[SEQ * 64];
// transposed half weights: [N][K] (K contiguous)
__device__ __half g_wqt[EMB * EMB];
__device__ __half g_wkt[(NKV*HDIM) * EMB];
__device__ __half g_wvt[(NKV*HDIM) * EMB];
__device__ __half g_wot[EMB * EMB];

// ---------------- helpers ----------------------------------------------------
__device__ __forceinline__ u32 f2h2(float lo, float hi) {
    __half2 h = __floats2half2_rn(lo, hi);
    return *reinterpret_cast<u32*>(&h);
}
__device__ __forceinline__ void mma_f16(float c[4], uint4 a, u32 b0, u32 b1) {
    asm("mma.sync.aligned.m16n8k16.row.col.f32.f16.f16.f32 "
        "{%0,%1,%2,%3},{%4,%5,%6,%7},{%8,%9},{%0,%1,%2,%3};"
        : "+f"(c[0]), "+f"(c[1]), "+f"(c[2]), "+f"(c[3])
        : "r"(a.x), "r"(a.y), "r"(a.z), "r"(a.w), "r"(b0), "r"(b1));
}

// ---------------- fp32 -> fp16 bulk convert ---------------------------------
__global__ void __launch_bounds__(256) f32_to_f16(const float* __restrict__ in,
                                                  __half* __restrict__ out) {
    const int i = blockIdx.x * 256 + threadIdx.x;
    float4 v = ((const float4*)in)[i];
    ((uint2*)out)[i] = make_uint2(f2h2(v.x, v.y), f2h2(v.z, v.w));
}

// ---------------- weight transpose + half convert: out[n][k]=h(in[k][n]) ----
__global__ void __launch_bounds__(256) transpose_half(
    const float* __restrict__ in, __half* __restrict__ out, int K, int N) {
    __shared__ __half t[32][33];
    const int n0 = blockIdx.x * 32, k0 = blockIdx.y * 32;
    const int x = threadIdx.x & 31, y = threadIdx.x >> 5;
#pragma unroll
    for (int j = 0; j < 4; j++) {
        const int k = y + j * 8;
        t[k][x] = __float2half_rn(in[(size_t)(k0 + k) * N + n0 + x]);
    }
    __syncthreads();
#pragma unroll
    for (int j = 0; j < 4; j++) {
        const int n = y + j * 8;
        out[(size_t)(n0 + n) * K + k0 + x] = t[x][n];
    }
}

// ---------------- fp16 MMA GEMM: C[M,N] = Ah[M,K] @ Bh[N,K]^T ---------------
// BM=BN=128, BK=64, 256 threads (8 warps 2x4), warp tile 64x32, m16n8k16.
// SMEM: row-major half, stride 72 (conflict-free u32 fragment reads).
#define GEMM_SMEM_BYTES (2 * 128 * 72 * 2)

__global__ void __launch_bounds__(256, 2) hgemm(const __half* __restrict__ A,
                                                const __half* __restrict__ B,
                                                float* __restrict__ C,
                                                int M, int N, int K) {
    extern __shared__ __half sh[];
    __half* As = sh;               // [128][72]
    __half* Bs = sh + 128 * 72;    // [128][72]

    const int tid  = threadIdx.x;
    const int lane = tid & 31;
    const int wid  = tid >> 5;
    const int wm   = wid >> 2;          // 0..1
    const int wn   = wid & 3;           // 0..3
    const int g    = lane >> 2;
    const int t    = lane & 3;
    const int row0 = blockIdx.y * 128;
    const int col0 = blockIdx.x * 128;

    float c[4][4][4];
#pragma unroll
    for (int i = 0; i < 4; i++)
#pragma unroll
        for (int n = 0; n < 4; n++)
#pragma unroll
            for (int r = 0; r < 4; r++) c[i][n][r] = 0.f;

    for (int kb = 0; kb < K; kb += 64) {
        // ---- stage A and B (uint4 = 8 halves) ----
#pragma unroll
        for (int j = 0; j < 4; j++) {
            const int idx = tid + j * 256;          // 0..1023
            const int r = idx >> 3, c8 = (idx & 7) * 8;
            *(uint4*)&As[r * 72 + c8] =
                *(const uint4*)&A[(size_t)(row0 + r) * K + kb + c8];
            *(uint4*)&Bs[r * 72 + c8] =
                *(const uint4*)&B[(size_t)(col0 + r) * K + kb + c8];
        }
        __syncthreads();

        // ---- 4 k16-steps ----
#pragma unroll
        for (int kt = 0; kt < 4; kt++) {
            uint4 af[4];
#pragma unroll
            for (int mt = 0; mt < 4; mt++) {
                const int row = wm * 64 + mt * 16;
                af[mt].x = *(const u32*)&As[(row + g)     * 72 + kt * 16 + 2 * t];
                af[mt].y = *(const u32*)&As[(row + g + 8) * 72 + kt * 16 + 2 * t];
                af[mt].z = *(const u32*)&As[(row + g)     * 72 + kt * 16 + 2 * t + 8];
                af[mt].w = *(const u32*)&As[(row + g + 8) * 72 + kt * 16 + 2 * t + 8];
            }
            u32 bf[4][2];
#pragma unroll
            for (int nt = 0; nt < 4; nt++) {
                const int n = wn * 32 + nt * 8;
                bf[nt][0] = *(const u32*)&Bs[(n + g) * 72 + kt * 16 + 2 * t];
                bf[nt][1] = *(const u32*)&Bs[(n + g) * 72 + kt * 16 + 2 * t + 8];
            }
#pragma unroll
            for (int mt = 0; mt < 4; mt++)
#pragma unroll
                for (int nt = 0; nt < 4; nt++)
                    mma_f16(c[mt][nt], af[mt], bf[nt][0], bf[nt][1]);
        }
        __syncthreads();
    }

    // ---- epilogue (same mapping as verified tf32 kernel) ----
#pragma unroll
    for (int mt = 0; mt < 4; mt++) {
        const int row = row0 + wm * 64 + mt * 16 + g;
#pragma unroll
        for (int nt = 0; nt < 4; nt++) {
            const int col = col0 + wn * 32 + nt * 8 + 2 * t;
            *(float2*)&C[(size_t)row * N + col] =
                make_float2(c[mt][nt][0], c[mt][nt][1]);
            *(float2*)&C[(size_t)(row + 8) * N + col] =
                make_float2(c[mt][nt][2], c[mt][nt][3]);
        }
    }
}

// ---------------- RoPE table precompute (once, tiny) ------------------------
__global__ void __launch_bounds__(64) rope_table_kernel(const int* __restrict__ pos_ids) {
    const int s = blockIdx.x;
    const int i = threadIdx.x;
    const float freq  = powf(10000.0f, -(float)i / 64.0f);
    const float ang_f = (float)pos_ids[s] * freq;
    const double ang  = (double)ang_f;
    g_rcos[s * 64 + i] = (float)cos(ang);
    g_rsin[s * 64 + i] = (float)sin(ang);
}

// ---------------- RMSNorm + RoPE (+ V pass-through), warp-per-unit ---------
// grid SEQ, 256 threads. Warp w handles units {w, w+8, w+16}.
// unit<16: Q head (writes half); 16..19: K head (fp32 to d_out); 20..23: V copy.
__global__ void __launch_bounds__(256) norm_rope_kernel(
    const float* __restrict__ qproj, const float* __restrict__ kproj,
    const float* __restrict__ vproj,
    const float* __restrict__ qw, const float* __restrict__ kw,
    __half* __restrict__ qout,  // [NHEADS][SEQ][HDIM] half
    float*  __restrict__ kout,  // [NKV][SEQ][HDIM]  (d_out)
    float*  __restrict__ vout)  // [NKV][SEQ][HDIM]  (d_out)
{
    const int s = blockIdx.x;
    const int w = threadIdx.x >> 5;
    const int l = threadIdx.x & 31;
    const int c = l * 4;

#pragma unroll
    for (int uu = 0; uu < 3; uu++) {
        const int unit = w + uu * 8;
        if (unit >= 20) {                        // V copy
            const int kv = unit - 20;
            *(float4*)&vout[((size_t)kv * SEQ + s) * HDIM + c] =
                *(const float4*)&vproj[(size_t)s * (NKV * HDIM) + kv * HDIM + c];
            continue;
        }
        float4 v; const float* wptr;
        if (unit < 16) {
            v = *(const float4*)&qproj[(size_t)s * EMB + unit * HDIM + c];
            wptr = qw;
        } else {
            v = *(const float4*)&kproj[(size_t)s * (NKV * HDIM) + (unit - 16) * HDIM + c];
            wptr = kw;
        }
        float sq = v.x * v.x + v.y * v.y + v.z * v.z + v.w * v.w;
#pragma unroll
        for (int off = 16; off > 0; off >>= 1)
            sq += __shfl_xor_sync(0xffffffffu, sq, off);
        const float inv = rsqrtf(sq * (1.0f / HDIM) + 1e-6f);
        const float4 wv = *(const float4*)&wptr[c];
        float xn[4] = {wv.x * v.x * inv, wv.y * v.y * inv,
                       wv.z * v.z * inv, wv.w * v.w * inv};
        float pr[4];
#pragma unroll
        for (int i = 0; i < 4; i++)
            pr[i] = __shfl_xor_sync(0xffffffffu, xn[i], 16);
        const float4 cs = *(const float4*)&g_rcos[s * 64 + (c & 63)];
        const float4 sn = *(const float4*)&g_rsin[s * 64 + (c & 63)];
        const float cc[4] = {cs.x, cs.y, cs.z, cs.w};
        const float ss[4] = {sn.x, sn.y, sn.z, sn.w};
        float o[4];
#pragma unroll
        for (int i = 0; i < 4; i++)
            o[i] = (l < 16) ? (xn[i] * cc[i] - pr[i] * ss[i])
                            : (xn[i] * cc[i] + pr[i] * ss[i]);
        if (unit < 16) {
            *(uint2*)&qout[((size_t)unit * SEQ + s) * HDIM + c] =
                make_uint2(f2h2(o[0], o[1]), f2h2(o[2], o[3]));
        } else {
            *(float4*)&kout[((size_t)(unit - 16) * SEQ + s) * HDIM + c] =
                make_float4(o[0], o[1], o[2], o[3]);
        }
    }
}

// ---------------- Flash attention (fp16 mma.sync, causal) ------------------
// BM=128, BN=64. 8 warps; warp w owns query rows [w*16, w*16+16).
// Qs[128][136]h, Ks[64][136]h, Vt[128][72]h, Ps[128][72]h (doubles as V stg [64][136]).
#define FQ_LD 136
#define FK_LD 136
#define FV_LD 72
#define FP_LD 72
#define FLASH_SMEM_HALVES (128*FQ_LD + 64*FK_LD + 128*FV_LD + 128*FP_LD)
#define FLASH_SMEM_BYTES  (FLASH_SMEM_HALVES * 2)

__global__ void __launch_bounds__(256, 1) flash_f16(
    const __half* __restrict__ Q,   // [NHEADS][SEQ][HDIM] half
    const float*  __restrict__ Kd,  // [NKV][SEQ][HDIM] fp32
    const float*  __restrict__ Vd,  // [NKV][SEQ][HDIM] fp32
    __half* __restrict__ ctx)       // [SEQ][NHEADS*HDIM] half
{
    extern __shared__ __half smh[];
    __half* Qs = smh;                    // [128][136]
    __half* Ks = Qs + 128 * FQ_LD;       // [64][136]
    __half* Vt = Ks + 64 * FK_LD;        // [128][72]
    __half* Ps = Vt + 128 * FV_LD;       // [128][72] / V staging [64][136]

    const int tid  = threadIdx.x;
    const int lane = tid & 31;
    const int w    = tid >> 5;
    const int g    = lane >> 2;
    const int t    = lane & 3;
    const int qt   = (gridDim.x - 1) - blockIdx.x;   // big tiles first
    const int head = blockIdx.y;
    const int kv   = head / GROUP;
    const int q0   = qt * 128;
    const int rw   = w * 16;

    // ---- stage Q tile (half copy) ----
    {
        const uint4* src = (const uint4*)(Q + ((size_t)head * SEQ + q0) * HDIM);
#pragma unroll
        for (int j = 0; j < 8; j++) {
            const int i = tid + j * 256;             // 0..2047
            const int r = i >> 4, c8 = (i & 15) * 8;
            *(uint4*)&Qs[r * FQ_LD + c8] = src[r * 16 + (i & 15)];
        }
    }
    __syncthreads();

    // ---- persistent Q fragments: 8 k16-steps ----
    uint4 af[8];
#pragma unroll
    for (int kt = 0; kt < 8; kt++) {
        af[kt].x = *(const u32*)&Qs[(rw + g)     * FQ_LD + kt * 16 + 2 * t];
        af[kt].y = *(const u32*)&Qs[(rw + g + 8) * FQ_LD + kt * 16 + 2 * t];
        af[kt].z = *(const u32*)&Qs[(rw + g)     * FQ_LD + kt * 16 + 2 * t + 8];
        af[kt].w = *(const u32*)&Qs[(rw + g + 8) * FQ_LD + kt * 16 + 2 * t + 8];
    }

    float o[16][4];
#pragma unroll
    for (int n = 0; n < 16; n++)
#pragma unroll
        for (int r = 0; r < 4; r++) o[n][r] = 0.f;
    float mA = -INFINITY, mB = -INFINITY, lA = 0.f, lB = 0.f;

    const float scale = 0.08838834764831845f;
    const int rowA = q0 + rw + g;
    const int rowB = rowA + 8;
    const int njt  = 2 * qt + 2;

    for (int jt = 0; jt < njt; jt++) {
        const int k0 = jt * 64;

        // ---- stage K (half) and V (half, raw into Ps staging) ----
        {
            const float4* ksrc = (const float4*)(Kd + ((size_t)kv * SEQ + k0) * HDIM);
            const float4* vsrc = (const float4*)(Vd + ((size_t)kv * SEQ + k0) * HDIM);
#pragma unroll
            for (int j = 0; j < 8; j++) {
                const int i = tid + j * 256;         // 0..2047
                const int r = i >> 5, c = (i & 31) * 4;
                float4 a = ksrc[i];
                *(uint2*)&Ks[r * FK_LD + c] = make_uint2(f2h2(a.x, a.y), f2h2(a.z, a.w));
                float4 b = vsrc[i];
                *(uint2*)&Ps[r * 136 + c]   = make_uint2(f2h2(b.x, b.y), f2h2(b.z, b.w));
            }
        }
        __syncthreads();

        // ---- transpose V staging -> Vt[dim][key] ----
#pragma unroll
        for (int j = 0; j < 4; j++) {
            const int i = tid + j * 256;             // 0..1023
            const int key2 = i & 31, d4 = i >> 5;    // 0..31 each
            uint2 a = *(const uint2*)&Ps[(2 * key2)     * 136 + 4 * d4];
            uint2 b = *(const uint2*)&Ps[(2 * key2 + 1) * 136 + 4 * d4];
            const u32 a0 = a.x & 0xffff, a1 = a.x >> 16, a2 = a.y & 0xffff, a3 = a.y >> 16;
            const u32 b0 = b.x & 0xffff, b1 = b.x >> 16, b2 = b.y & 0xffff, b3 = b.y >> 16;
            *(u32*)&Vt[(4 * d4 + 0) * FV_LD + 2 * key2] = a0 | (b0 << 16);
            *(u32*)&Vt[(4 * d4 + 1) * FV_LD + 2 * key2] = a1 | (b1 << 16);
            *(u32*)&Vt[(4 * d4 + 2) * FV_LD + 2 * key2] = a2 | (b2 << 16);
            *(u32*)&Vt[(4 * d4 + 3) * FV_LD + 2 * key2] = a3 | (b3 << 16);
        }
        __syncthreads();

        // ---- S = Q @ K^T : 8 k16-steps x 8 n-tiles ----
        float s[8][4];
#pragma unroll
        for (int n = 0; n < 8; n++)
#pragma unroll
            for (int r = 0; r < 4; r++) s[n][r] = 0.f;
#pragma unroll
        for (int kt = 0; kt < 8; kt++) {
#pragma unroll
            for (int nt = 0; nt < 8; nt++) {
                const u32 b0 = *(const u32*)&Ks[(nt * 8 + g) * FK_LD + kt * 16 + 2 * t];
                const u32 b1 = *(const u32*)&Ks[(nt * 8 + g) * FK_LD + kt * 16 + 2 * t + 8];
                mma_f16(s[nt], af[kt], b0, b1);
            }
        }

        // ---- scale + causal mask ----
        const bool dodiag = (jt >= 2 * qt);
#pragma unroll
        for (int nt = 0; nt < 8; nt++) {
            const int c0 = k0 + nt * 8 + 2 * t;
            const int c1 = c0 + 1;
            s[nt][0] *= scale; s[nt][1] *= scale;
            s[nt][2] *= scale; s[nt][3] *= scale;
            if (dodiag) {
                if (c0 > rowA) s[nt][0] = -1e30f;
                if (c1 > rowA) s[nt][1] = -1e30f;
                if (c0 > rowB) s[nt][2] = -1e30f;
                if (c1 > rowB) s[nt][3] = -1e30f;
            }
        }

        // ---- online softmax ----
        float mxA = -1e30f, mxB = -1e30f;
#pragma unroll
        for (int nt = 0; nt < 8; nt++) {
            mxA = fmaxf(mxA, fmaxf(s[nt][0], s[nt][1]));
            mxB = fmaxf(mxB, fmaxf(s[nt][2], s[nt][3]));
        }
        mxA = fmaxf(mxA, __shfl_xor_sync(0xffffffffu, mxA, 1));
        mxA = fmaxf(mxA, __shfl_xor_sync(0xffffffffu, mxA, 2));
        mxB = fmaxf(mxB, __shfl_xor_sync(0xffffffffu, mxB, 1));
        mxB = fmaxf(mxB, __shfl_xor_sync(0xffffffffu, mxB, 2));

        const float mnA = fmaxf(mA, mxA);
        const float mnB = fmaxf(mB, mxB);
        const float cA  = __expf(mA - mnA);
        const float cB  = __expf(mB - mnB);

        float sA = 0.f, sB = 0.f;
#pragma unroll
        for (int nt = 0; nt < 8; nt++) {
            const float p0 = __expf(s[nt][0] - mnA);
            const float p1 = __expf(s[nt][1] - mnA);
            const float p2 = __expf(s[nt][2] - mnB);
            const float p3 = __expf(s[nt][3] - mnB);
            sA += p0 + p1;  sB += p2 + p3;
            const int cc = nt * 8 + 2 * t;
            *(u32*)&Ps[(rw + g)     * FP_LD + cc] = f2h2(p0, p1);
            *(u32*)&Ps[(rw + g + 8) * FP_LD + cc] = f2h2(p2, p3);
        }
        sA += __shfl_xor_sync(0xffffffffu, sA, 1);
        sA += __shfl_xor_sync(0xffffffffu, sA, 2);
        sB += __shfl_xor_sync(0xffffffffu, sB, 1);
        sB += __shfl_xor_sync(0xffffffffu, sB, 2);

        lA = lA * cA + sA;  lB = lB * cB + sB;
        mA = mnA;           mB = mnB;
#pragma unroll
        for (int nt = 0; nt < 16; nt++) {
            o[nt][0] *= cA;  o[nt][1] *= cA;
            o[nt][2] *= cB;  o[nt][3] *= cB;
        }
        __syncwarp();   // P rows warp-private: order STS -> LDS

        // ---- O += P @ V : 4 k16-steps x 16 n-tiles ----
#pragma unroll
        for (int kt = 0; kt < 4; kt++) {
            uint4 pf;
            pf.x = *(const u32*)&Ps[(rw + g)     * FP_LD + kt * 16 + 2 * t];
            pf.y = *(const u32*)&Ps[(rw + g + 8) * FP_LD + kt * 16 + 2 * t];
            pf.z = *(const u32*)&Ps[(rw + g)     * FP_LD + kt * 16 + 2 * t + 8];
            pf.w = *(const u32*)&Ps[(rw + g + 8) * FP_LD + kt * 16 + 2 * t + 8];
#pragma unroll
            for (int nt = 0; nt < 16; nt++) {
                const u32 b0 = *(const u32*)&Vt[(nt * 8 + g) * FV_LD + kt * 16 + 2 * t];
                const u32 b1 = *(const u32*)&Vt[(nt * 8 + g) * FV_LD + kt * 16 + 2 * t + 8];
                mma_f16(o[nt], pf, b0, b1);
            }
        }
        __syncthreads();   // protect Ks/Ps/Vt for next iteration
    }

    // ---- epilogue: normalize, write half ctx ----
    const float iA = 1.0f / lA;
    const float iB = 1.0f / lB;
#pragma unroll
    for (int nt = 0; nt < 16; nt++) {
        const int col = head * HDIM + nt * 8 + 2 * t;
        *(u32*)&ctx[(size_t)rowA * EMB + col] = f2h2(o[nt][0] * iA, o[nt][1] * iA);
        *(u32*)&ctx[(size_t)rowB * EMB + col] = f2h2(o[nt][2] * iB, o[nt][3] * iB);
    }
}

// ---------------- launch ----------------------------------------------------
extern "C" void kernel_launch(void* const* d_in, const int* in_sizes, int n_in,
                              void* d_out, int out_size) {
    const float* x   = (const float*)d_in[0];
    const int*   pos = (const int*)  d_in[1];
    // d_in[2] = attn_mask (pure causal triu(-1e9)) -- implemented analytically
    const float* Wq  = (const float*)d_in[3];
    const float* Wk  = (const float*)d_in[4];
    const float* Wv  = (const float*)d_in[5];
    const float* Wo  = (const float*)d_in[6];
    const float* qw  = (const float*)d_in[7];
    const float* kw  = (const float*)d_in[8];

    float* out  = (float*)d_out;                       // [4096, 2048]
    float* kout = out  + (size_t)SEQ * EMB;            // [4, 4096, 128]
    float* vout = kout + (size_t)NKV * SEQ * HDIM;     // [4, 4096, 128]

    float *qproj, *kproj, *vproj, *rc;
    __half *xh, *qh, *ctxh, *wqt, *wkt, *wvt, *wot;
    cudaGetSymbolAddress((void**)&qproj, g_qproj);
    cudaGetSymbolAddress((void**)&kproj, g_kproj);
    cudaGetSymbolAddress((void**)&vproj, g_vproj);
    cudaGetSymbolAddress((void**)&xh,    g_xh);
    cudaGetSymbolAddress((void**)&qh,    g_qh);
    cudaGetSymbolAddress((void**)&ctxh,  g_ctxh);
    cudaGetSymbolAddress((void**)&wqt,   g_wqt);
    cudaGetSymbolAddress((void**)&wkt,   g_wkt);
    cudaGetSymbolAddress((void**)&wvt,   g_wvt);
    cudaGetSymbolAddress((void**)&wot,   g_wot);
    (void)rc;

    cudaFuncSetAttribute(hgemm,
                         cudaFuncAttributeMaxDynamicSharedMemorySize, GEMM_SMEM_BYTES);
    cudaFuncSetAttribute(flash_f16,
                         cudaFuncAttributeMaxDynamicSharedMemorySize, FLASH_SMEM_BYTES);

    // 0) one-time conversions
    f32_to_f16<<<(SEQ * EMB / 4) / 256, 256>>>(x, xh);
    transpose_half<<<dim3(EMB / 32, EMB / 32), 256>>>(Wq, wqt, EMB, EMB);
    transpose_half<<<dim3((NKV * HDIM) / 32, EMB / 32), 256>>>(Wk, wkt, EMB, NKV * HDIM);
    transpose_half<<<dim3((NKV * HDIM) / 32, EMB / 32), 256>>>(Wv, wvt, EMB, NKV * HDIM);
    transpose_half<<<dim3(EMB / 32, EMB / 32), 256>>>(Wo, wot, EMB, EMB);
    rope_table_kernel<<<SEQ, 64>>>(pos);

    // 1) projections (fp16 mma)
    hgemm<<<dim3(EMB / 128, SEQ / 128), 256, GEMM_SMEM_BYTES>>>(xh, wqt, qproj, SEQ, EMB, EMB);
    hgemm<<<dim3((NKV * HDIM) / 128, SEQ / 128), 256, GEMM_SMEM_BYTES>>>(xh, wkt, kproj, SEQ, NKV * HDIM, EMB);
    hgemm<<<dim3((NKV * HDIM) / 128, SEQ / 128), 256, GEMM_SMEM_BYTES>>>(xh, wvt, vproj, SEQ, NKV * HDIM, EMB);

    // 2) rmsnorm + rope (+ V transpose into d_out)
    norm_rope_kernel<<<SEQ, 256>>>(qproj, kproj, vproj, qw, kw, qh, kout, vout);

    // 3) causal flash attention (fp16 mma)
    flash_f16<<<dim3(SEQ / 128, NHEADS), 256, FLASH_SMEM_BYTES>>>(qh, kout, vout, ctxh);

    // 4) output projection (fp16 mma)
    hgemm<<<dim3(EMB / 128, SEQ / 128), 256, GEMM_SMEM_BYTES>>>(ctxh, wot, out, SEQ, EMB, EMB);
}

// round 7
// speedup vs baseline: 7.6128x; 1.1116x over previous
#include <cuda_runtime.h>
#include <cuda_fp16.h>
#include <math.h>
#include <stdint.h>

// Problem constants
#define SEQ      4096
#define EMB      2048
#define NHEADS   16
#define NKV      4
#define HDIM     128
#define GROUP    (NHEADS / NKV)
#define QKV_N    3072            // 2048 Q + 512 K + 512 V

typedef unsigned long long u64;
typedef unsigned int u32;

// ---------------- scratch (device globals; no allocation allowed) ----------
__device__ float  g_qkv [SEQ * QKV_N];            // fused projection output
__device__ __half g_xh  [SEQ * EMB];              // x in half
__device__ __half g_qh  [NHEADS * SEQ * HDIM];    // Q after norm+rope, half
__device__ __half g_kh  [NKV * SEQ * HDIM];       // K after norm+rope, half
__device__ __half g_vh  [NKV * SEQ * HDIM];       // V, half
__device__ __half g_ctxh[SEQ * NHEADS * HDIM];    // attention output, half
__device__ float  g_rcos[SEQ * 64];
__device__ float  g_rsin[SEQ * 64];
// transposed half weights
__device__ __half g_wqkvt[QKV_N * EMB];           // [3072][2048]
__device__ __half g_wot  [EMB * EMB];

// ---------------- helpers ----------------------------------------------------
__device__ __forceinline__ u32 f2h2(float lo, float hi) {
    __half2 h = __floats2half2_rn(lo, hi);
    return *reinterpret_cast<u32*>(&h);
}
__device__ __forceinline__ void mma_f16(float c[4], uint4 a, u32 b0, u32 b1) {
    asm("mma.sync.aligned.m16n8k16.row.col.f32.f16.f16.f32 "
        "{%0,%1,%2,%3},{%4,%5,%6,%7},{%8,%9},{%0,%1,%2,%3};"
        : "+f"(c[0]), "+f"(c[1]), "+f"(c[2]), "+f"(c[3])
        : "r"(a.x), "r"(a.y), "r"(a.z), "r"(a.w), "r"(b0), "r"(b1));
}
__device__ __forceinline__ u32 smem_u32(const void* p) {
    u32 a;
    asm("{ .reg .u64 t; cvta.to.shared.u64 t, %1; cvt.u32.u64 %0, t; }"
        : "=r"(a) : "l"(p));
    return a;
}
__device__ __forceinline__ void cp16(u32 saddr, const void* gptr) {
    asm volatile("cp.async.cg.shared.global [%0], [%1], 16;"
                 :: "r"(saddr), "l"(gptr) : "memory");
}
#define CP_COMMIT() asm volatile("cp.async.commit_group;" ::: "memory")
#define CP_WAIT(n)  asm volatile("cp.async.wait_group %0;" :: "n"(n) : "memory")

// ---------------- fp32 -> fp16 bulk convert ---------------------------------
__global__ void __launch_bounds__(256) f32_to_f16(const float* __restrict__ in,
                                                  __half* __restrict__ out) {
    const int i = blockIdx.x * 256 + threadIdx.x;
    float4 v = ((const float4*)in)[i];
    ((uint2*)out)[i] = make_uint2(f2h2(v.x, v.y), f2h2(v.z, v.w));
}

// ---------------- weight transpose + half convert: out[n][k]=h(in[k][n]) ----
__global__ void __launch_bounds__(256) transpose_half(
    const float* __restrict__ in, __half* __restrict__ out, int K, int N) {
    __shared__ __half t[32][33];
    const int n0 = blockIdx.x * 32, k0 = blockIdx.y * 32;
    const int x = threadIdx.x & 31, y = threadIdx.x >> 5;
#pragma unroll
    for (int j = 0; j < 4; j++) {
        const int k = y + j * 8;
        t[k][x] = __float2half_rn(in[(size_t)(k0 + k) * N + n0 + x]);
    }
    __syncthreads();
#pragma unroll
    for (int j = 0; j < 4; j++) {
        const int n = y + j * 8;
        out[(size_t)(n0 + n) * K + k0 + x] = t[x][n];
    }
}

// ---------------- fp16 MMA GEMM, cp.async double-buffered -------------------
// C[M,N] = Ah[M,K] @ Bh[N,K]^T. BM=BN=128, BK=64, 8 warps (2x4), m16n8k16.
// 2 stages x (A[128][72] + B[128][72]) halves = 73728 B.
#define GSTG_H   (128 * 72)                 // halves per operand per stage
#define GEMM_SMEM_BYTES (4 * GSTG_H * 2)

__global__ void __launch_bounds__(256, 2) hgemm(const __half* __restrict__ A,
                                                const __half* __restrict__ B,
                                                float* __restrict__ C,
                                                int M, int N, int K) {
    extern __shared__ __half sh[];
    const u32 shb = smem_u32(sh);

    const int tid  = threadIdx.x;
    const int lane = tid & 31;
    const int wid  = tid >> 5;
    const int wm   = wid >> 2;          // 0..1
    const int wn   = wid & 3;           // 0..3
    const int g    = lane >> 2;
    const int t    = lane & 3;
    const int row0 = blockIdx.y * 128;
    const int col0 = blockIdx.x * 128;

    const int l_r  = tid >> 3;          // 0..31 (x4 rows via j)
    const int l_c8 = (tid & 7) * 8;

    float c[4][4][4];
#pragma unroll
    for (int i = 0; i < 4; i++)
#pragma unroll
        for (int n = 0; n < 4; n++)
#pragma unroll
            for (int r = 0; r < 4; r++) c[i][n][r] = 0.f;

    const int NS = K >> 6;

    // issue stage s loads (A+B) into buffer s&1
    auto issue = [&](int s) {
        const int kb   = s << 6;
        const u32 base = shb + (u32)(s & 1) * (2 * GSTG_H * 2);
        const u32 ab   = base;
        const u32 bb   = base + GSTG_H * 2;
#pragma unroll
        for (int j = 0; j < 4; j++) {
            const int r = l_r + j * 32;
            cp16(ab + (u32)(r * 72 + l_c8) * 2,
                 &A[(size_t)(row0 + r) * K + kb + l_c8]);
            cp16(bb + (u32)(r * 72 + l_c8) * 2,
                 &B[(size_t)(col0 + r) * K + kb + l_c8]);
        }
        CP_COMMIT();
    };

    issue(0);
    for (int s = 0; s < NS; s++) {
        if (s + 1 < NS) issue(s + 1);
        if (s + 1 < NS) { CP_WAIT(1); } else { CP_WAIT(0); }
        __syncthreads();

        const __half* As = sh + (s & 1) * (2 * GSTG_H);
        const __half* Bs = As + GSTG_H;

#pragma unroll
        for (int kt = 0; kt < 4; kt++) {
            uint4 af[4];
#pragma unroll
            for (int mt = 0; mt < 4; mt++) {
                const int row = wm * 64 + mt * 16;
                af[mt].x = *(const u32*)&As[(row + g)     * 72 + kt * 16 + 2 * t];
                af[mt].y = *(const u32*)&As[(row + g + 8) * 72 + kt * 16 + 2 * t];
                af[mt].z = *(const u32*)&As[(row + g)     * 72 + kt * 16 + 2 * t + 8];
                af[mt].w = *(const u32*)&As[(row + g + 8) * 72 + kt * 16 + 2 * t + 8];
            }
            u32 bf[4][2];
#pragma unroll
            for (int nt = 0; nt < 4; nt++) {
                const int n = wn * 32 + nt * 8;
                bf[nt][0] = *(const u32*)&Bs[(n + g) * 72 + kt * 16 + 2 * t];
                bf[nt][1] = *(const u32*)&Bs[(n + g) * 72 + kt * 16 + 2 * t + 8];
            }
#pragma unroll
            for (int mt = 0; mt < 4; mt++)
#pragma unroll
                for (int nt = 0; nt < 4; nt++)
                    mma_f16(c[mt][nt], af[mt], bf[nt][0], bf[nt][1]);
        }
        __syncthreads();
    }

#pragma unroll
    for (int mt = 0; mt < 4; mt++) {
        const int row = row0 + wm * 64 + mt * 16 + g;
#pragma unroll
        for (int nt = 0; nt < 4; nt++) {
            const int col = col0 + wn * 32 + nt * 8 + 2 * t;
            *(float2*)&C[(size_t)row * N + col] =
                make_float2(c[mt][nt][0], c[mt][nt][1]);
            *(float2*)&C[(size_t)(row + 8) * N + col] =
                make_float2(c[mt][nt][2], c[mt][nt][3]);
        }
    }
}

// ---------------- RoPE table precompute -------------------------------------
__global__ void __launch_bounds__(64) rope_table_kernel(const int* __restrict__ pos_ids) {
    const int s = blockIdx.x;
    const int i = threadIdx.x;
    const float freq  = powf(10000.0f, -(float)i / 64.0f);
    const float ang_f = (float)pos_ids[s] * freq;
    const double ang  = (double)ang_f;
    g_rcos[s * 64 + i] = (float)cos(ang);
    g_rsin[s * 64 + i] = (float)sin(ang);
}

// ---------------- RMSNorm + RoPE from fused qkv ------------------------------
// grid SEQ, 256 thr. Warp w: units {w, w+8, w+16}.
// unit<16: Q head -> half; 16..19: K -> fp32 d_out + half cache; 20..23: V copy both.
__global__ void __launch_bounds__(256) norm_rope_kernel(
    const float* __restrict__ qkv,           // [SEQ][3072]
    const float* __restrict__ qw, const float* __restrict__ kw,
    __half* __restrict__ qout,               // [NHEADS][SEQ][HDIM]
    float*  __restrict__ kout,  float* __restrict__ vout,   // d_out fp32
    __half* __restrict__ khalf, __half* __restrict__ vhalf) // flash caches
{
    const int s = blockIdx.x;
    const int w = threadIdx.x >> 5;
    const int l = threadIdx.x & 31;
    const int c = l * 4;
    const float* row = qkv + (size_t)s * QKV_N;

#pragma unroll
    for (int uu = 0; uu < 3; uu++) {
        const int unit = w + uu * 8;
        if (unit >= 20) {                        // V copy (fp32 + half)
            const int kv = unit - 20;
            const float4 v = *(const float4*)&row[2560 + kv * HDIM + c];
            *(float4*)&vout[((size_t)kv * SEQ + s) * HDIM + c] = v;
            *(uint2*)&vhalf[((size_t)kv * SEQ + s) * HDIM + c] =
                make_uint2(f2h2(v.x, v.y), f2h2(v.z, v.w));
            continue;
        }
        float4 v; const float* wptr;
        if (unit < 16) { v = *(const float4*)&row[unit * HDIM + c];              wptr = qw; }
        else           { v = *(const float4*)&row[2048 + (unit - 16) * HDIM + c]; wptr = kw; }

        float sq = v.x * v.x + v.y * v.y + v.z * v.z + v.w * v.w;
#pragma unroll
        for (int off = 16; off > 0; off >>= 1)
            sq += __shfl_xor_sync(0xffffffffu, sq, off);
        const float inv = rsqrtf(sq * (1.0f / HDIM) + 1e-6f);
        const float4 wv = *(const float4*)&wptr[c];
        float xn[4] = {wv.x * v.x * inv, wv.y * v.y * inv,
                       wv.z * v.z * inv, wv.w * v.w * inv};
        float pr[4];
#pragma unroll
        for (int i = 0; i < 4; i++)
            pr[i] = __shfl_xor_sync(0xffffffffu, xn[i], 16);
        const float4 cs = *(const float4*)&g_rcos[s * 64 + (c & 63)];
        const float4 sn = *(const float4*)&g_rsin[s * 64 + (c & 63)];
        const float cc[4] = {cs.x, cs.y, cs.z, cs.w};
        const float ss[4] = {sn.x, sn.y, sn.z, sn.w};
        float o[4];
#pragma unroll
        for (int i = 0; i < 4; i++)
            o[i] = (l < 16) ? (xn[i] * cc[i] - pr[i] * ss[i])
                            : (xn[i] * cc[i] + pr[i] * ss[i]);
        if (unit < 16) {
            *(uint2*)&qout[((size_t)unit * SEQ + s) * HDIM + c] =
                make_uint2(f2h2(o[0], o[1]), f2h2(o[2], o[3]));
        } else {
            const int kvh = unit - 16;
            *(float4*)&kout[((size_t)kvh * SEQ + s) * HDIM + c] =
                make_float4(o[0], o[1], o[2], o[3]);
            *(uint2*)&khalf[((size_t)kvh * SEQ + s) * HDIM + c] =
                make_uint2(f2h2(o[0], o[1]), f2h2(o[2], o[3]));
        }
    }
}

// ---------------- Flash attention (fp16 mma.sync, causal, half K/V) --------
#define FQ_LD 136
#define FK_LD 136
#define FV_LD 72
#define FP_LD 72
#define FLASH_SMEM_HALVES (128*FQ_LD + 64*FK_LD + 128*FV_LD + 128*FP_LD)
#define FLASH_SMEM_BYTES  (FLASH_SMEM_HALVES * 2)

__global__ void __launch_bounds__(256, 1) flash_f16(
    const __half* __restrict__ Q,   // [NHEADS][SEQ][HDIM]
    const __half* __restrict__ Kh,  // [NKV][SEQ][HDIM]
    const __half* __restrict__ Vh,  // [NKV][SEQ][HDIM]
    __half* __restrict__ ctx)       // [SEQ][NHEADS*HDIM]
{
    extern __shared__ __half smh[];
    __half* Qs = smh;                    // [128][136]
    __half* Ks = Qs + 128 * FQ_LD;       // [64][136]
    __half* Vt = Ks + 64 * FK_LD;        // [128][72]
    __half* Ps = Vt + 128 * FV_LD;       // [128][72] / V staging [64][136]

    const int tid  = threadIdx.x;
    const int lane = tid & 31;
    const int w    = tid >> 5;
    const int g    = lane >> 2;
    const int t    = lane & 3;
    const int qt   = (gridDim.x - 1) - blockIdx.x;   // big tiles first
    const int head = blockIdx.y;
    const int kv   = head / GROUP;
    const int q0   = qt * 128;
    const int rw   = w * 16;

    {
        const uint4* src = (const uint4*)(Q + ((size_t)head * SEQ + q0) * HDIM);
#pragma unroll
        for (int j = 0; j < 8; j++) {
            const int i = tid + j * 256;
            const int r = i >> 4, c8 = (i & 15) * 8;
            *(uint4*)&Qs[r * FQ_LD + c8] = src[r * 16 + (i & 15)];
        }
    }
    __syncthreads();

    uint4 af[8];
#pragma unroll
    for (int kt = 0; kt < 8; kt++) {
        af[kt].x = *(const u32*)&Qs[(rw + g)     * FQ_LD + kt * 16 + 2 * t];
        af[kt].y = *(const u32*)&Qs[(rw + g + 8) * FQ_LD + kt * 16 + 2 * t];
        af[kt].z = *(const u32*)&Qs[(rw + g)     * FQ_LD + kt * 16 + 2 * t + 8];
        af[kt].w = *(const u32*)&Qs[(rw + g + 8) * FQ_LD + kt * 16 + 2 * t + 8];
    }

    float o[16][4];
#pragma unroll
    for (int n = 0; n < 16; n++)
#pragma unroll
        for (int r = 0; r < 4; r++) o[n][r] = 0.f;
    float mA = -INFINITY, mB = -INFINITY, lA = 0.f, lB = 0.f;

    const float scale = 0.08838834764831845f;
    const int rowA = q0 + rw + g;
    const int rowB = rowA + 8;
    const int njt  = 2 * qt + 2;

    for (int jt = 0; jt < njt; jt++) {
        const int k0 = jt * 64;

        // ---- stage K and V (pure half copies) ----
        {
            const uint4* ksrc = (const uint4*)(Kh + ((size_t)kv * SEQ + k0) * HDIM);
            const uint4* vsrc = (const uint4*)(Vh + ((size_t)kv * SEQ + k0) * HDIM);
#pragma unroll
            for (int j = 0; j < 4; j++) {
                const int i = tid + j * 256;       // 0..1023
                const int r = i >> 4, c8 = (i & 15) * 8;
                *(uint4*)&Ks[r * FK_LD + c8] = ksrc[i];
                *(uint4*)&Ps[r * 136 + c8]   = vsrc[i];
            }
        }
        __syncthreads();

        // ---- transpose V staging -> Vt[dim][key] ----
#pragma unroll
        for (int j = 0; j < 4; j++) {
            const int i = tid + j * 256;
            const int key2 = i & 31, d4 = i >> 5;
            uint2 a = *(const uint2*)&Ps[(2 * key2)     * 136 + 4 * d4];
            uint2 b = *(const uint2*)&Ps[(2 * key2 + 1) * 136 + 4 * d4];
            const u32 a0 = a.x & 0xffff, a1 = a.x >> 16, a2 = a.y & 0xffff, a3 = a.y >> 16;
            const u32 b0 = b.x & 0xffff, b1 = b.x >> 16, b2 = b.y & 0xffff, b3 = b.y >> 16;
            *(u32*)&Vt[(4 * d4 + 0) * FV_LD + 2 * key2] = a0 | (b0 << 16);
            *(u32*)&Vt[(4 * d4 + 1) * FV_LD + 2 * key2] = a1 | (b1 << 16);
            *(u32*)&Vt[(4 * d4 + 2) * FV_LD + 2 * key2] = a2 | (b2 << 16);
            *(u32*)&Vt[(4 * d4 + 3) * FV_LD + 2 * key2] = a3 | (b3 << 16);
        }
        __syncthreads();

        // ---- S = Q @ K^T ----
        float s[8][4];
#pragma unroll
        for (int n = 0; n < 8; n++)
#pragma unroll
            for (int r = 0; r < 4; r++) s[n][r] = 0.f;
#pragma unroll
        for (int kt = 0; kt < 8; kt++) {
#pragma unroll
            for (int nt = 0; nt < 8; nt++) {
                const u32 b0 = *(const u32*)&Ks[(nt * 8 + g) * FK_LD + kt * 16 + 2 * t];
                const u32 b1 = *(const u32*)&Ks[(nt * 8 + g) * FK_LD + kt * 16 + 2 * t + 8];
                mma_f16(s[nt], af[kt], b0, b1);
            }
        }

        const bool dodiag = (jt >= 2 * qt);
#pragma unroll
        for (int nt = 0; nt < 8; nt++) {
            const int c0 = k0 + nt * 8 + 2 * t;
            const int c1 = c0 + 1;
            s[nt][0] *= scale; s[nt][1] *= scale;
            s[nt][2] *= scale; s[nt][3] *= scale;
            if (dodiag) {
                if (c0 > rowA) s[nt][0] = -1e30f;
                if (c1 > rowA) s[nt][1] = -1e30f;
                if (c0 > rowB) s[nt][2] = -1e30f;
                if (c1 > rowB) s[nt][3] = -1e30f;
            }
        }

        float mxA = -1e30f, mxB = -1e30f;
#pragma unroll
        for (int nt = 0; nt < 8; nt++) {
            mxA = fmaxf(mxA, fmaxf(s[nt][0], s[nt][1]));
            mxB = fmaxf(mxB, fmaxf(s[nt][2], s[nt][3]));
        }
        mxA = fmaxf(mxA, __shfl_xor_sync(0xffffffffu, mxA, 1));
        mxA = fmaxf(mxA, __shfl_xor_sync(0xffffffffu, mxA, 2));
        mxB = fmaxf(mxB, __shfl_xor_sync(0xffffffffu, mxB, 1));
        mxB = fmaxf(mxB, __shfl_xor_sync(0xffffffffu, mxB, 2));

        const float mnA = fmaxf(mA, mxA);
        const float mnB = fmaxf(mB, mxB);
        const float cA  = __expf(mA - mnA);
        const float cB  = __expf(mB - mnB);

        float sA = 0.f, sB = 0.f;
#pragma unroll
        for (int nt = 0; nt < 8; nt++) {
            const float p0 = __expf(s[nt][0] - mnA);
            const float p1 = __expf(s[nt][1] - mnA);
            const float p2 = __expf(s[nt][2] - mnB);
            const float p3 = __expf(s[nt][3] - mnB);
            sA += p0 + p1;  sB += p2 + p3;
            const int cc = nt * 8 + 2 * t;
            *(u32*)&Ps[(rw + g)     * FP_LD + cc] = f2h2(p0, p1);
            *(u32*)&Ps[(rw + g + 8) * FP_LD + cc] = f2h2(p2, p3);
        }
        sA += __shfl_xor_sync(0xffffffffu, sA, 1);
        sA += __shfl_xor_sync(0xffffffffu, sA, 2);
        sB += __shfl_xor_sync(0xffffffffu, sB, 1);
        sB += __shfl_xor_sync(0xffffffffu, sB, 2);

        lA = lA * cA + sA;  lB = lB * cB + sB;
        mA = mnA;           mB = mnB;
#pragma unroll
        for (int nt = 0; nt < 16; nt++) {
            o[nt][0] *= cA;  o[nt][1] *= cA;
            o[nt][2] *= cB;  o[nt][3] *= cB;
        }
        __syncwarp();

        // ---- O += P @ V ----
#pragma unroll
        for (int kt = 0; kt < 4; kt++) {
            uint4 pf;
            pf.x = *(const u32*)&Ps[(rw + g)     * FP_LD + kt * 16 + 2 * t];
            pf.y = *(const u32*)&Ps[(rw + g + 8) * FP_LD + kt * 16 + 2 * t];
            pf.z = *(const u32*)&Ps[(rw + g)     * FP_LD + kt * 16 + 2 * t + 8];
            pf.w = *(const u32*)&Ps[(rw + g + 8) * FP_LD + kt * 16 + 2 * t + 8];
#pragma unroll
            for (int nt = 0; nt < 16; nt++) {
                const u32 b0 = *(const u32*)&Vt[(nt * 8 + g) * FV_LD + kt * 16 + 2 * t];
                const u32 b1 = *(const u32*)&Vt[(nt * 8 + g) * FV_LD + kt * 16 + 2 * t + 8];
                mma_f16(o[nt], pf, b0, b1);
            }
        }
        __syncthreads();
    }

    const float iA = 1.0f / lA;
    const float iB = 1.0f / lB;
#pragma unroll
    for (int nt = 0; nt < 16; nt++) {
        const int col = head * HDIM + nt * 8 + 2 * t;
        *(u32*)&ctx[(size_t)rowA * EMB + col] = f2h2(o[nt][0] * iA, o[nt][1] * iA);
        *(u32*)&ctx[(size_t)rowB * EMB + col] = f2h2(o[nt][2] * iB, o[nt][3] * iB);
    }
}

// ---------------- launch ----------------------------------------------------
extern "C" void kernel_launch(void* const* d_in, const int* in_sizes, int n_in,
                              void* d_out, int out_size) {
    const float* x   = (const float*)d_in[0];
    const int*   pos = (const int*)  d_in[1];
    // d_in[2] = attn_mask (pure causal) -- analytic
    const float* Wq  = (const float*)d_in[3];
    const float* Wk  = (const float*)d_in[4];
    const float* Wv  = (const float*)d_in[5];
    const float* Wo  = (const float*)d_in[6];
    const float* qw  = (const float*)d_in[7];
    const float* kw  = (const float*)d_in[8];

    float* out  = (float*)d_out;
    float* kout = out  + (size_t)SEQ * EMB;
    float* vout = kout + (size_t)NKV * SEQ * HDIM;

    float  *qkv;
    __half *xh, *qh, *kh, *vh, *ctxh, *wqkvt, *wot;
    cudaGetSymbolAddress((void**)&qkv,   g_qkv);
    cudaGetSymbolAddress((void**)&xh,    g_xh);
    cudaGetSymbolAddress((void**)&qh,    g_qh);
    cudaGetSymbolAddress((void**)&kh,    g_kh);
    cudaGetSymbolAddress((void**)&vh,    g_vh);
    cudaGetSymbolAddress((void**)&ctxh,  g_ctxh);
    cudaGetSymbolAddress((void**)&wqkvt, g_wqkvt);
    cudaGetSymbolAddress((void**)&wot,   g_wot);

    cudaFuncSetAttribute(hgemm,
                         cudaFuncAttributeMaxDynamicSharedMemorySize, GEMM_SMEM_BYTES);
    cudaFuncSetAttribute(flash_f16,
                         cudaFuncAttributeMaxDynamicSharedMemorySize, FLASH_SMEM_BYTES);

    // 0) one-time conversions: x->half, weights -> transposed half (fused QKV)
    f32_to_f16<<<(SEQ * EMB / 4) / 256, 256>>>(x, xh);
    transpose_half<<<dim3(EMB / 32, EMB / 32), 256>>>(Wq, wqkvt, EMB, EMB);
    transpose_half<<<dim3((NKV * HDIM) / 32, EMB / 32), 256>>>(
        Wk, wqkvt + (size_t)2048 * EMB, EMB, NKV * HDIM);
    transpose_half<<<dim3((NKV * HDIM) / 32, EMB / 32), 256>>>(
        Wv, wqkvt + (size_t)2560 * EMB, EMB, NKV * HDIM);
    transpose_half<<<dim3(EMB / 32, EMB / 32), 256>>>(Wo, wot, EMB, EMB);
    rope_table_kernel<<<SEQ, 64>>>(pos);

    // 1) fused QKV projection
    hgemm<<<dim3(QKV_N / 128, SEQ / 128), 256, GEMM_SMEM_BYTES>>>(
        xh, wqkvt, qkv, SEQ, QKV_N, EMB);

    // 2) rmsnorm + rope; emits half Q plus fp32+half K/V
    norm_rope_kernel<<<SEQ, 256>>>(qkv, qw, kw, qh, kout, vout, kh, vh);

    // 3) causal flash attention
    flash_f16<<<dim3(SEQ / 128, NHEADS), 256, FLASH_SMEM_BYTES>>>(qh, kh, vh, ctxh);

    // 4) output projection
    hgemm<<<dim3(EMB / 128, SEQ / 128), 256, GEMM_SMEM_BYTES>>>(
        ctxh, wot, out, SEQ, EMB, EMB);
}

// round 8
// speedup vs baseline: 8.3888x; 1.1019x over previous
#include <cuda_runtime.h>
#include <cuda_fp16.h>
#include <math.h>
#include <stdint.h>

// Problem constants
#define SEQ      4096
#define EMB      2048
#define NHEADS   16
#define NKV      4
#define HDIM     128
#define GROUP    (NHEADS / NKV)
#define QKV_N    3072            // 2048 Q + 512 K + 512 V

typedef unsigned long long u64;
typedef unsigned int u32;

// ---------------- scratch (device globals; no allocation allowed) ----------
__device__ float  g_qkv [SEQ * QKV_N];            // fused projection output
__device__ __half g_xh  [SEQ * EMB];              // x in half
__device__ __half g_qh  [NHEADS * SEQ * HDIM];    // Q after norm+rope, half
__device__ __half g_kh  [NKV * SEQ * HDIM];       // K after norm+rope, half
__device__ __half g_vh  [NKV * SEQ * HDIM];       // V, half
__device__ __half g_ctxh[SEQ * NHEADS * HDIM];    // attention output, half
__device__ float  g_rcos[SEQ * 64];
__device__ float  g_rsin[SEQ * 64];
// transposed half weights
__device__ __half g_wqkvt[QKV_N * EMB];           // [3072][2048]
__device__ __half g_wot  [EMB * EMB];

// ---------------- helpers ----------------------------------------------------
__device__ __forceinline__ u32 f2h2(float lo, float hi) {
    __half2 h = __floats2half2_rn(lo, hi);
    return *reinterpret_cast<u32*>(&h);
}
__device__ __forceinline__ void mma_f16(float c[4], uint4 a, u32 b0, u32 b1) {
    asm("mma.sync.aligned.m16n8k16.row.col.f32.f16.f16.f32 "
        "{%0,%1,%2,%3},{%4,%5,%6,%7},{%8,%9},{%0,%1,%2,%3};"
        : "+f"(c[0]), "+f"(c[1]), "+f"(c[2]), "+f"(c[3])
        : "r"(a.x), "r"(a.y), "r"(a.z), "r"(a.w), "r"(b0), "r"(b1));
}
__device__ __forceinline__ u32 smem_u32(const void* p) {
    u32 a;
    asm("{ .reg .u64 t; cvta.to.shared.u64 t, %1; cvt.u32.u64 %0, t; }"
        : "=r"(a) : "l"(p));
    return a;
}
__device__ __forceinline__ void cp16(u32 saddr, const void* gptr) {
    asm volatile("cp.async.cg.shared.global [%0], [%1], 16;"
                 :: "r"(saddr), "l"(gptr) : "memory");
}
#define CP_COMMIT() asm volatile("cp.async.commit_group;" ::: "memory")
#define CP_WAIT(n)  asm volatile("cp.async.wait_group %0;" :: "n"(n) : "memory")

__device__ __forceinline__ void ldsm4(u32 r[4], u32 saddr) {
    asm volatile("ldmatrix.sync.aligned.m8n8.x4.shared.b16 {%0,%1,%2,%3}, [%4];"
                 : "=r"(r[0]), "=r"(r[1]), "=r"(r[2]), "=r"(r[3]) : "r"(saddr));
}
__device__ __forceinline__ void ldsm4t(u32 r[4], u32 saddr) {
    asm volatile("ldmatrix.sync.aligned.m8n8.x4.trans.shared.b16 {%0,%1,%2,%3}, [%4];"
                 : "=r"(r[0]), "=r"(r[1]), "=r"(r[2]), "=r"(r[3]) : "r"(saddr));
}

// ---------------- fp32 -> fp16 bulk convert ---------------------------------
__global__ void __launch_bounds__(256) f32_to_f16(const float* __restrict__ in,
                                                  __half* __restrict__ out) {
    const int i = blockIdx.x * 256 + threadIdx.x;
    float4 v = ((const float4*)in)[i];
    ((uint2*)out)[i] = make_uint2(f2h2(v.x, v.y), f2h2(v.z, v.w));
}

// ---------------- fused QKV weight transpose: out[n][k] = h(W[k][n]) -------
__global__ void __launch_bounds__(256) transpose_qkv(
    const float* __restrict__ Wq, const float* __restrict__ Wk,
    const float* __restrict__ Wv, __half* __restrict__ out) {
    __shared__ __half t[32][33];
    const int n0 = blockIdx.x * 32, k0 = blockIdx.y * 32;
    const int x = threadIdx.x & 31, y = threadIdx.x >> 5;
    const float* src; int N, nl;
    if      (n0 < 2048) { src = Wq; N = 2048; nl = n0; }
    else if (n0 < 2560) { src = Wk; N = 512;  nl = n0 - 2048; }
    else                { src = Wv; N = 512;  nl = n0 - 2560; }
#pragma unroll
    for (int j = 0; j < 4; j++) {
        const int k = y + j * 8;
        t[k][x] = __float2half_rn(src[(size_t)(k0 + k) * N + nl + x]);
    }
    __syncthreads();
#pragma unroll
    for (int j = 0; j < 4; j++) {
        const int n = y + j * 8;
        out[(size_t)(n0 + n) * EMB + k0 + x] = t[x][n];
    }
}

// ---------------- single weight transpose (Wo) ------------------------------
__global__ void __launch_bounds__(256) transpose_half(
    const float* __restrict__ in, __half* __restrict__ out, int K, int N) {
    __shared__ __half t[32][33];
    const int n0 = blockIdx.x * 32, k0 = blockIdx.y * 32;
    const int x = threadIdx.x & 31, y = threadIdx.x >> 5;
#pragma unroll
    for (int j = 0; j < 4; j++) {
        const int k = y + j * 8;
        t[k][x] = __float2half_rn(in[(size_t)(k0 + k) * N + n0 + x]);
    }
    __syncthreads();
#pragma unroll
    for (int j = 0; j < 4; j++) {
        const int n = y + j * 8;
        out[(size_t)(n0 + n) * K + k0 + x] = t[x][n];
    }
}

// ---------------- fp16 MMA GEMM, cp.async double-buffered -------------------
#define GSTG_H   (128 * 72)
#define GEMM_SMEM_BYTES (4 * GSTG_H * 2)

__global__ void __launch_bounds__(256, 2) hgemm(const __half* __restrict__ A,
                                                const __half* __restrict__ B,
                                                float* __restrict__ C,
                                                int M, int N, int K) {
    extern __shared__ __half sh[];
    const u32 shb = smem_u32(sh);

    const int tid  = threadIdx.x;
    const int lane = tid & 31;
    const int wid  = tid >> 5;
    const int wm   = wid >> 2;
    const int wn   = wid & 3;
    const int g    = lane >> 2;
    const int t    = lane & 3;
    const int row0 = blockIdx.y * 128;
    const int col0 = blockIdx.x * 128;

    const int l_r  = tid >> 3;
    const int l_c8 = (tid & 7) * 8;

    float c[4][4][4];
#pragma unroll
    for (int i = 0; i < 4; i++)
#pragma unroll
        for (int n = 0; n < 4; n++)
#pragma unroll
            for (int r = 0; r < 4; r++) c[i][n][r] = 0.f;

    const int NS = K >> 6;

    auto issue = [&](int s) {
        const int kb   = s << 6;
        const u32 base = shb + (u32)(s & 1) * (2 * GSTG_H * 2);
        const u32 ab   = base;
        const u32 bb   = base + GSTG_H * 2;
#pragma unroll
        for (int j = 0; j < 4; j++) {
            const int r = l_r + j * 32;
            cp16(ab + (u32)(r * 72 + l_c8) * 2,
                 &A[(size_t)(row0 + r) * K + kb + l_c8]);
            cp16(bb + (u32)(r * 72 + l_c8) * 2,
                 &B[(size_t)(col0 + r) * K + kb + l_c8]);
        }
        CP_COMMIT();
    };

    issue(0);
    for (int s = 0; s < NS; s++) {
        if (s + 1 < NS) issue(s + 1);
        if (s + 1 < NS) { CP_WAIT(1); } else { CP_WAIT(0); }
        __syncthreads();

        const __half* As = sh + (s & 1) * (2 * GSTG_H);
        const __half* Bs = As + GSTG_H;

#pragma unroll
        for (int kt = 0; kt < 4; kt++) {
            uint4 af[4];
#pragma unroll
            for (int mt = 0; mt < 4; mt++) {
                const int row = wm * 64 + mt * 16;
                af[mt].x = *(const u32*)&As[(row + g)     * 72 + kt * 16 + 2 * t];
                af[mt].y = *(const u32*)&As[(row + g + 8) * 72 + kt * 16 + 2 * t];
                af[mt].z = *(const u32*)&As[(row + g)     * 72 + kt * 16 + 2 * t + 8];
                af[mt].w = *(const u32*)&As[(row + g + 8) * 72 + kt * 16 + 2 * t + 8];
            }
            u32 bf[4][2];
#pragma unroll
            for (int nt = 0; nt < 4; nt++) {
                const int n = wn * 32 + nt * 8;
                bf[nt][0] = *(const u32*)&Bs[(n + g) * 72 + kt * 16 + 2 * t];
                bf[nt][1] = *(const u32*)&Bs[(n + g) * 72 + kt * 16 + 2 * t + 8];
            }
#pragma unroll
            for (int mt = 0; mt < 4; mt++)
#pragma unroll
                for (int nt = 0; nt < 4; nt++)
                    mma_f16(c[mt][nt], af[mt], bf[nt][0], bf[nt][1]);
        }
        __syncthreads();
    }

#pragma unroll
    for (int mt = 0; mt < 4; mt++) {
        const int row = row0 + wm * 64 + mt * 16 + g;
#pragma unroll
        for (int nt = 0; nt < 4; nt++) {
            const int col = col0 + wn * 32 + nt * 8 + 2 * t;
            *(float2*)&C[(size_t)row * N + col] =
                make_float2(c[mt][nt][0], c[mt][nt][1]);
            *(float2*)&C[(size_t)(row + 8) * N + col] =
                make_float2(c[mt][nt][2], c[mt][nt][3]);
        }
    }
}

// ---------------- RoPE table precompute -------------------------------------
__global__ void __launch_bounds__(64) rope_table_kernel(const int* __restrict__ pos_ids) {
    const int s = blockIdx.x;
    const int i = threadIdx.x;
    const float freq  = powf(10000.0f, -(float)i / 64.0f);
    const float ang_f = (float)pos_ids[s] * freq;
    const double ang  = (double)ang_f;
    g_rcos[s * 64 + i] = (float)cos(ang);
    g_rsin[s * 64 + i] = (float)sin(ang);
}

// ---------------- RMSNorm + RoPE from fused qkv ------------------------------
__global__ void __launch_bounds__(256) norm_rope_kernel(
    const float* __restrict__ qkv,
    const float* __restrict__ qw, const float* __restrict__ kw,
    __half* __restrict__ qout,
    float*  __restrict__ kout,  float* __restrict__ vout,
    __half* __restrict__ khalf, __half* __restrict__ vhalf)
{
    const int s = blockIdx.x;
    const int w = threadIdx.x >> 5;
    const int l = threadIdx.x & 31;
    const int c = l * 4;
    const float* row = qkv + (size_t)s * QKV_N;

#pragma unroll
    for (int uu = 0; uu < 3; uu++) {
        const int unit = w + uu * 8;
        if (unit >= 20) {
            const int kv = unit - 20;
            const float4 v = *(const float4*)&row[2560 + kv * HDIM + c];
            *(float4*)&vout[((size_t)kv * SEQ + s) * HDIM + c] = v;
            *(uint2*)&vhalf[((size_t)kv * SEQ + s) * HDIM + c] =
                make_uint2(f2h2(v.x, v.y), f2h2(v.z, v.w));
            continue;
        }
        float4 v; const float* wptr;
        if (unit < 16) { v = *(const float4*)&row[unit * HDIM + c];               wptr = qw; }
        else           { v = *(const float4*)&row[2048 + (unit - 16) * HDIM + c]; wptr = kw; }

        float sq = v.x * v.x + v.y * v.y + v.z * v.z + v.w * v.w;
#pragma unroll
        for (int off = 16; off > 0; off >>= 1)
            sq += __shfl_xor_sync(0xffffffffu, sq, off);
        const float inv = rsqrtf(sq * (1.0f / HDIM) + 1e-6f);
        const float4 wv = *(const float4*)&wptr[c];
        float xn[4] = {wv.x * v.x * inv, wv.y * v.y * inv,
                       wv.z * v.z * inv, wv.w * v.w * inv};
        float pr[4];
#pragma unroll
        for (int i = 0; i < 4; i++)
            pr[i] = __shfl_xor_sync(0xffffffffu, xn[i], 16);
        const float4 cs = *(const float4*)&g_rcos[s * 64 + (c & 63)];
        const float4 sn = *(const float4*)&g_rsin[s * 64 + (c & 63)];
        const float cc[4] = {cs.x, cs.y, cs.z, cs.w};
        const float ss[4] = {sn.x, sn.y, sn.z, sn.w};
        float o[4];
#pragma unroll
        for (int i = 0; i < 4; i++)
            o[i] = (l < 16) ? (xn[i] * cc[i] - pr[i] * ss[i])
                            : (xn[i] * cc[i] + pr[i] * ss[i]);
        if (unit < 16) {
            *(uint2*)&qout[((size_t)unit * SEQ + s) * HDIM + c] =
                make_uint2(f2h2(o[0], o[1]), f2h2(o[2], o[3]));
        } else {
            const int kvh = unit - 16;
            *(float4*)&kout[((size_t)kvh * SEQ + s) * HDIM + c] =
                make_float4(o[0], o[1], o[2], o[3]);
            *(uint2*)&khalf[((size_t)kvh * SEQ + s) * HDIM + c] =
                make_uint2(f2h2(o[0], o[1]), f2h2(o[2], o[3]));
        }
    }
}

// ---------------- Flash attention (fp16 mma, cp.async, ldmatrix) -----------
// BM=128, BN=64; warp w owns rows [w*16, w*16+16). Double-buffered K/V tiles.
#define FQ_LD 136
#define KS_LD 136
#define VS_LD 136
#define FP_LD 72
#define KS_TILE_H (64 * KS_LD)
#define VS_TILE_H (64 * VS_LD)
#define FLASH_SMEM_HALVES (128*FQ_LD + 2*KS_TILE_H + 2*VS_TILE_H + 128*FP_LD)
#define FLASH_SMEM_BYTES  (FLASH_SMEM_HALVES * 2)

__global__ void __launch_bounds__(256, 1) flash_f16(
    const __half* __restrict__ Q,
    const __half* __restrict__ Kh,
    const __half* __restrict__ Vh,
    __half* __restrict__ ctx)
{
    extern __shared__ __half smh[];
    __half* Qs = smh;                          // [128][136]
    __half* Ks = Qs + 128 * FQ_LD;             // 2 x [64][136]
    __half* Vs = Ks + 2 * KS_TILE_H;           // 2 x [64][136]
    __half* Ps = Vs + 2 * VS_TILE_H;           // [128][72]

    const u32 ksb0 = smem_u32(Ks);
    const u32 vsb0 = smem_u32(Vs);

    const int tid  = threadIdx.x;
    const int lane = tid & 31;
    const int w    = tid >> 5;
    const int g    = lane >> 2;
    const int t    = lane & 3;
    const int qt   = (gridDim.x - 1) - blockIdx.x;   // big tiles first
    const int head = blockIdx.y;
    const int kv   = head / GROUP;
    const int q0   = qt * 128;
    const int rw   = w * 16;

    // per-lane ldmatrix offsets
    const u32 k_off = ((u32)(((lane >> 4) & 1) * 8 + (lane & 7)) * KS_LD
                       + (u32)(((lane >> 3) & 1) * 8)) * 2;
    const u32 v_off = ((u32)(((lane >> 3) & 1) * 8 + (lane & 7)) * VS_LD
                       + (u32)((lane >> 4) * 8)) * 2;

    const __half* kg = Kh + (size_t)kv * SEQ * HDIM;
    const __half* vg = Vh + (size_t)kv * SEQ * HDIM;
    const int l_r  = tid >> 4;             // 0..15
    const int l_c8 = (tid & 15) * 8;       // 0..120

    const int njt = 2 * qt + 2;

    // issue tile jt's K/V into buffer jt&1 (4 cp16 per array per thread)
    auto issue = [&](int jt) {
        const int k0 = jt * 64;
        const u32 kd = ksb0 + (u32)(jt & 1) * (KS_TILE_H * 2);
        const u32 vd = vsb0 + (u32)(jt & 1) * (VS_TILE_H * 2);
#pragma unroll
        for (int j = 0; j < 4; j++) {
            const int r = l_r + j * 16;
            cp16(kd + (u32)(r * KS_LD + l_c8) * 2,
                 kg + (size_t)(k0 + r) * HDIM + l_c8);
            cp16(vd + (u32)(r * VS_LD + l_c8) * 2,
                 vg + (size_t)(k0 + r) * HDIM + l_c8);
        }
        CP_COMMIT();
    };

    // ---- stage Q tile + prefetch first K/V ----
    issue(0);
    if (njt > 1) issue(1);
    {
        const uint4* src = (const uint4*)(Q + ((size_t)head * SEQ + q0) * HDIM);
#pragma unroll
        for (int j = 0; j < 8; j++) {
            const int i = tid + j * 256;
            const int r = i >> 4, c8 = (i & 15) * 8;
            *(uint4*)&Qs[r * FQ_LD + c8] = src[r * 16 + (i & 15)];
        }
    }
    __syncthreads();

    uint4 af[8];
#pragma unroll
    for (int kt = 0; kt < 8; kt++) {
        af[kt].x = *(const u32*)&Qs[(rw + g)     * FQ_LD + kt * 16 + 2 * t];
        af[kt].y = *(const u32*)&Qs[(rw + g + 8) * FQ_LD + kt * 16 + 2 * t];
        af[kt].z = *(const u32*)&Qs[(rw + g)     * FQ_LD + kt * 16 + 2 * t + 8];
        af[kt].w = *(const u32*)&Qs[(rw + g + 8) * FQ_LD + kt * 16 + 2 * t + 8];
    }

    float o[16][4];
#pragma unroll
    for (int n = 0; n < 16; n++)
#pragma unroll
        for (int r = 0; r < 4; r++) o[n][r] = 0.f;
    float mA = -INFINITY, mB = -INFINITY, lA = 0.f, lB = 0.f;

    const float scale = 0.08838834764831845f;
    const int rowA = q0 + rw + g;
    const int rowB = rowA + 8;

    for (int jt = 0; jt < njt; jt++) {
        const int k0 = jt * 64;
        if (jt + 1 < njt) { CP_WAIT(1); } else { CP_WAIT(0); }
        __syncthreads();

        const u32 kfb = ksb0 + (u32)(jt & 1) * (KS_TILE_H * 2) + k_off;
        const u32 vfb = vsb0 + (u32)(jt & 1) * (VS_TILE_H * 2) + v_off;

        // ---- S = Q @ K^T : ldmatrix.x4 b-fragments ----
        float s[8][4];
#pragma unroll
        for (int n = 0; n < 8; n++)
#pragma unroll
            for (int r = 0; r < 4; r++) s[n][r] = 0.f;
#pragma unroll
        for (int kt = 0; kt < 8; kt++) {
#pragma unroll
            for (int np = 0; np < 4; np++) {
                u32 bf[4];
                ldsm4(bf, kfb + (u32)(np * 16 * KS_LD + kt * 16) * 2);
                mma_f16(s[2 * np],     af[kt], bf[0], bf[1]);
                mma_f16(s[2 * np + 1], af[kt], bf[2], bf[3]);
            }
        }

        // ---- scale + causal mask ----
        const bool dodiag = (jt >= 2 * qt);
#pragma unroll
        for (int nt = 0; nt < 8; nt++) {
            const int c0 = k0 + nt * 8 + 2 * t;
            const int c1 = c0 + 1;
            s[nt][0] *= scale; s[nt][1] *= scale;
            s[nt][2] *= scale; s[nt][3] *= scale;
            if (dodiag) {
                if (c0 > rowA) s[nt][0] = -1e30f;
                if (c1 > rowA) s[nt][1] = -1e30f;
                if (c0 > rowB) s[nt][2] = -1e30f;
                if (c1 > rowB) s[nt][3] = -1e30f;
            }
        }

        // ---- online softmax ----
        float mxA = -1e30f, mxB = -1e30f;
#pragma unroll
        for (int nt = 0; nt < 8; nt++) {
            mxA = fmaxf(mxA, fmaxf(s[nt][0], s[nt][1]));
            mxB = fmaxf(mxB, fmaxf(s[nt][2], s[nt][3]));
        }
        mxA = fmaxf(mxA, __shfl_xor_sync(0xffffffffu, mxA, 1));
        mxA = fmaxf(mxA, __shfl_xor_sync(0xffffffffu, mxA, 2));
        mxB = fmaxf(mxB, __shfl_xor_sync(0xffffffffu, mxB, 1));
        mxB = fmaxf(mxB, __shfl_xor_sync(0xffffffffu, mxB, 2));

        const float mnA = fmaxf(mA, mxA);
        const float mnB = fmaxf(mB, mxB);
        const float cA  = __expf(mA - mnA);
        const float cB  = __expf(mB - mnB);

        float sA = 0.f, sB = 0.f;
#pragma unroll
        for (int nt = 0; nt < 8; nt++) {
            const float p0 = __expf(s[nt][0] - mnA);
            const float p1 = __expf(s[nt][1] - mnA);
            const float p2 = __expf(s[nt][2] - mnB);
            const float p3 = __expf(s[nt][3] - mnB);
            sA += p0 + p1;  sB += p2 + p3;
            const int cc = nt * 8 + 2 * t;
            *(u32*)&Ps[(rw + g)     * FP_LD + cc] = f2h2(p0, p1);
            *(u32*)&Ps[(rw + g + 8) * FP_LD + cc] = f2h2(p2, p3);
        }
        sA += __shfl_xor_sync(0xffffffffu, sA, 1);
        sA += __shfl_xor_sync(0xffffffffu, sA, 2);
        sB += __shfl_xor_sync(0xffffffffu, sB, 1);
        sB += __shfl_xor_sync(0xffffffffu, sB, 2);

        lA = lA * cA + sA;  lB = lB * cB + sB;
        mA = mnA;           mB = mnB;
#pragma unroll
        for (int nt = 0; nt < 16; nt++) {
            o[nt][0] *= cA;  o[nt][1] *= cA;
            o[nt][2] *= cB;  o[nt][3] *= cB;
        }
        __syncwarp();   // P rows warp-private

        // ---- O += P @ V : ldmatrix.x4.trans on row-major V ----
#pragma unroll
        for (int kt = 0; kt < 4; kt++) {
            uint4 pf;
            pf.x = *(const u32*)&Ps[(rw + g)     * FP_LD + kt * 16 + 2 * t];
            pf.y = *(const u32*)&Ps[(rw + g + 8) * FP_LD + kt * 16 + 2 * t];
            pf.z = *(const u32*)&Ps[(rw + g)     * FP_LD + kt * 16 + 2 * t + 8];
            pf.w = *(const u32*)&Ps[(rw + g + 8) * FP_LD + kt * 16 + 2 * t + 8];
#pragma unroll
            for (int np = 0; np < 8; np++) {
                u32 bf[4];
                ldsm4t(bf, vfb + (u32)(kt * 16 * VS_LD + np * 16) * 2);
                mma_f16(o[2 * np],     pf, bf[0], bf[1]);
                mma_f16(o[2 * np + 1], pf, bf[2], bf[3]);
            }
        }
        __syncthreads();               // all warps done with buf jt&1
        if (jt + 2 < njt) issue(jt + 2);
    }

    const float iA = 1.0f / lA;
    const float iB = 1.0f / lB;
#pragma unroll
    for (int nt = 0; nt < 16; nt++) {
        const int col = head * HDIM + nt * 8 + 2 * t;
        *(u32*)&ctx[(size_t)rowA * EMB + col] = f2h2(o[nt][0] * iA, o[nt][1] * iA);
        *(u32*)&ctx[(size_t)rowB * EMB + col] = f2h2(o[nt][2] * iB, o[nt][3] * iB);
    }
}

// ---------------- launch ----------------------------------------------------
extern "C" void kernel_launch(void* const* d_in, const int* in_sizes, int n_in,
                              void* d_out, int out_size) {
    const float* x   = (const float*)d_in[0];
    const int*   pos = (const int*)  d_in[1];
    // d_in[2] = attn_mask (pure causal) -- analytic
    const float* Wq  = (const float*)d_in[3];
    const float* Wk  = (const float*)d_in[4];
    const float* Wv  = (const float*)d_in[5];
    const float* Wo  = (const float*)d_in[6];
    const float* qw  = (const float*)d_in[7];
    const float* kw  = (const float*)d_in[8];

    float* out  = (float*)d_out;
    float* kout = out  + (size_t)SEQ * EMB;
    float* vout = kout + (size_t)NKV * SEQ * HDIM;

    float  *qkv;
    __half *xh, *qh, *kh, *vh, *ctxh, *wqkvt, *wot;
    cudaGetSymbolAddress((void**)&qkv,   g_qkv);
    cudaGetSymbolAddress((void**)&xh,    g_xh);
    cudaGetSymbolAddress((void**)&qh,    g_qh);
    cudaGetSymbolAddress((void**)&kh,    g_kh);
    cudaGetSymbolAddress((void**)&vh,    g_vh);
    cudaGetSymbolAddress((void**)&ctxh,  g_ctxh);
    cudaGetSymbolAddress((void**)&wqkvt, g_wqkvt);
    cudaGetSymbolAddress((void**)&wot,   g_wot);

    cudaFuncSetAttribute(hgemm,
                         cudaFuncAttributeMaxDynamicSharedMemorySize, GEMM_SMEM_BYTES);
    cudaFuncSetAttribute(flash_f16,
                         cudaFuncAttributeMaxDynamicSharedMemorySize, FLASH_SMEM_BYTES);

    // 0) one-time conversions
    f32_to_f16<<<(SEQ * EMB / 4) / 256, 256>>>(x, xh);
    transpose_qkv<<<dim3(QKV_N / 32, EMB / 32), 256>>>(Wq, Wk, Wv, wqkvt);
    transpose_half<<<dim3(EMB / 32, EMB / 32), 256>>>(Wo, wot, EMB, EMB);
    rope_table_kernel<<<SEQ, 64>>>(pos);

    // 1) fused QKV projection
    hgemm<<<dim3(QKV_N / 128, SEQ / 128), 256, GEMM_SMEM_BYTES>>>(
        xh, wqkvt, qkv, SEQ, QKV_N, EMB);

    // 2) rmsnorm + rope
    norm_rope_kernel<<<SEQ, 256>>>(qkv, qw, kw, qh, kout, vout, kh, vh);

    // 3) causal flash attention
    flash_f16<<<dim3(SEQ / 128, NHEADS), 256, FLASH_SMEM_BYTES>>>(qh, kh, vh, ctxh);

    // 4) output projection
    hgemm<<<dim3(EMB / 128, SEQ / 128), 256, GEMM_SMEM_BYTES>>>(
        ctxh, wot, out, SEQ, EMB, EMB);
}

// round 9
// speedup vs baseline: 8.9348x; 1.0651x over previous
#include <cuda_runtime.h>
#include <cuda_fp16.h>
#include <math.h>
#include <stdint.h>

// Problem constants
#define SEQ      4096
#define EMB      2048
#define NHEADS   16
#define NKV      4
#define HDIM     128
#define GROUP    (NHEADS / NKV)
#define QKV_N    3072            // 2048 Q + 512 K + 512 V

typedef unsigned long long u64;
typedef unsigned int u32;

// ---------------- scratch (device globals; no allocation allowed) ----------
__device__ __half g_qkvh[SEQ * QKV_N];            // fused projection (half)
__device__ __half g_xh  [SEQ * EMB];
__device__ __half g_qh  [NHEADS * SEQ * HDIM];
__device__ __half g_kh  [NKV * SEQ * HDIM];
__device__ __half g_vh  [NKV * SEQ * HDIM];
__device__ __half g_ctxh[SEQ * NHEADS * HDIM];
__device__ float  g_rcos[SEQ * 64];
__device__ float  g_rsin[SEQ * 64];
__device__ __half g_wqkvt[QKV_N * EMB];           // [3072][2048]
__device__ __half g_wot  [EMB * EMB];

// ---------------- helpers ----------------------------------------------------
__device__ __forceinline__ u32 f2h2(float lo, float hi) {
    __half2 h = __floats2half2_rn(lo, hi);
    return *reinterpret_cast<u32*>(&h);
}
__device__ __forceinline__ void mma_f16(float c[4], uint4 a, u32 b0, u32 b1) {
    asm("mma.sync.aligned.m16n8k16.row.col.f32.f16.f16.f32 "
        "{%0,%1,%2,%3},{%4,%5,%6,%7},{%8,%9},{%0,%1,%2,%3};"
        : "+f"(c[0]), "+f"(c[1]), "+f"(c[2]), "+f"(c[3])
        : "r"(a.x), "r"(a.y), "r"(a.z), "r"(a.w), "r"(b0), "r"(b1));
}
__device__ __forceinline__ u32 smem_u32(const void* p) {
    u32 a;
    asm("{ .reg .u64 t; cvta.to.shared.u64 t, %1; cvt.u32.u64 %0, t; }"
        : "=r"(a) : "l"(p));
    return a;
}
__device__ __forceinline__ void cp16(u32 saddr, const void* gptr) {
    asm volatile("cp.async.cg.shared.global [%0], [%1], 16;"
                 :: "r"(saddr), "l"(gptr) : "memory");
}
#define CP_COMMIT() asm volatile("cp.async.commit_group;" ::: "memory")
#define CP_WAIT(n)  asm volatile("cp.async.wait_group %0;" :: "n"(n) : "memory")

__device__ __forceinline__ void ldsm4(u32 r[4], u32 saddr) {
    asm volatile("ldmatrix.sync.aligned.m8n8.x4.shared.b16 {%0,%1,%2,%3}, [%4];"
                 : "=r"(r[0]), "=r"(r[1]), "=r"(r[2]), "=r"(r[3]) : "r"(saddr));
}
__device__ __forceinline__ void ldsm4t(u32 r[4], u32 saddr) {
    asm volatile("ldmatrix.sync.aligned.m8n8.x4.trans.shared.b16 {%0,%1,%2,%3}, [%4];"
                 : "=r"(r[0]), "=r"(r[1]), "=r"(r[2]), "=r"(r[3]) : "r"(saddr));
}

// ---------------- merged prep kernel ----------------------------------------
// blocks [0,8192)            : x fp32 -> half
// blocks [8192,14336)        : QKV weight transpose -> wqkvt
// blocks [14336,18432)       : Wo transpose -> wot
// blocks [18432,19456)       : rope table (sincosf)
#define PREP_BLOCKS (8192 + 6144 + 4096 + 1024)

__global__ void __launch_bounds__(256) prep_kernel(
    const float* __restrict__ x,
    const float* __restrict__ Wq, const float* __restrict__ Wk,
    const float* __restrict__ Wv, const float* __restrict__ Wo,
    const int* __restrict__ pos,
    __half* __restrict__ xh, __half* __restrict__ wqkvt,
    __half* __restrict__ wot)
{
    __shared__ __half t[32][33];
    const int b   = blockIdx.x;
    const int tid = threadIdx.x;

    if (b < 8192) {                                  // x -> half
        const int i = b * 256 + tid;
        float4 v = ((const float4*)x)[i];
        ((uint2*)xh)[i] = make_uint2(f2h2(v.x, v.y), f2h2(v.z, v.w));
        return;
    }
    if (b < 8192 + 6144) {                           // QKV transpose
        const int bb = b - 8192;
        const int n0 = (bb % 96) * 32, k0 = (bb / 96) * 32;
        const int xL = tid & 31, y = tid >> 5;
        const float* src; int N, nl;
        if      (n0 < 2048) { src = Wq; N = 2048; nl = n0; }
        else if (n0 < 2560) { src = Wk; N = 512;  nl = n0 - 2048; }
        else                { src = Wv; N = 512;  nl = n0 - 2560; }
#pragma unroll
        for (int j = 0; j < 4; j++) {
            const int k = y + j * 8;
            t[k][xL] = __float2half_rn(src[(size_t)(k0 + k) * N + nl + xL]);
        }
        __syncthreads();
#pragma unroll
        for (int j = 0; j < 4; j++) {
            const int n = y + j * 8;
            wqkvt[(size_t)(n0 + n) * EMB + k0 + xL] = t[xL][n];
        }
        return;
    }
    if (b < 8192 + 6144 + 4096) {                    // Wo transpose
        const int bb = b - (8192 + 6144);
        const int n0 = (bb % 64) * 32, k0 = (bb / 64) * 32;
        const int xL = tid & 31, y = tid >> 5;
#pragma unroll
        for (int j = 0; j < 4; j++) {
            const int k = y + j * 8;
            t[k][xL] = __float2half_rn(Wo[(size_t)(k0 + k) * EMB + n0 + xL]);
        }
        __syncthreads();
#pragma unroll
        for (int j = 0; j < 4; j++) {
            const int n = y + j * 8;
            wot[(size_t)(n0 + n) * EMB + k0 + xL] = t[xL][n];
        }
        return;
    }
    {                                                // rope table
        const int idx = (b - (8192 + 6144 + 4096)) * 256 + tid;
        const int s = idx >> 6, i = idx & 63;
        const float freq = powf(10000.0f, -(float)i / 64.0f);
        const float ang  = (float)pos[s] * freq;
        float sv, cv;
        sincosf(ang, &sv, &cv);
        g_rcos[s * 64 + i] = cv;
        g_rsin[s * 64 + i] = sv;
    }
}

// ---------------- fp16 MMA GEMM (fp32 out), cp.async double-buffered --------
#define GSTG_H   (128 * 72)
#define GEMM_SMEM_BYTES (4 * GSTG_H * 2)

__global__ void __launch_bounds__(256, 2) hgemm(const __half* __restrict__ A,
                                                const __half* __restrict__ B,
                                                float* __restrict__ C,
                                                int M, int N, int K) {
    extern __shared__ __half sh[];
    const u32 shb = smem_u32(sh);

    const int tid  = threadIdx.x;
    const int lane = tid & 31;
    const int wid  = tid >> 5;
    const int wm   = wid >> 2;
    const int wn   = wid & 3;
    const int g    = lane >> 2;
    const int t    = lane & 3;
    const int row0 = blockIdx.y * 128;
    const int col0 = blockIdx.x * 128;

    const int l_r  = tid >> 3;
    const int l_c8 = (tid & 7) * 8;

    float c[4][4][4];
#pragma unroll
    for (int i = 0; i < 4; i++)
#pragma unroll
        for (int n = 0; n < 4; n++)
#pragma unroll
            for (int r = 0; r < 4; r++) c[i][n][r] = 0.f;

    const int NS = K >> 6;

    auto issue = [&](int s) {
        const int kb   = s << 6;
        const u32 base = shb + (u32)(s & 1) * (2 * GSTG_H * 2);
        const u32 ab   = base;
        const u32 bb   = base + GSTG_H * 2;
#pragma unroll
        for (int j = 0; j < 4; j++) {
            const int r = l_r + j * 32;
            cp16(ab + (u32)(r * 72 + l_c8) * 2,
                 &A[(size_t)(row0 + r) * K + kb + l_c8]);
            cp16(bb + (u32)(r * 72 + l_c8) * 2,
                 &B[(size_t)(col0 + r) * K + kb + l_c8]);
        }
        CP_COMMIT();
    };

    issue(0);
    for (int s = 0; s < NS; s++) {
        if (s + 1 < NS) issue(s + 1);
        if (s + 1 < NS) { CP_WAIT(1); } else { CP_WAIT(0); }
        __syncthreads();

        const __half* As = sh + (s & 1) * (2 * GSTG_H);
        const __half* Bs = As + GSTG_H;

#pragma unroll
        for (int kt = 0; kt < 4; kt++) {
            uint4 af[4];
#pragma unroll
            for (int mt = 0; mt < 4; mt++) {
                const int row = wm * 64 + mt * 16;
                af[mt].x = *(const u32*)&As[(row + g)     * 72 + kt * 16 + 2 * t];
                af[mt].y = *(const u32*)&As[(row + g + 8) * 72 + kt * 16 + 2 * t];
                af[mt].z = *(const u32*)&As[(row + g)     * 72 + kt * 16 + 2 * t + 8];
                af[mt].w = *(const u32*)&As[(row + g + 8) * 72 + kt * 16 + 2 * t + 8];
            }
            u32 bf[4][2];
#pragma unroll
            for (int nt = 0; nt < 4; nt++) {
                const int n = wn * 32 + nt * 8;
                bf[nt][0] = *(const u32*)&Bs[(n + g) * 72 + kt * 16 + 2 * t];
                bf[nt][1] = *(const u32*)&Bs[(n + g) * 72 + kt * 16 + 2 * t + 8];
            }
#pragma unroll
            for (int mt = 0; mt < 4; mt++)
#pragma unroll
                for (int nt = 0; nt < 4; nt++)
                    mma_f16(c[mt][nt], af[mt], bf[nt][0], bf[nt][1]);
        }
        __syncthreads();
    }

#pragma unroll
    for (int mt = 0; mt < 4; mt++) {
        const int row = row0 + wm * 64 + mt * 16 + g;
#pragma unroll
        for (int nt = 0; nt < 4; nt++) {
            const int col = col0 + wn * 32 + nt * 8 + 2 * t;
            *(float2*)&C[(size_t)row * N + col] =
                make_float2(c[mt][nt][0], c[mt][nt][1]);
            *(float2*)&C[(size_t)(row + 8) * N + col] =
                make_float2(c[mt][nt][2], c[mt][nt][3]);
        }
    }
}

// ---------------- fp16 MMA GEMM (half out) ----------------------------------
__global__ void __launch_bounds__(256, 2) hgemm_h(const __half* __restrict__ A,
                                                  const __half* __restrict__ B,
                                                  __half* __restrict__ C,
                                                  int M, int N, int K) {
    extern __shared__ __half sh[];
    const u32 shb = smem_u32(sh);

    const int tid  = threadIdx.x;
    const int lane = tid & 31;
    const int wid  = tid >> 5;
    const int wm   = wid >> 2;
    const int wn   = wid & 3;
    const int g    = lane >> 2;
    const int t    = lane & 3;
    const int row0 = blockIdx.y * 128;
    const int col0 = blockIdx.x * 128;

    const int l_r  = tid >> 3;
    const int l_c8 = (tid & 7) * 8;

    float c[4][4][4];
#pragma unroll
    for (int i = 0; i < 4; i++)
#pragma unroll
        for (int n = 0; n < 4; n++)
#pragma unroll
            for (int r = 0; r < 4; r++) c[i][n][r] = 0.f;

    const int NS = K >> 6;

    auto issue = [&](int s) {
        const int kb   = s << 6;
        const u32 base = shb + (u32)(s & 1) * (2 * GSTG_H * 2);
        const u32 ab   = base;
        const u32 bb   = base + GSTG_H * 2;
#pragma unroll
        for (int j = 0; j < 4; j++) {
            const int r = l_r + j * 32;
            cp16(ab + (u32)(r * 72 + l_c8) * 2,
                 &A[(size_t)(row0 + r) * K + kb + l_c8]);
            cp16(bb + (u32)(r * 72 + l_c8) * 2,
                 &B[(size_t)(col0 + r) * K + kb + l_c8]);
        }
        CP_COMMIT();
    };

    issue(0);
    for (int s = 0; s < NS; s++) {
        if (s + 1 < NS) issue(s + 1);
        if (s + 1 < NS) { CP_WAIT(1); } else { CP_WAIT(0); }
        __syncthreads();

        const __half* As = sh + (s & 1) * (2 * GSTG_H);
        const __half* Bs = As + GSTG_H;

#pragma unroll
        for (int kt = 0; kt < 4; kt++) {
            uint4 af[4];
#pragma unroll
            for (int mt = 0; mt < 4; mt++) {
                const int row = wm * 64 + mt * 16;
                af[mt].x = *(const u32*)&As[(row + g)     * 72 + kt * 16 + 2 * t];
                af[mt].y = *(const u32*)&As[(row + g + 8) * 72 + kt * 16 + 2 * t];
                af[mt].z = *(const u32*)&As[(row + g)     * 72 + kt * 16 + 2 * t + 8];
                af[mt].w = *(const u32*)&As[(row + g + 8) * 72 + kt * 16 + 2 * t + 8];
            }
            u32 bf[4][2];
#pragma unroll
            for (int nt = 0; nt < 4; nt++) {
                const int n = wn * 32 + nt * 8;
                bf[nt][0] = *(const u32*)&Bs[(n + g) * 72 + kt * 16 + 2 * t];
                bf[nt][1] = *(const u32*)&Bs[(n + g) * 72 + kt * 16 + 2 * t + 8];
            }
#pragma unroll
            for (int mt = 0; mt < 4; mt++)
#pragma unroll
                for (int nt = 0; nt < 4; nt++)
                    mma_f16(c[mt][nt], af[mt], bf[nt][0], bf[nt][1]);
        }
        __syncthreads();
    }

#pragma unroll
    for (int mt = 0; mt < 4; mt++) {
        const int row = row0 + wm * 64 + mt * 16 + g;
#pragma unroll
        for (int nt = 0; nt < 4; nt++) {
            const int col = col0 + wn * 32 + nt * 8 + 2 * t;
            *(u32*)&C[(size_t)row * N + col]       = f2h2(c[mt][nt][0], c[mt][nt][1]);
            *(u32*)&C[(size_t)(row + 8) * N + col] = f2h2(c[mt][nt][2], c[mt][nt][3]);
        }
    }
}

// ---------------- RMSNorm + RoPE from half qkv -------------------------------
__global__ void __launch_bounds__(256) norm_rope_kernel(
    const __half* __restrict__ qkv,          // [SEQ][3072] half
    const float* __restrict__ qw, const float* __restrict__ kw,
    __half* __restrict__ qout,
    float*  __restrict__ kout,  float* __restrict__ vout,
    __half* __restrict__ khalf, __half* __restrict__ vhalf)
{
    const int s = blockIdx.x;
    const int w = threadIdx.x >> 5;
    const int l = threadIdx.x & 31;
    const int c = l * 4;
    const __half* row = qkv + (size_t)s * QKV_N;

#pragma unroll
    for (int uu = 0; uu < 3; uu++) {
        const int unit = w + uu * 8;
        if (unit >= 20) {                        // V copy (fp32 d_out + half cache)
            const int kv = unit - 20;
            uint2 hv = *(const uint2*)&row[2560 + kv * HDIM + c];
            __half2 h0 = *(__half2*)&hv.x, h1 = *(__half2*)&hv.y;
            float2 a = __half22float2(h0), b2 = __half22float2(h1);
            *(float4*)&vout[((size_t)kv * SEQ + s) * HDIM + c] =
                make_float4(a.x, a.y, b2.x, b2.y);
            *(uint2*)&vhalf[((size_t)kv * SEQ + s) * HDIM + c] = hv;
            continue;
        }
        float4 v; const float* wptr;
        {
            const int off = (unit < 16) ? unit * HDIM + c
                                        : 2048 + (unit - 16) * HDIM + c;
            uint2 hv = *(const uint2*)&row[off];
            __half2 h0 = *(__half2*)&hv.x, h1 = *(__half2*)&hv.y;
            float2 a = __half22float2(h0), b2 = __half22float2(h1);
            v = make_float4(a.x, a.y, b2.x, b2.y);
            wptr = (unit < 16) ? qw : kw;
        }

        float sq = v.x * v.x + v.y * v.y + v.z * v.z + v.w * v.w;
#pragma unroll
        for (int off = 16; off > 0; off >>= 1)
            sq += __shfl_xor_sync(0xffffffffu, sq, off);
        const float inv = rsqrtf(sq * (1.0f / HDIM) + 1e-6f);
        const float4 wv = *(const float4*)&wptr[c];
        float xn[4] = {wv.x * v.x * inv, wv.y * v.y * inv,
                       wv.z * v.z * inv, wv.w * v.w * inv};
        float pr[4];
#pragma unroll
        for (int i = 0; i < 4; i++)
            pr[i] = __shfl_xor_sync(0xffffffffu, xn[i], 16);
        const float4 cs = *(const float4*)&g_rcos[s * 64 + (c & 63)];
        const float4 sn = *(const float4*)&g_rsin[s * 64 + (c & 63)];
        const float cc[4] = {cs.x, cs.y, cs.z, cs.w};
        const float ss[4] = {sn.x, sn.y, sn.z, sn.w};
        float o[4];
#pragma unroll
        for (int i = 0; i < 4; i++)
            o[i] = (l < 16) ? (xn[i] * cc[i] - pr[i] * ss[i])
                            : (xn[i] * cc[i] + pr[i] * ss[i]);
        if (unit < 16) {
            *(uint2*)&qout[((size_t)unit * SEQ + s) * HDIM + c] =
                make_uint2(f2h2(o[0], o[1]), f2h2(o[2], o[3]));
        } else {
            const int kvh = unit - 16;
            *(float4*)&kout[((size_t)kvh * SEQ + s) * HDIM + c] =
                make_float4(o[0], o[1], o[2], o[3]);
            *(uint2*)&khalf[((size_t)kvh * SEQ + s) * HDIM + c] =
                make_uint2(f2h2(o[0], o[1]), f2h2(o[2], o[3]));
        }
    }
}

// ---------------- Flash attention: BM=128, BN=128, cp.async + ldmatrix -----
// P buffer aliases Q staging (Q consumed into registers before first P write).
#define FQ_LD 136
#define KS_LD 136
#define VS_LD 136
#define FP_LD 136
#define KS_TILE_H (128 * KS_LD)
#define VS_TILE_H (128 * VS_LD)
#define FLASH_SMEM_HALVES (128*FQ_LD + 2*KS_TILE_H + 2*VS_TILE_H)
#define FLASH_SMEM_BYTES  (FLASH_SMEM_HALVES * 2)

__global__ void __launch_bounds__(256, 1) flash_f16(
    const __half* __restrict__ Q,
    const __half* __restrict__ Kh,
    const __half* __restrict__ Vh,
    __half* __restrict__ ctx)
{
    extern __shared__ __half smh[];
    __half* Qs = smh;                          // [128][136]  (aliased by Ps)
    __half* Ps = smh;                          // [128][136]
    __half* Ks = Qs + 128 * FQ_LD;             // 2 x [128][136]
    __half* Vs = Ks + 2 * KS_TILE_H;           // 2 x [128][136]

    const u32 ksb0 = smem_u32(Ks);
    const u32 vsb0 = smem_u32(Vs);

    const int tid  = threadIdx.x;
    const int lane = tid & 31;
    const int w    = tid >> 5;
    const int g    = lane >> 2;
    const int t    = lane & 3;
    const int qt   = (gridDim.x - 1) - blockIdx.x;   // big tiles first
    const int head = blockIdx.y;
    const int kv   = head / GROUP;
    const int q0   = qt * 128;
    const int rw   = w * 16;

    const u32 k_off = ((u32)(((lane >> 4) & 1) * 8 + (lane & 7)) * KS_LD
                       + (u32)(((lane >> 3) & 1) * 8)) * 2;
    const u32 v_off = ((u32)(((lane >> 3) & 1) * 8 + (lane & 7)) * VS_LD
                       + (u32)((lane >> 4) * 8)) * 2;

    const __half* kg = Kh + (size_t)kv * SEQ * HDIM;
    const __half* vg = Vh + (size_t)kv * SEQ * HDIM;
    const int l_r  = tid >> 4;             // 0..15
    const int l_c8 = (tid & 15) * 8;

    const int njt = qt + 1;

    auto issue = [&](int jt) {
        const int k0 = jt * 128;
        const u32 kd = ksb0 + (u32)(jt & 1) * (KS_TILE_H * 2);
        const u32 vd = vsb0 + (u32)(jt & 1) * (VS_TILE_H * 2);
#pragma unroll
        for (int j = 0; j < 8; j++) {
            const int r = l_r + j * 16;
            cp16(kd + (u32)(r * KS_LD + l_c8) * 2,
                 kg + (size_t)(k0 + r) * HDIM + l_c8);
            cp16(vd + (u32)(r * VS_LD + l_c8) * 2,
                 vg + (size_t)(k0 + r) * HDIM + l_c8);
        }
        CP_COMMIT();
    };

    issue(0);
    if (njt > 1) issue(1);
    {
        const uint4* src = (const uint4*)(Q + ((size_t)head * SEQ + q0) * HDIM);
#pragma unroll
        for (int j = 0; j < 8; j++) {
            const int i = tid + j * 256;
            const int r = i >> 4, c8 = (i & 15) * 8;
            *(uint4*)&Qs[r * FQ_LD + c8] = src[r * 16 + (i & 15)];
        }
    }
    __syncthreads();

    uint4 af[8];
#pragma unroll
    for (int kt = 0; kt < 8; kt++) {
        af[kt].x = *(const u32*)&Qs[(rw + g)     * FQ_LD + kt * 16 + 2 * t];
        af[kt].y = *(const u32*)&Qs[(rw + g + 8) * FQ_LD + kt * 16 + 2 * t];
        af[kt].z = *(const u32*)&Qs[(rw + g)     * FQ_LD + kt * 16 + 2 * t + 8];
        af[kt].w = *(const u32*)&Qs[(rw + g + 8) * FQ_LD + kt * 16 + 2 * t + 8];
    }

    float o[16][4];
#pragma unroll
    for (int n = 0; n < 16; n++)
#pragma unroll
        for (int r = 0; r < 4; r++) o[n][r] = 0.f;
    float mA = -INFINITY, mB = -INFINITY, lA = 0.f, lB = 0.f;

    const float scale = 0.08838834764831845f;
    const int rowA = q0 + rw + g;
    const int rowB = rowA + 8;

    for (int jt = 0; jt < njt; jt++) {
        const int k0 = jt * 128;
        if (jt + 1 < njt) { CP_WAIT(1); } else { CP_WAIT(0); }
        __syncthreads();

        const u32 kfb = ksb0 + (u32)(jt & 1) * (KS_TILE_H * 2) + k_off;
        const u32 vfb = vsb0 + (u32)(jt & 1) * (VS_TILE_H * 2) + v_off;

        // ---- S = Q @ K^T : 16 n-tiles of 8 keys ----
        float s[16][4];
#pragma unroll
        for (int n = 0; n < 16; n++)
#pragma unroll
            for (int r = 0; r < 4; r++) s[n][r] = 0.f;
#pragma unroll
        for (int kt = 0; kt < 8; kt++) {
#pragma unroll
            for (int np = 0; np < 8; np++) {
                u32 bf[4];
                ldsm4(bf, kfb + (u32)(np * 16 * KS_LD + kt * 16) * 2);
                mma_f16(s[2 * np],     af[kt], bf[0], bf[1]);
                mma_f16(s[2 * np + 1], af[kt], bf[2], bf[3]);
            }
        }

        // ---- scale + causal mask ----
        const bool dodiag = (jt == qt);
#pragma unroll
        for (int nt = 0; nt < 16; nt++) {
            const int c0 = k0 + nt * 8 + 2 * t;
            const int c1 = c0 + 1;
            s[nt][0] *= scale; s[nt][1] *= scale;
            s[nt][2] *= scale; s[nt][3] *= scale;
            if (dodiag) {
                if (c0 > rowA) s[nt][0] = -1e30f;
                if (c1 > rowA) s[nt][1] = -1e30f;
                if (c0 > rowB) s[nt][2] = -1e30f;
                if (c1 > rowB) s[nt][3] = -1e30f;
            }
        }

        // ---- online softmax ----
        float mxA = -1e30f, mxB = -1e30f;
#pragma unroll
        for (int nt = 0; nt < 16; nt++) {
            mxA = fmaxf(mxA, fmaxf(s[nt][0], s[nt][1]));
            mxB = fmaxf(mxB, fmaxf(s[nt][2], s[nt][3]));
        }
        mxA = fmaxf(mxA, __shfl_xor_sync(0xffffffffu, mxA, 1));
        mxA = fmaxf(mxA, __shfl_xor_sync(0xffffffffu, mxA, 2));
        mxB = fmaxf(mxB, __shfl_xor_sync(0xffffffffu, mxB, 1));
        mxB = fmaxf(mxB, __shfl_xor_sync(0xffffffffu, mxB, 2));

        const float mnA = fmaxf(mA, mxA);
        const float mnB = fmaxf(mB, mxB);
        const float cA  = __expf(mA - mnA);
        const float cB  = __expf(mB - mnB);

        float sA = 0.f, sB = 0.f;
#pragma unroll
        for (int nt = 0; nt < 16; nt++) {
            const float p0 = __expf(s[nt][0] - mnA);
            const float p1 = __expf(s[nt][1] - mnA);
            const float p2 = __expf(s[nt][2] - mnB);
            const float p3 = __expf(s[nt][3] - mnB);
            sA += p0 + p1;  sB += p2 + p3;
            const int cc = nt * 8 + 2 * t;
            *(u32*)&Ps[(rw + g)     * FP_LD + cc] = f2h2(p0, p1);
            *(u32*)&Ps[(rw + g + 8) * FP_LD + cc] = f2h2(p2, p3);
        }
        sA += __shfl_xor_sync(0xffffffffu, sA, 1);
        sA += __shfl_xor_sync(0xffffffffu, sA, 2);
        sB += __shfl_xor_sync(0xffffffffu, sB, 1);
        sB += __shfl_xor_sync(0xffffffffu, sB, 2);

        lA = lA * cA + sA;  lB = lB * cB + sB;
        mA = mnA;           mB = mnB;
#pragma unroll
        for (int nt = 0; nt < 16; nt++) {
            o[nt][0] *= cA;  o[nt][1] *= cA;
            o[nt][2] *= cB;  o[nt][3] *= cB;
        }
        __syncwarp();   // P rows warp-private

        // ---- O += P @ V : 8 k16-steps over 128 keys ----
#pragma unroll
        for (int kt = 0; kt < 8; kt++) {
            uint4 pf;
            pf.x = *(const u32*)&Ps[(rw + g)     * FP_LD + kt * 16 + 2 * t];
            pf.y = *(const u32*)&Ps[(rw + g + 8) * FP_LD + kt * 16 + 2 * t];
            pf.z = *(const u32*)&Ps[(rw + g)     * FP_LD + kt * 16 + 2 * t + 8];
            pf.w = *(const u32*)&Ps[(rw + g + 8) * FP_LD + kt * 16 + 2 * t + 8];
#pragma unroll
            for (int np = 0; np < 8; np++) {
                u32 bf[4];
                ldsm4t(bf, vfb + (u32)(kt * 16 * VS_LD + np * 16) * 2);
                mma_f16(o[2 * np],     pf, bf[0], bf[1]);
                mma_f16(o[2 * np + 1], pf, bf[2], bf[3]);
            }
        }
        __syncthreads();
        if (jt + 2 < njt) issue(jt + 2);
    }

    const float iA = 1.0f / lA;
    const float iB = 1.0f / lB;
#pragma unroll
    for (int nt = 0; nt < 16; nt++) {
        const int col = head * HDIM + nt * 8 + 2 * t;
        *(u32*)&ctx[(size_t)rowA * EMB + col] = f2h2(o[nt][0] * iA, o[nt][1] * iA);
        *(u32*)&ctx[(size_t)rowB * EMB + col] = f2h2(o[nt][2] * iB, o[nt][3] * iB);
    }
}

// ---------------- launch ----------------------------------------------------
extern "C" void kernel_launch(void* const* d_in, const int* in_sizes, int n_in,
                              void* d_out, int out_size) {
    const float* x   = (const float*)d_in[0];
    const int*   pos = (const int*)  d_in[1];
    // d_in[2] = attn_mask (pure causal) -- analytic
    const float* Wq  = (const float*)d_in[3];
    const float* Wk  = (const float*)d_in[4];
    const float* Wv  = (const float*)d_in[5];
    const float* Wo  = (const float*)d_in[6];
    const float* qw  = (const float*)d_in[7];
    const float* kw  = (const float*)d_in[8];

    float* out  = (float*)d_out;
    float* kout = out  + (size_t)SEQ * EMB;
    float* vout = kout + (size_t)NKV * SEQ * HDIM;

    __half *qkvh, *xh, *qh, *kh, *vh, *ctxh, *wqkvt, *wot;
    cudaGetSymbolAddress((void**)&qkvh,  g_qkvh);
    cudaGetSymbolAddress((void**)&xh,    g_xh);
    cudaGetSymbolAddress((void**)&qh,    g_qh);
    cudaGetSymbolAddress((void**)&kh,    g_kh);
    cudaGetSymbolAddress((void**)&vh,    g_vh);
    cudaGetSymbolAddress((void**)&ctxh,  g_ctxh);
    cudaGetSymbolAddress((void**)&wqkvt, g_wqkvt);
    cudaGetSymbolAddress((void**)&wot,   g_wot);

    cudaFuncSetAttribute(hgemm,
                         cudaFuncAttributeMaxDynamicSharedMemorySize, GEMM_SMEM_BYTES);
    cudaFuncSetAttribute(hgemm_h,
                         cudaFuncAttributeMaxDynamicSharedMemorySize, GEMM_SMEM_BYTES);
    cudaFuncSetAttribute(flash_f16,
                         cudaFuncAttributeMaxDynamicSharedMemorySize, FLASH_SMEM_BYTES);

    // 0) all prep in one launch
    prep_kernel<<<PREP_BLOCKS, 256>>>(x, Wq, Wk, Wv, Wo, pos, xh, wqkvt, wot);

    // 1) fused QKV projection (half output)
    hgemm_h<<<dim3(QKV_N / 128, SEQ / 128), 256, GEMM_SMEM_BYTES>>>(
        xh, wqkvt, qkvh, SEQ, QKV_N, EMB);

    // 2) rmsnorm + rope
    norm_rope_kernel<<<SEQ, 256>>>(qkvh, qw, kw, qh, kout, vout, kh, vh);

    // 3) causal flash attention (BN=128)
    flash_f16<<<dim3(SEQ / 128, NHEADS), 256, FLASH_SMEM_BYTES>>>(qh, kh, vh, ctxh);

    // 4) output projection
    hgemm<<<dim3(EMB / 128, SEQ / 128), 256, GEMM_SMEM_BYTES>>>(
        ctxh, wot, out, SEQ, EMB, EMB);
}

// round 11
// speedup vs baseline: 9.6473x; 1.0797x over previous
#include <cuda_runtime.h>
#include <cuda_fp16.h>
#include <math.h>
#include <stdint.h>

// Problem constants
#define SEQ      4096
#define EMB      2048
#define NHEADS   16
#define NKV      4
#define HDIM     128
#define GROUP    (NHEADS / NKV)
#define QKV_N    3072            // 2048 Q + 512 K + 512 V

typedef unsigned long long u64;
typedef unsigned int u32;

// softmax scale folded into Q: 1/sqrt(128) * log2(e)
#define QSCL 0.12753102694420f

// ---------------- scratch (device globals; no allocation allowed) ----------
__device__ __half g_qkvh[SEQ * QKV_N];            // fused projection (half)
__device__ __half g_xh  [SEQ * EMB];
__device__ __half g_qh  [NHEADS * SEQ * HDIM];
__device__ __half g_kh  [NKV * SEQ * HDIM];
__device__ __half g_vh  [NKV * SEQ * HDIM];
__device__ __half g_ctxh[SEQ * NHEADS * HDIM];
__device__ float  g_rcos[SEQ * 64];
__device__ float  g_rsin[SEQ * 64];
__device__ __half g_wqkvt[QKV_N * EMB];           // [3072][2048]
__device__ __half g_wot  [EMB * EMB];

// ---------------- helpers ----------------------------------------------------
__device__ __forceinline__ u32 f2h2(float lo, float hi) {
    __half2 h = __floats2half2_rn(lo, hi);
    return *reinterpret_cast<u32*>(&h);
}
__device__ __forceinline__ void mma_f16(float c[4], uint4 a, u32 b0, u32 b1) {
    asm("mma.sync.aligned.m16n8k16.row.col.f32.f16.f16.f32 "
        "{%0,%1,%2,%3},{%4,%5,%6,%7},{%8,%9},{%0,%1,%2,%3};"
        : "+f"(c[0]), "+f"(c[1]), "+f"(c[2]), "+f"(c[3])
        : "r"(a.x), "r"(a.y), "r"(a.z), "r"(a.w), "r"(b0), "r"(b1));
}
__device__ __forceinline__ u32 smem_u32(const void* p) {
    u32 a;
    asm("{ .reg .u64 t; cvta.to.shared.u64 t, %1; cvt.u32.u64 %0, t; }"
        : "=r"(a) : "l"(p));
    return a;
}
__device__ __forceinline__ void cp16(u32 saddr, const void* gptr) {
    asm volatile("cp.async.cg.shared.global [%0], [%1], 16;"
                 :: "r"(saddr), "l"(gptr) : "memory");
}
#define CP_COMMIT() asm volatile("cp.async.commit_group;" ::: "memory")
#define CP_WAIT(n)  asm volatile("cp.async.wait_group %0;" :: "n"(n) : "memory")

__device__ __forceinline__ void ldsm4(u32 r[4], u32 saddr) {
    asm volatile("ldmatrix.sync.aligned.m8n8.x4.shared.b16 {%0,%1,%2,%3}, [%4];"
                 : "=r"(r[0]), "=r"(r[1]), "=r"(r[2]), "=r"(r[3]) : "r"(saddr));
}
__device__ __forceinline__ void ldsm4t(u32 r[4], u32 saddr) {
    asm volatile("ldmatrix.sync.aligned.m8n8.x4.trans.shared.b16 {%0,%1,%2,%3}, [%4];"
                 : "=r"(r[0]), "=r"(r[1]), "=r"(r[2]), "=r"(r[3]) : "r"(saddr));
}

// ---------------- merged prep kernel ----------------------------------------
#define PREP_BLOCKS (8192 + 6144 + 4096 + 1024)

__global__ void __launch_bounds__(256) prep_kernel(
    const float* __restrict__ x,
    const float* __restrict__ Wq, const float* __restrict__ Wk,
    const float* __restrict__ Wv, const float* __restrict__ Wo,
    const int* __restrict__ pos,
    __half* __restrict__ xh, __half* __restrict__ wqkvt,
    __half* __restrict__ wot)
{
    __shared__ __half t[32][33];
    const int b   = blockIdx.x;
    const int tid = threadIdx.x;

    if (b < 8192) {                                  // x -> half
        const int i = b * 256 + tid;
        float4 v = ((const float4*)x)[i];
        ((uint2*)xh)[i] = make_uint2(f2h2(v.x, v.y), f2h2(v.z, v.w));
        return;
    }
    if (b < 8192 + 6144) {                           // QKV transpose
        const int bb = b - 8192;
        const int n0 = (bb % 96) * 32, k0 = (bb / 96) * 32;
        const int xL = tid & 31, y = tid >> 5;
        const float* src; int N, nl;
        if      (n0 < 2048) { src = Wq; N = 2048; nl = n0; }
        else if (n0 < 2560) { src = Wk; N = 512;  nl = n0 - 2048; }
        else                { src = Wv; N = 512;  nl = n0 - 2560; }
#pragma unroll
        for (int j = 0; j < 4; j++) {
            const int k = y + j * 8;
            t[k][xL] = __float2half_rn(src[(size_t)(k0 + k) * N + nl + xL]);
        }
        __syncthreads();
#pragma unroll
        for (int j = 0; j < 4; j++) {
            const int n = y + j * 8;
            wqkvt[(size_t)(n0 + n) * EMB + k0 + xL] = t[xL][n];
        }
        return;
    }
    if (b < 8192 + 6144 + 4096) {                    // Wo transpose
        const int bb = b - (8192 + 6144);
        const int n0 = (bb % 64) * 32, k0 = (bb / 64) * 32;
        const int xL = tid & 31, y = tid >> 5;
#pragma unroll
        for (int j = 0; j < 4; j++) {
            const int k = y + j * 8;
            t[k][xL] = __float2half_rn(Wo[(size_t)(k0 + k) * EMB + n0 + xL]);
        }
        __syncthreads();
#pragma unroll
        for (int j = 0; j < 4; j++) {
            const int n = y + j * 8;
            wot[(size_t)(n0 + n) * EMB + k0 + xL] = t[xL][n];
        }
        return;
    }
    {                                                // rope table
        const int idx = (b - (8192 + 6144 + 4096)) * 256 + tid;
        const int s = idx >> 6, i = idx & 63;
        const float freq = powf(10000.0f, -(float)i / 64.0f);
        const float ang  = (float)pos[s] * freq;
        float sv, cv;
        sincosf(ang, &sv, &cv);
        g_rcos[s * 64 + i] = cv;
        g_rsin[s * 64 + i] = sv;
    }
}

// ---------------- fp16 MMA GEMM core (ldmatrix fragments) -------------------
#define GSTG_H   (128 * 72)
#define GEMM_SMEM_BYTES (4 * GSTG_H * 2)

// A-operand lane map:  lanes[0:8)->rows0-7/k0-7, [8:16)->rows8-15/k0-7,
//                      [16:24)->rows0-7/k8-15, [24:32)->rows8-15/k8-15
// B-operand lane map (flash-verified): lanes[0:8)->n0-7/k0-7, [8:16)->n0-7/k8-15,
//                      [16:24)->n8-15/k0-7, [24:32)->n8-15/k8-15
#define HGEMM_BODY(C_STORE)                                                     \
    extern __shared__ __half sh[];                                             \
    const u32 shb = smem_u32(sh);                                              \
    const int tid  = threadIdx.x;                                              \
    const int lane = tid & 31;                                                 \
    const int wid  = tid >> 5;                                                 \
    const int wm   = wid >> 2;                                                 \
    const int wn   = wid & 3;                                                  \
    const int g    = lane >> 2;                                                \
    const int t    = lane & 3;                                                 \
    const int row0 = blockIdx.y * 128;                                         \
    const int col0 = blockIdx.x * 128;                                         \
    const int l_r  = tid >> 3;                                                 \
    const int l_c8 = (tid & 7) * 8;                                            \
    const u32 a_loff = ((u32)((((lane >> 3) & 1) * 8 + (lane & 7)) * 72)       \
                        + (u32)((lane >> 4) * 8)) * 2;                         \
    const u32 b_loff = ((u32)((((lane >> 4) & 1) * 8 + (lane & 7)) * 72)       \
                        + (u32)(((lane >> 3) & 1) * 8)) * 2;                   \
    float c[4][4][4];                                                          \
    _Pragma("unroll")                                                          \
    for (int i = 0; i < 4; i++)                                                \
        _Pragma("unroll")                                                      \
        for (int n = 0; n < 4; n++)                                            \
            _Pragma("unroll")                                                  \
            for (int r = 0; r < 4; r++) c[i][n][r] = 0.f;                      \
    const int NS = K >> 6;                                                     \
    auto issue = [&](int s) {                                                  \
        const int kb   = s << 6;                                               \
        const u32 base = shb + (u32)(s & 1) * (2 * GSTG_H * 2);                \
        const u32 ab   = base;                                                 \
        const u32 bb   = base + GSTG_H * 2;                                    \
        _Pragma("unroll")                                                      \
        for (int j = 0; j < 4; j++) {                                          \
            const int r = l_r + j * 32;                                        \
            cp16(ab + (u32)(r * 72 + l_c8) * 2,                                \
                 &A[(size_t)(row0 + r) * K + kb + l_c8]);                      \
            cp16(bb + (u32)(r * 72 + l_c8) * 2,                                \
                 &B[(size_t)(col0 + r) * K + kb + l_c8]);                      \
        }                                                                      \
        CP_COMMIT();                                                           \
    };                                                                         \
    issue(0);                                                                  \
    for (int s = 0; s < NS; s++) {                                             \
        if (s + 1 < NS) issue(s + 1);                                          \
        if (s + 1 < NS) { CP_WAIT(1); } else { CP_WAIT(0); }                   \
        __syncthreads();                                                       \
        const u32 asb = shb + (u32)(s & 1) * (2 * GSTG_H * 2) + a_loff;        \
        const u32 bsb = shb + (u32)(s & 1) * (2 * GSTG_H * 2) + GSTG_H * 2     \
                        + b_loff;                                              \
        _Pragma("unroll")                                                      \
        for (int kt = 0; kt < 4; kt++) {                                       \
            uint4 af[4];                                                       \
            _Pragma("unroll")                                                  \
            for (int mt = 0; mt < 4; mt++) {                                   \
                u32 aq[4];                                                     \
                ldsm4(aq, asb + (u32)(((wm * 64 + mt * 16) * 72                \
                                       + kt * 16) * 2));                       \
                af[mt] = make_uint4(aq[0], aq[1], aq[2], aq[3]);               \
            }                                                                  \
            u32 bf[4][2];                                                      \
            _Pragma("unroll")                                                  \
            for (int pr = 0; pr < 2; pr++) {                                   \
                u32 bq[4];                                                     \
                ldsm4(bq, bsb + (u32)(((wn * 32 + pr * 16) * 72                \
                                       + kt * 16) * 2));                       \
                bf[2 * pr][0]     = bq[0]; bf[2 * pr][1]     = bq[1];          \
                bf[2 * pr + 1][0] = bq[2]; bf[2 * pr + 1][1] = bq[3];          \
            }                                                                  \
            _Pragma("unroll")                                                  \
            for (int mt = 0; mt < 4; mt++)                                     \
                _Pragma("unroll")                                              \
                for (int nt = 0; nt < 4; nt++)                                 \
                    mma_f16(c[mt][nt], af[mt], bf[nt][0], bf[nt][1]);          \
        }                                                                      \
        __syncthreads();                                                       \
    }                                                                          \
    _Pragma("unroll")                                                          \
    for (int mt = 0; mt < 4; mt++) {                                           \
        const int row = row0 + wm * 64 + mt * 16 + g;                          \
        _Pragma("unroll")                                                      \
        for (int nt = 0; nt < 4; nt++) {                                       \
            const int col = col0 + wn * 32 + nt * 8 + 2 * t;                   \
            C_STORE                                                            \
        }                                                                      \
    }

__global__ void __launch_bounds__(256, 2) hgemm(const __half* __restrict__ A,
                                                const __half* __restrict__ B,
                                                float* __restrict__ C,
                                                int M, int N, int K) {
    HGEMM_BODY(
        *(float2*)&C[(size_t)row * N + col] =
            make_float2(c[mt][nt][0], c[mt][nt][1]);
        *(float2*)&C[(size_t)(row + 8) * N + col] =
            make_float2(c[mt][nt][2], c[mt][nt][3]);
    )
}

__global__ void __launch_bounds__(256, 2) hgemm_h(const __half* __restrict__ A,
                                                  const __half* __restrict__ B,
                                                  __half* __restrict__ C,
                                                  int M, int N, int K) {
    HGEMM_BODY(
        *(u32*)&C[(size_t)row * N + col]       = f2h2(c[mt][nt][0], c[mt][nt][1]);
        *(u32*)&C[(size_t)(row + 8) * N + col] = f2h2(c[mt][nt][2], c[mt][nt][3]);
    )
}

// ---------------- RMSNorm + RoPE from half qkv -------------------------------
// Q output is pre-scaled by QSCL (softmax scale folded in, log2 domain).
__global__ void __launch_bounds__(256) norm_rope_kernel(
    const __half* __restrict__ qkv,
    const float* __restrict__ qw, const float* __restrict__ kw,
    __half* __restrict__ qout,
    float*  __restrict__ kout,  float* __restrict__ vout,
    __half* __restrict__ khalf, __half* __restrict__ vhalf)
{
    const int s = blockIdx.x;
    const int w = threadIdx.x >> 5;
    const int l = threadIdx.x & 31;
    const int c = l * 4;
    const __half* row = qkv + (size_t)s * QKV_N;

#pragma unroll
    for (int uu = 0; uu < 3; uu++) {
        const int unit = w + uu * 8;
        if (unit >= 20) {
            const int kv = unit - 20;
            uint2 hv = *(const uint2*)&row[2560 + kv * HDIM + c];
            __half2 h0 = *(__half2*)&hv.x, h1 = *(__half2*)&hv.y;
            float2 a = __half22float2(h0), b2 = __half22float2(h1);
            *(float4*)&vout[((size_t)kv * SEQ + s) * HDIM + c] =
                make_float4(a.x, a.y, b2.x, b2.y);
            *(uint2*)&vhalf[((size_t)kv * SEQ + s) * HDIM + c] = hv;
            continue;
        }
        float4 v; const float* wptr;
        {
            const int off = (unit < 16) ? unit * HDIM + c
                                        : 2048 + (unit - 16) * HDIM + c;
            uint2 hv = *(const uint2*)&row[off];
            __half2 h0 = *(__half2*)&hv.x, h1 = *(__half2*)&hv.y;
            float2 a = __half22float2(h0), b2 = __half22float2(h1);
            v = make_float4(a.x, a.y, b2.x, b2.y);
            wptr = (unit < 16) ? qw : kw;
        }

        float sq = v.x * v.x + v.y * v.y + v.z * v.z + v.w * v.w;
#pragma unroll
        for (int off = 16; off > 0; off >>= 1)
            sq += __shfl_xor_sync(0xffffffffu, sq, off);
        const float inv = rsqrtf(sq * (1.0f / HDIM) + 1e-6f);
        const float4 wv = *(const float4*)&wptr[c];
        float xn[4] = {wv.x * v.x * inv, wv.y * v.y * inv,
                       wv.z * v.z * inv, wv.w * v.w * inv};
        float pr[4];
#pragma unroll
        for (int i = 0; i < 4; i++)
            pr[i] = __shfl_xor_sync(0xffffffffu, xn[i], 16);
        const float4 cs = *(const float4*)&g_rcos[s * 64 + (c & 63)];
        const float4 sn = *(const float4*)&g_rsin[s * 64 + (c & 63)];
        const float cc[4] = {cs.x, cs.y, cs.z, cs.w};
        const float ss[4] = {sn.x, sn.y, sn.z, sn.w};
        float o[4];
#pragma unroll
        for (int i = 0; i < 4; i++)
            o[i] = (l < 16) ? (xn[i] * cc[i] - pr[i] * ss[i])
                            : (xn[i] * cc[i] + pr[i] * ss[i]);
        if (unit < 16) {
            *(uint2*)&qout[((size_t)unit * SEQ + s) * HDIM + c] =
                make_uint2(f2h2(o[0] * QSCL, o[1] * QSCL),
                           f2h2(o[2] * QSCL, o[3] * QSCL));
        } else {
            const int kvh = unit - 16;
            *(float4*)&kout[((size_t)kvh * SEQ + s) * HDIM + c] =
                make_float4(o[0], o[1], o[2], o[3]);
            *(uint2*)&khalf[((size_t)kvh * SEQ + s) * HDIM + c] =
                make_uint2(f2h2(o[0], o[1]), f2h2(o[2], o[3]));
        }
    }
}

// ---------------- Flash attention: BM=128, BN=128, log2-domain softmax -----
#define FQ_LD 136
#define KS_LD 136
#define VS_LD 136
#define FP_LD 136
#define KS_TILE_H (128 * KS_LD)
#define VS_TILE_H (128 * VS_LD)
#define FLASH_SMEM_HALVES (128*FQ_LD + 2*KS_TILE_H + 2*VS_TILE_H)
#define FLASH_SMEM_BYTES  (FLASH_SMEM_HALVES * 2)

__global__ void __launch_bounds__(256, 1) flash_f16(
    const __half* __restrict__ Q,
    const __half* __restrict__ Kh,
    const __half* __restrict__ Vh,
    __half* __restrict__ ctx)
{
    extern __shared__ __half smh[];
    __half* Qs = smh;                          // [128][136]  (aliased by Ps)
    __half* Ps = smh;                          // [128][136]
    __half* Ks = Qs + 128 * FQ_LD;             // 2 x [128][136]
    __half* Vs = Ks + 2 * KS_TILE_H;           // 2 x [128][136]

    const u32 ksb0 = smem_u32(Ks);
    const u32 vsb0 = smem_u32(Vs);

    const int tid  = threadIdx.x;
    const int lane = tid & 31;
    const int w    = tid >> 5;
    const int g    = lane >> 2;
    const int t    = lane & 3;
    const int qt   = (gridDim.x - 1) - blockIdx.x;   // big tiles first
    const int head = blockIdx.y;
    const int kv   = head / GROUP;
    const int q0   = qt * 128;
    const int rw   = w * 16;

    const u32 k_off = ((u32)(((lane >> 4) & 1) * 8 + (lane & 7)) * KS_LD
                       + (u32)(((lane >> 3) & 1) * 8)) * 2;
    const u32 v_off = ((u32)(((lane >> 3) & 1) * 8 + (lane & 7)) * VS_LD
                       + (u32)((lane >> 4) * 8)) * 2;

    const __half* kg = Kh + (size_t)kv * SEQ * HDIM;
    const __half* vg = Vh + (size_t)kv * SEQ * HDIM;
    const int l_r  = tid >> 4;
    const int l_c8 = (tid & 15) * 8;

    const int njt = qt + 1;

    auto issue = [&](int jt) {
        const int k0 = jt * 128;
        const u32 kd = ksb0 + (u32)(jt & 1) * (KS_TILE_H * 2);
        const u32 vd = vsb0 + (u32)(jt & 1) * (VS_TILE_H * 2);
#pragma unroll
        for (int j = 0; j < 8; j++) {
            const int r = l_r + j * 16;
            cp16(kd + (u32)(r * KS_LD + l_c8) * 2,
                 kg + (size_t)(k0 + r) * HDIM + l_c8);
            cp16(vd + (u32)(r * VS_LD + l_c8) * 2,
                 vg + (size_t)(k0 + r) * HDIM + l_c8);
        }
        CP_COMMIT();
    };

    issue(0);
    if (njt > 1) issue(1);
    {
        const uint4* src = (const uint4*)(Q + ((size_t)head * SEQ + q0) * HDIM);
#pragma unroll
        for (int j = 0; j < 8; j++) {
            const int i = tid + j * 256;
            const int r = i >> 4, c8 = (i & 15) * 8;
            *(uint4*)&Qs[r * FQ_LD + c8] = src[r * 16 + (i & 15)];
        }
    }
    __syncthreads();

    uint4 af[8];
#pragma unroll
    for (int kt = 0; kt < 8; kt++) {
        af[kt].x = *(const u32*)&Qs[(rw + g)     * FQ_LD + kt * 16 + 2 * t];
        af[kt].y = *(const u32*)&Qs[(rw + g + 8) * FQ_LD + kt * 16 + 2 * t];
        af[kt].z = *(const u32*)&Qs[(rw + g)     * FQ_LD + kt * 16 + 2 * t + 8];
        af[kt].w = *(const u32*)&Qs[(rw + g + 8) * FQ_LD + kt * 16 + 2 * t + 8];
    }

    float o[16][4];
#pragma unroll
    for (int n = 0; n < 16; n++)
#pragma unroll
        for (int r = 0; r < 4; r++) o[n][r] = 0.f;
    float mA = -INFINITY, mB = -INFINITY, lA = 0.f, lB = 0.f;

    const int rowA = q0 + rw + g;
    const int rowB = rowA + 8;

    for (int jt = 0; jt < njt; jt++) {
        const int k0 = jt * 128;
        if (jt + 1 < njt) { CP_WAIT(1); } else { CP_WAIT(0); }
        __syncthreads();

        const u32 kfb = ksb0 + (u32)(jt & 1) * (KS_TILE_H * 2) + k_off;
        const u32 vfb = vsb0 + (u32)(jt & 1) * (VS_TILE_H * 2) + v_off;

        // ---- S = Q @ K^T  (scores already in log2 domain via QSCL) ----
        float s[16][4];
#pragma unroll
        for (int n = 0; n < 16; n++)
#pragma unroll
            for (int r = 0; r < 4; r++) s[n][r] = 0.f;
#pragma unroll
        for (int kt = 0; kt < 8; kt++) {
#pragma unroll
            for (int np = 0; np < 8; np++) {
                u32 bf[4];
                ldsm4(bf, kfb + (u32)(np * 16 * KS_LD + kt * 16) * 2);
                mma_f16(s[2 * np],     af[kt], bf[0], bf[1]);
                mma_f16(s[2 * np + 1], af[kt], bf[2], bf[3]);
            }
        }

        // ---- causal mask (diag tile only) ----
        if (jt == qt) {
#pragma unroll
            for (int nt = 0; nt < 16; nt++) {
                const int c0 = k0 + nt * 8 + 2 * t;
                const int c1 = c0 + 1;
                if (c0 > rowA) s[nt][0] = -1e30f;
                if (c1 > rowA) s[nt][1] = -1e30f;
                if (c0 > rowB) s[nt][2] = -1e30f;
                if (c1 > rowB) s[nt][3] = -1e30f;
            }
        }

        // ---- online softmax (base-2) ----
        float mxA = -1e30f, mxB = -1e30f;
#pragma unroll
        for (int nt = 0; nt < 16; nt++) {
            mxA = fmaxf(mxA, fmaxf(s[nt][0], s[nt][1]));
            mxB = fmaxf(mxB, fmaxf(s[nt][2], s[nt][3]));
        }
        mxA = fmaxf(mxA, __shfl_xor_sync(0xffffffffu, mxA, 1));
        mxA = fmaxf(mxA, __shfl_xor_sync(0xffffffffu, mxA, 2));
        mxB = fmaxf(mxB, __shfl_xor_sync(0xffffffffu, mxB, 1));
        mxB = fmaxf(mxB, __shfl_xor_sync(0xffffffffu, mxB, 2));

        const float mnA = fmaxf(mA, mxA);
        const float mnB = fmaxf(mB, mxB);
        const float cA  = exp2f(mA - mnA);
        const float cB  = exp2f(mB - mnB);

        float sA = 0.f, sB = 0.f;
#pragma unroll
        for (int nt = 0; nt < 16; nt++) {
            const float p0 = exp2f(s[nt][0] - mnA);
            const float p1 = exp2f(s[nt][1] - mnA);
            const float p2 = exp2f(s[nt][2] - mnB);
            const float p3 = exp2f(s[nt][3] - mnB);
            sA += p0 + p1;  sB += p2 + p3;
            const int cc = nt * 8 + 2 * t;
            *(u32*)&Ps[(rw + g)     * FP_LD + cc] = f2h2(p0, p1);
            *(u32*)&Ps[(rw + g + 8) * FP_LD + cc] = f2h2(p2, p3);
        }
        sA += __shfl_xor_sync(0xffffffffu, sA, 1);
        sA += __shfl_xor_sync(0xffffffffu, sA, 2);
        sB += __shfl_xor_sync(0xffffffffu, sB, 1);
        sB += __shfl_xor_sync(0xffffffffu, sB, 2);

        lA = lA * cA + sA;  lB = lB * cB + sB;
        mA = mnA;           mB = mnB;
#pragma unroll
        for (int nt = 0; nt < 16; nt++) {
            o[nt][0] *= cA;  o[nt][1] *= cA;
            o[nt][2] *= cB;  o[nt][3] *= cB;
        }
        __syncwarp();   // P rows warp-private

        // ---- O += P @ V ----
#pragma unroll
        for (int kt = 0; kt < 8; kt++) {
            uint4 pf;
            pf.x = *(const u32*)&Ps[(rw + g)     * FP_LD + kt * 16 + 2 * t];
            pf.y = *(const u32*)&Ps[(rw + g + 8) * FP_LD + kt * 16 + 2 * t];
            pf.z = *(const u32*)&Ps[(rw + g)     * FP_LD + kt * 16 + 2 * t + 8];
            pf.w = *(const u32*)&Ps[(rw + g + 8) * FP_LD + kt * 16 + 2 * t + 8];
#pragma unroll
            for (int np = 0; np < 8; np++) {
                u32 bf[4];
                ldsm4t(bf, vfb + (u32)(kt * 16 * VS_LD + np * 16) * 2);
                mma_f16(o[2 * np],     pf, bf[0], bf[1]);
                mma_f16(o[2 * np + 1], pf, bf[2], bf[3]);
            }
        }
        __syncthreads();
        if (jt + 2 < njt) issue(jt + 2);
    }

    const float iA = 1.0f / lA;
    const float iB = 1.0f / lB;
#pragma unroll
    for (int nt = 0; nt < 16; nt++) {
        const int col = head * HDIM + nt * 8 + 2 * t;
        *(u32*)&ctx[(size_t)rowA * EMB + col] = f2h2(o[nt][0] * iA, o[nt][1] * iA);
        *(u32*)&ctx[(size_t)rowB * EMB + col] = f2h2(o[nt][2] * iB, o[nt][3] * iB);
    }
}

// ---------------- launch ----------------------------------------------------
extern "C" void kernel_launch(void* const* d_in, const int* in_sizes, int n_in,
                              void* d_out, int out_size) {
    const float* x   = (const float*)d_in[0];
    const int*   pos = (const int*)  d_in[1];
    // d_in[2] = attn_mask (pure causal) -- analytic
    const float* Wq  = (const float*)d_in[3];
    const float* Wk  = (const float*)d_in[4];
    const float* Wv  = (const float*)d_in[5];
    const float* Wo  = (const float*)d_in[6];
    const float* qw  = (const float*)d_in[7];
    const float* kw  = (const float*)d_in[8];

    float* out  = (float*)d_out;
    float* kout = out  + (size_t)SEQ * EMB;
    float* vout = kout + (size_t)NKV * SEQ * HDIM;

    __half *qkvh, *xh, *qh, *kh, *vh, *ctxh, *wqkvt, *wot;
    cudaGetSymbolAddress((void**)&qkvh,  g_qkvh);
    cudaGetSymbolAddress((void**)&xh,    g_xh);
    cudaGetSymbolAddress((void**)&qh,    g_qh);
    cudaGetSymbolAddress((void**)&kh,    g_kh);
    cudaGetSymbolAddress((void**)&vh,    g_vh);
    cudaGetSymbolAddress((void**)&ctxh,  g_ctxh);
    cudaGetSymbolAddress((void**)&wqkvt, g_wqkvt);
    cudaGetSymbolAddress((void**)&wot,   g_wot);

    cudaFuncSetAttribute(hgemm,
                         cudaFuncAttributeMaxDynamicSharedMemorySize, GEMM_SMEM_BYTES);
    cudaFuncSetAttribute(hgemm_h,
                         cudaFuncAttributeMaxDynamicSharedMemorySize, GEMM_SMEM_BYTES);
    cudaFuncSetAttribute(flash_f16,
                         cudaFuncAttributeMaxDynamicSharedMemorySize, FLASH_SMEM_BYTES);

    // 0) all prep in one launch
    prep_kernel<<<PREP_BLOCKS, 256>>>(x, Wq, Wk, Wv, Wo, pos, xh, wqkvt, wot);

    // 1) fused QKV projection (half output)
    hgemm_h<<<dim3(QKV_N / 128, SEQ / 128), 256, GEMM_SMEM_BYTES>>>(
        xh, wqkvt, qkvh, SEQ, QKV_N, EMB);

    // 2) rmsnorm + rope (Q pre-scaled for log2-domain softmax)
    norm_rope_kernel<<<SEQ, 256>>>(qkvh, qw, kw, qh, kout, vout, kh, vh);

    // 3) causal flash attention
    flash_f16<<<dim3(SEQ / 128, NHEADS), 256, FLASH_SMEM_BYTES>>>(qh, kh, vh, ctxh);

    // 4) output projection
    hgemm<<<dim3(EMB / 128, SEQ / 128), 256, GEMM_SMEM_BYTES>>>(
        ctxh, wot, out, SEQ, EMB, EMB);
}